// round 1
// baseline (speedup 1.0000x reference)
#include <cuda_runtime.h>
#include <math.h>
#include <stdint.h>

#define NPTS 32768
#define TOTAL 2336
#define TWOTOTAL 4672
#define INNER 64

// ---------------- scratch (static device memory; no allocation) --------------
__device__ float g_p[NPTS * 3];
__device__ float g_Xn[(size_t)NPTS * TOTAL];     // gathered+normalized feats, later reused as Vn
__device__ float g_Y[(size_t)NPTS * TWOTOTAL];   // GEMM1 output
__device__ float g_down[NPTS * INNER];

// ---------------- math helpers ----------------------------------------------
__device__ __forceinline__ float sigmoidf_(float x) { return 1.0f / (1.0f + expf(-x)); }
__device__ __forceinline__ float gelu_tanh(float x) {
    float x3 = x * x * x;
    return 0.5f * x * (1.0f + tanhf(0.7978845608028654f * (x + 0.044715f * x3)));
}
__device__ __forceinline__ int wrapi(int v, int d) {
    if (v < 0) v += d; else if (v >= d) v -= d; return v;
}

__device__ const int FACE3[6][3] = {{1,0,0},{-1,0,0},{0,1,0},{0,-1,0},{0,0,1},{0,0,-1}};
__device__ const int ST8[8][4]   = {{1,0,0,0},{-1,0,0,0},{0,1,0,0},{0,-1,0,0},
                                    {0,0,1,0},{0,0,-1,0},{0,0,0,1},{0,0,0,-1}};

// ---------------- K1: per-point preamble MLP -> p ----------------------------
__global__ void k1_preamble(const float* __restrict__ pos, const float* __restrict__ t,
                            const float* __restrict__ sph_proj,
                            const float* __restrict__ tb1, const float* __restrict__ tb2,
                            const float* __restrict__ gn1, const float* __restrict__ gw1,
                            const float* __restrict__ gn2, const float* __restrict__ gw2,
                            const float* __restrict__ gn3, const float* __restrict__ gw3)
{
    int i = blockIdx.x * blockDim.x + threadIdx.x;
    if (i >= NPTS) return;

    float x = pos[i * 3 + 0], y = pos[i * 3 + 1], z = pos[i * 3 + 2];
    float rho = sqrtf(x * x + y * y + z * z);
    float phi = atan2f(y, x);
    float cz = z / rho;
    cz = fminf(1.0f, fmaxf(-1.0f, cz));
    float theta = acosf(cz);

    float h[12];
#pragma unroll
    for (int j = 0; j < 8; j++)
        h[j] = rho * sph_proj[j] + phi * sph_proj[8 + j] + theta * sph_proj[16 + j];
    float tv = t[i];
    float ct = cosf(tv + tb1[0]);
    float st = sinf(tv + tb2[0]);
    h[8] = ct; h[9] = st;
    h[10] = ct * sigmoidf_(ct);
    h[11] = st * sigmoidf_(st);

    // layer 1: rmsnorm(12) @ gw1(12x32) -> geglu -> 16
    float ss = 0.f;
#pragma unroll
    for (int j = 0; j < 12; j++) ss += h[j] * h[j];
    float sc = 1.0f / (sqrtf(ss / 12.0f) + 1e-8f);
    float hn[12];
#pragma unroll
    for (int j = 0; j < 12; j++) hn[j] = gn1[j] * h[j] * sc;
    float y1[32];
#pragma unroll
    for (int j = 0; j < 32; j++) y1[j] = 0.f;
#pragma unroll
    for (int r = 0; r < 12; r++) {
        float a = hn[r];
#pragma unroll
        for (int j = 0; j < 32; j++) y1[j] += a * gw1[r * 32 + j];
    }
    float h2[16];
#pragma unroll
    for (int k = 0; k < 16; k++) h2[k] = y1[k] * gelu_tanh(y1[16 + k]);

    // layer 2: rmsnorm(16) @ gw2(16x32) -> geglu -> 16
    ss = 0.f;
#pragma unroll
    for (int j = 0; j < 16; j++) ss += h2[j] * h2[j];
    sc = 1.0f / (sqrtf(ss / 16.0f) + 1e-8f);
    float hn2[16];
#pragma unroll
    for (int j = 0; j < 16; j++) hn2[j] = gn2[j] * h2[j] * sc;
    float y2[32];
#pragma unroll
    for (int j = 0; j < 32; j++) y2[j] = 0.f;
#pragma unroll
    for (int r = 0; r < 16; r++) {
        float a = hn2[r];
#pragma unroll
        for (int j = 0; j < 32; j++) y2[j] += a * gw2[r * 32 + j];
    }
    float h3[16];
#pragma unroll
    for (int k = 0; k < 16; k++) h3[k] = y2[k] * gelu_tanh(y2[16 + k]);

    // layer 3: rmsnorm(16) @ gw3(16x3) -> sigmoid
    ss = 0.f;
#pragma unroll
    for (int j = 0; j < 16; j++) ss += h3[j] * h3[j];
    sc = 1.0f / (sqrtf(ss / 16.0f) + 1e-8f);
    float z3[3] = {0.f, 0.f, 0.f};
#pragma unroll
    for (int r = 0; r < 16; r++) {
        float a = gn3[r] * h3[r] * sc;
#pragma unroll
        for (int j = 0; j < 3; j++) z3[j] += a * gw3[r * 3 + j];
    }
    g_p[i * 3 + 0] = sigmoidf_(z3[0]);
    g_p[i * 3 + 1] = sigmoidf_(z3[1]);
    g_p[i * 3 + 2] = sigmoidf_(z3[2]);
}

// ---------------- K2: table gather + rmsnorm(vn1) -> Xn ----------------------
__global__ void k2_gather(const float* __restrict__ t,
                          const float* __restrict__ table0, const float* __restrict__ table1,
                          const float* __restrict__ table2, const float* __restrict__ table3,
                          const float* __restrict__ st1, const float* __restrict__ st2,
                          const float* __restrict__ tf, const float* __restrict__ vn1)
{
    int i = blockIdx.x;
    __shared__ const float* segp[47];
    __shared__ float feat[TOTAL];
    __shared__ float red[128];

    float p0 = g_p[i * 3 + 0], p1 = g_p[i * 3 + 1], p2 = g_p[i * 3 + 2];
    float tt = t[i];

    int s = threadIdx.x;
    if (s < 47) {
        const float* base = nullptr;
        if (s < 28) {
            int tb = s / 7;   // table id
            int o = s % 7;    // 0 base, 1..6 FACE3
            int d, F; const float* T;
            if (tb == 0)      { d = 128; F = 16;  T = table0; }
            else if (tb == 1) { d = 64;  F = 32;  T = table1; }
            else if (tb == 2) { d = 32;  F = 64;  T = table2; }
            else              { d = 16;  F = 128; T = table3; }
            int ix = (int)(p0 * (float)(d - 1));
            int iy = (int)(p1 * (float)(d - 1));
            int iz = (int)(p2 * (float)(d - 1));
            if (o > 0) {
                ix = wrapi(ix + FACE3[o - 1][0], d);
                iy = wrapi(iy + FACE3[o - 1][1], d);
                iz = wrapi(iz + FACE3[o - 1][2], d);
            }
            base = T + (size_t)((ix * d + iy) * d + iz) * F;
        } else if (s < 46) {
            int grp = (s - 28) / 9;   // 0: st1, 1: st2
            int o = (s - 28) % 9;
            if (grp == 0) {
                int a = (int)(p0 * 15.0f), b = (int)(p1 * 15.0f),
                    c = (int)(p2 * 15.0f), e = (int)(tt * 63.0f);
                if (o > 0) {
                    a = wrapi(a + ST8[o - 1][0], 16);
                    b = wrapi(b + ST8[o - 1][1], 16);
                    c = wrapi(c + ST8[o - 1][2], 16);
                    e = wrapi(e + ST8[o - 1][3], 64);
                }
                base = st1 + (size_t)(((a * 16 + b) * 16 + c) * 64 + e) * 64;
            } else {
                int a = (int)(p0 * 63.0f), b = (int)(p1 * 63.0f),
                    c = (int)(p2 * 31.0f), e = (int)(tt * 15.0f);
                if (o > 0) {
                    a = wrapi(a + ST8[o - 1][0], 64);
                    b = wrapi(b + ST8[o - 1][1], 64);
                    c = wrapi(c + ST8[o - 1][2], 32);
                    e = wrapi(e + ST8[o - 1][3], 16);
                }
                base = st2 + (size_t)(((a * 64 + b) * 32 + c) * 16 + e) * 8;
            }
        } else {
            int a = (int)(p0 * 3.0f), b = (int)(p1 * 3.0f),
                c = (int)(p2 * 3.0f), e = (int)(tt * 65535.0f);
            base = tf + (size_t)(((a * 4 + b) * 4 + c) * 65536 + e) * 8;
        }
        segp[s] = base;
    }
    __syncthreads();

    float ss = 0.f;
    for (int f = threadIdx.x; f < TOTAL; f += 128) {
        int seg, off;
        if (f < 112)       { seg = f >> 4;                off = f & 15; }
        else if (f < 336)  { int g = f - 112;  seg = 7  + (g >> 5); off = g & 31; }
        else if (f < 784)  { int g = f - 336;  seg = 14 + (g >> 6); off = g & 63; }
        else if (f < 1680) { int g = f - 784;  seg = 21 + (g >> 7); off = g & 127; }
        else if (f < 2256) { int g = f - 1680; seg = 28 + (g >> 6); off = g & 63; }
        else if (f < 2328) { int g = f - 2256; seg = 37 + (g >> 3); off = g & 7; }
        else               { seg = 46;                    off = f - 2328; }
        float v = segp[seg][off];
        feat[f] = v;
        ss += v * v;
    }
    red[threadIdx.x] = ss;
    __syncthreads();
    for (int w = 64; w > 0; w >>= 1) {
        if (threadIdx.x < w) red[threadIdx.x] += red[threadIdx.x + w];
        __syncthreads();
    }
    float rms = sqrtf(red[0] / (float)TOTAL);
    float sc = 1.0f / (rms + 1e-8f);
    float* out = g_Xn + (size_t)i * TOTAL;
    for (int f = threadIdx.x; f < TOTAL; f += 128)
        out[f] = vn1[f] * feat[f] * sc;
}

// ---------------- K3: GEMM1  Y[N,4672] = Xn[N,2336] @ vw1 --------------------
#define BM 128
#define BN 128
#define BK 16
__global__ __launch_bounds__(256) void k3_gemm1(const float* __restrict__ B, int K, int Ncols)
{
    __shared__ float As[BK][BM];
    __shared__ float Bs[BK][BN];
    const float* A = g_Xn;
    float* C = g_Y;

    int tid = threadIdx.x;
    int tx = tid % 16, ty = tid / 16;
    int bm = blockIdx.y * BM;
    int bn = blockIdx.x * BN;

    float acc[8][8];
#pragma unroll
    for (int a = 0; a < 8; a++)
#pragma unroll
        for (int b = 0; b < 8; b++) acc[a][b] = 0.f;

    int ar = tid >> 2;           // 0..63
    int ac = (tid & 3) * 4;      // 0,4,8,12
    int br = tid >> 5;           // 0..7
    int bc = (tid & 31) * 4;     // 0..124

    for (int k0 = 0; k0 < K; k0 += BK) {
#pragma unroll
        for (int ii = 0; ii < 2; ii++) {
            int row = ar + ii * 64;
            float4 v = *(const float4*)&A[(size_t)(bm + row) * K + k0 + ac];
            As[ac + 0][row] = v.x; As[ac + 1][row] = v.y;
            As[ac + 2][row] = v.z; As[ac + 3][row] = v.w;
        }
#pragma unroll
        for (int ii = 0; ii < 2; ii++) {
            int row = br + ii * 8;
            int col = bn + bc;
            float4 v = make_float4(0.f, 0.f, 0.f, 0.f);
            if (col < Ncols) v = *(const float4*)&B[(size_t)(k0 + row) * Ncols + col];
            *(float4*)&Bs[row][bc] = v;
        }
        __syncthreads();
#pragma unroll
        for (int k = 0; k < BK; k++) {
            float af[8], bf[8];
#pragma unroll
            for (int a = 0; a < 8; a++) af[a] = As[k][ty * 8 + a];
#pragma unroll
            for (int b = 0; b < 8; b++) bf[b] = Bs[k][tx * 8 + b];
#pragma unroll
            for (int a = 0; a < 8; a++)
#pragma unroll
                for (int b = 0; b < 8; b++) acc[a][b] += af[a] * bf[b];
        }
        __syncthreads();
    }
#pragma unroll
    for (int a = 0; a < 8; a++) {
        int row = bm + ty * 8 + a;
#pragma unroll
        for (int b = 0; b < 8; b += 4) {
            int col = bn + tx * 8 + b;
            if (col < Ncols) {
                *(float4*)&C[(size_t)row * Ncols + col] =
                    make_float4(acc[a][b], acc[a][b + 1], acc[a][b + 2], acc[a][b + 3]);
            }
        }
    }
}

// ---------------- K4: geglu + rmsnorm(vn2) -> Vn (reuses g_Xn) ----------------
__global__ void k4_act(const float* __restrict__ vn2)
{
    int i = blockIdx.x;
    __shared__ float vbuf[TOTAL];
    __shared__ float red[256];
    const float* Yr = g_Y + (size_t)i * TWOTOTAL;

    float ss = 0.f;
    for (int j = threadIdx.x; j < TOTAL; j += 256) {
        float a = Yr[j];
        float g = Yr[TOTAL + j];
        float v = a * gelu_tanh(g);
        vbuf[j] = v;
        ss += v * v;
    }
    red[threadIdx.x] = ss;
    __syncthreads();
    for (int w = 128; w > 0; w >>= 1) {
        if (threadIdx.x < w) red[threadIdx.x] += red[threadIdx.x + w];
        __syncthreads();
    }
    float rms = sqrtf(red[0] / (float)TOTAL);
    float sc = 1.0f / (rms + 1e-8f);
    float* out = g_Xn + (size_t)i * TOTAL;
    for (int j = threadIdx.x; j < TOTAL; j += 256)
        out[j] = vn2[j] * vbuf[j] * sc;
}

// ---------------- K5: GEMM2  down[N,64] = Vn[N,2336] @ vw2 --------------------
__global__ __launch_bounds__(256) void k5_gemm2(const float* __restrict__ B, int K)
{
    __shared__ float As[BK][BM];
    __shared__ float Bs[BK][64];
    const float* A = g_Xn;
    float* C = g_down;

    int tid = threadIdx.x;
    int tx = tid % 16, ty = tid / 16;   // col = tx*4 (TN=4), row = ty*8 (TM=8)
    int bm = blockIdx.y * BM;

    float acc[8][4];
#pragma unroll
    for (int a = 0; a < 8; a++)
#pragma unroll
        for (int b = 0; b < 4; b++) acc[a][b] = 0.f;

    int ar = tid >> 2;
    int ac = (tid & 3) * 4;
    int br = tid >> 4;          // 0..15
    int bc = (tid & 15) * 4;    // 0..60

    for (int k0 = 0; k0 < K; k0 += BK) {
#pragma unroll
        for (int ii = 0; ii < 2; ii++) {
            int row = ar + ii * 64;
            float4 v = *(const float4*)&A[(size_t)(bm + row) * K + k0 + ac];
            As[ac + 0][row] = v.x; As[ac + 1][row] = v.y;
            As[ac + 2][row] = v.z; As[ac + 3][row] = v.w;
        }
        {
            float4 v = *(const float4*)&B[(size_t)(k0 + br) * 64 + bc];
            *(float4*)&Bs[br][bc] = v;
        }
        __syncthreads();
#pragma unroll
        for (int k = 0; k < BK; k++) {
            float af[8], bf[4];
#pragma unroll
            for (int a = 0; a < 8; a++) af[a] = As[k][ty * 8 + a];
#pragma unroll
            for (int b = 0; b < 4; b++) bf[b] = Bs[k][tx * 4 + b];
#pragma unroll
            for (int a = 0; a < 8; a++)
#pragma unroll
                for (int b = 0; b < 4; b++) acc[a][b] += af[a] * bf[b];
        }
        __syncthreads();
    }
#pragma unroll
    for (int a = 0; a < 8; a++) {
        int row = bm + ty * 8 + a;
        *(float4*)&C[(size_t)row * 64 + tx * 4] =
            make_float4(acc[a][0], acc[a][1], acc[a][2], acc[a][3]);
    }
}

// ---------------- K6: final linear  out = [down, p, t] @ fw + fb --------------
__global__ void k6_final(const float* __restrict__ t,
                         const float* __restrict__ fw, const float* __restrict__ fb,
                         float* __restrict__ out)
{
    int i = blockIdx.x * blockDim.x + threadIdx.x;
    if (i >= NPTS) return;
    const float* dr = g_down + (size_t)i * 64;
    float o0 = fb[0], o1 = fb[1], o2 = fb[2], o3 = fb[3];
#pragma unroll 8
    for (int r = 0; r < 64; r++) {
        float a = dr[r];
        o0 += a * fw[r * 4 + 0];
        o1 += a * fw[r * 4 + 1];
        o2 += a * fw[r * 4 + 2];
        o3 += a * fw[r * 4 + 3];
    }
    float p0 = g_p[i * 3 + 0], p1 = g_p[i * 3 + 1], p2 = g_p[i * 3 + 2];
    float tv = t[i];
    o0 += p0 * fw[256 + 0] + p1 * fw[260 + 0] + p2 * fw[264 + 0] + tv * fw[268 + 0];
    o1 += p0 * fw[256 + 1] + p1 * fw[260 + 1] + p2 * fw[264 + 1] + tv * fw[268 + 1];
    o2 += p0 * fw[256 + 2] + p1 * fw[260 + 2] + p2 * fw[264 + 2] + tv * fw[268 + 2];
    o3 += p0 * fw[256 + 3] + p1 * fw[260 + 3] + p2 * fw[264 + 3] + tv * fw[268 + 3];
    out[i * 4 + 0] = o0;
    out[i * 4 + 1] = o1;
    out[i * 4 + 2] = o2;
    out[i * 4 + 3] = o3;
}

// ---------------- launcher ----------------------------------------------------
extern "C" void kernel_launch(void* const* d_in, const int* in_sizes, int n_in,
                              void* d_out, int out_size)
{
    const float* pos      = (const float*)d_in[0];
    // d_in[1] = dir (unused by reference)
    const float* t        = (const float*)d_in[2];
    const float* table0   = (const float*)d_in[3];
    const float* table1   = (const float*)d_in[4];
    const float* table2   = (const float*)d_in[5];
    const float* table3   = (const float*)d_in[6];
    const float* st1      = (const float*)d_in[7];
    const float* st2      = (const float*)d_in[8];
    const float* tf       = (const float*)d_in[9];
    const float* sph_proj = (const float*)d_in[10];
    const float* tb1      = (const float*)d_in[11];
    const float* tb2      = (const float*)d_in[12];
    const float* gn1      = (const float*)d_in[13];
    const float* gw1      = (const float*)d_in[14];
    const float* gn2      = (const float*)d_in[15];
    const float* gw2      = (const float*)d_in[16];
    const float* gn3      = (const float*)d_in[17];
    const float* gw3      = (const float*)d_in[18];
    const float* vn1      = (const float*)d_in[19];
    const float* vw1      = (const float*)d_in[20];
    const float* vn2      = (const float*)d_in[21];
    const float* vw2      = (const float*)d_in[22];
    const float* fw       = (const float*)d_in[23];
    const float* fb       = (const float*)d_in[24];
    float* out = (float*)d_out;

    k1_preamble<<<NPTS / 256, 256>>>(pos, t, sph_proj, tb1, tb2,
                                     gn1, gw1, gn2, gw2, gn3, gw3);
    k2_gather<<<NPTS, 128>>>(t, table0, table1, table2, table3, st1, st2, tf, vn1);

    dim3 g1((TWOTOTAL + BN - 1) / BN, NPTS / BM);   // (37, 256)
    k3_gemm1<<<g1, 256>>>(vw1, TOTAL, TWOTOTAL);

    k4_act<<<NPTS, 256>>>(vn2);

    dim3 g2(1, NPTS / BM);                          // (1, 256)
    k5_gemm2<<<g2, 256>>>(vw2, TOTAL);

    k6_final<<<NPTS / 256, 256>>>(t, fw, fb, out);
}

// round 3
// speedup vs baseline: 2.7278x; 2.7278x over previous
#include <cuda_runtime.h>
#include <cuda_bf16.h>
#include <math.h>
#include <stdint.h>

#define NPTS 32768
#define TOTAL 2336
#define KPAD 2368          // TOTAL padded to multiple of 64
#define TWOTOTAL 4672
#define INNER 64
#define YW 4864            // padded GEMM1 output width (19 * 256)
#define AW 4736            // g_Abf row: [hi(2368) | lo(2368)]
#define WTS 4736           // g_WT row:  [hi(2368) | lo(2368)]
#define WTROWS 4864

// ---------------- scratch (static device memory; zero-initialized) -----------
__device__ float g_p[NPTS * 3];
__device__ __nv_bfloat16 g_Abf[(size_t)NPTS * AW];
__device__ __nv_bfloat16 g_WT[(size_t)WTROWS * WTS];
__device__ float g_Y[(size_t)NPTS * YW];
__device__ float g_Vn[(size_t)NPTS * TOTAL];
__device__ float g_down[NPTS * INNER];

// ---------------- common helpers ---------------------------------------------
__device__ __forceinline__ uint32_t smem_u32(const void* p) {
    uint32_t a;
    asm("{ .reg .u64 t; cvta.to.shared.u64 t, %1; cvt.u32.u64 %0, t; }" : "=r"(a) : "l"(p));
    return a;
}
__device__ __forceinline__ float sigmoidf_(float x) { return 1.0f / (1.0f + expf(-x)); }
__device__ __forceinline__ float gelu_tanh(float x) {
    float x3 = x * x * x;
    return 0.5f * x * (1.0f + tanhf(0.7978845608028654f * (x + 0.044715f * x3)));
}
__device__ __forceinline__ int wrapi(int v, int d) {
    if (v < 0) v += d; else if (v >= d) v -= d; return v;
}
__device__ const int FACE3[6][3] = {{1,0,0},{-1,0,0},{0,1,0},{0,-1,0},{0,0,1},{0,0,-1}};
__device__ const int ST8[8][4]   = {{1,0,0,0},{-1,0,0,0},{0,1,0,0},{0,-1,0,0},
                                    {0,0,1,0},{0,0,-1,0},{0,0,0,1},{0,0,0,-1}};

// ---------------- K1: per-point preamble MLP -> p ----------------------------
__global__ void k1_preamble(const float* __restrict__ pos, const float* __restrict__ t,
                            const float* __restrict__ sph_proj,
                            const float* __restrict__ tb1, const float* __restrict__ tb2,
                            const float* __restrict__ gn1, const float* __restrict__ gw1,
                            const float* __restrict__ gn2, const float* __restrict__ gw2,
                            const float* __restrict__ gn3, const float* __restrict__ gw3)
{
    int i = blockIdx.x * blockDim.x + threadIdx.x;
    if (i >= NPTS) return;

    float x = pos[i * 3 + 0], y = pos[i * 3 + 1], z = pos[i * 3 + 2];
    float rho = sqrtf(x * x + y * y + z * z);
    float phi = atan2f(y, x);
    float cz = z / rho;
    cz = fminf(1.0f, fmaxf(-1.0f, cz));
    float theta = acosf(cz);

    float h[12];
#pragma unroll
    for (int j = 0; j < 8; j++)
        h[j] = rho * sph_proj[j] + phi * sph_proj[8 + j] + theta * sph_proj[16 + j];
    float tv = t[i];
    float ct = cosf(tv + tb1[0]);
    float st = sinf(tv + tb2[0]);
    h[8] = ct; h[9] = st;
    h[10] = ct * sigmoidf_(ct);
    h[11] = st * sigmoidf_(st);

    float ss = 0.f;
#pragma unroll
    for (int j = 0; j < 12; j++) ss += h[j] * h[j];
    float sc = 1.0f / (sqrtf(ss / 12.0f) + 1e-8f);
    float hn[12];
#pragma unroll
    for (int j = 0; j < 12; j++) hn[j] = gn1[j] * h[j] * sc;
    float y1[32];
#pragma unroll
    for (int j = 0; j < 32; j++) y1[j] = 0.f;
#pragma unroll
    for (int r = 0; r < 12; r++) {
        float a = hn[r];
#pragma unroll
        for (int j = 0; j < 32; j++) y1[j] += a * gw1[r * 32 + j];
    }
    float h2[16];
#pragma unroll
    for (int k = 0; k < 16; k++) h2[k] = y1[k] * gelu_tanh(y1[16 + k]);

    ss = 0.f;
#pragma unroll
    for (int j = 0; j < 16; j++) ss += h2[j] * h2[j];
    sc = 1.0f / (sqrtf(ss / 16.0f) + 1e-8f);
    float hn2[16];
#pragma unroll
    for (int j = 0; j < 16; j++) hn2[j] = gn2[j] * h2[j] * sc;
    float y2[32];
#pragma unroll
    for (int j = 0; j < 32; j++) y2[j] = 0.f;
#pragma unroll
    for (int r = 0; r < 16; r++) {
        float a = hn2[r];
#pragma unroll
        for (int j = 0; j < 32; j++) y2[j] += a * gw2[r * 32 + j];
    }
    float h3[16];
#pragma unroll
    for (int k = 0; k < 16; k++) h3[k] = y2[k] * gelu_tanh(y2[16 + k]);

    ss = 0.f;
#pragma unroll
    for (int j = 0; j < 16; j++) ss += h3[j] * h3[j];
    sc = 1.0f / (sqrtf(ss / 16.0f) + 1e-8f);
    float z3[3] = {0.f, 0.f, 0.f};
#pragma unroll
    for (int r = 0; r < 16; r++) {
        float a = gn3[r] * h3[r] * sc;
#pragma unroll
        for (int j = 0; j < 3; j++) z3[j] += a * gw3[r * 3 + j];
    }
    g_p[i * 3 + 0] = sigmoidf_(z3[0]);
    g_p[i * 3 + 1] = sigmoidf_(z3[1]);
    g_p[i * 3 + 2] = sigmoidf_(z3[2]);
}

// ---------------- K2: gather + rmsnorm(vn1) -> bf16 hi/lo in g_Abf ------------
__global__ void k2_gather(const float* __restrict__ t,
                          const float* __restrict__ table0, const float* __restrict__ table1,
                          const float* __restrict__ table2, const float* __restrict__ table3,
                          const float* __restrict__ st1, const float* __restrict__ st2,
                          const float* __restrict__ tf, const float* __restrict__ vn1)
{
    int i = blockIdx.x;
    __shared__ const float* segp[47];
    __shared__ float feat[TOTAL];
    __shared__ float red[128];

    float p0 = g_p[i * 3 + 0], p1 = g_p[i * 3 + 1], p2 = g_p[i * 3 + 2];
    float tt = t[i];

    int s = threadIdx.x;
    if (s < 47) {
        const float* base = nullptr;
        if (s < 28) {
            int tb = s / 7;
            int o = s % 7;
            int d, F; const float* T;
            if (tb == 0)      { d = 128; F = 16;  T = table0; }
            else if (tb == 1) { d = 64;  F = 32;  T = table1; }
            else if (tb == 2) { d = 32;  F = 64;  T = table2; }
            else              { d = 16;  F = 128; T = table3; }
            int ix = (int)(p0 * (float)(d - 1));
            int iy = (int)(p1 * (float)(d - 1));
            int iz = (int)(p2 * (float)(d - 1));
            if (o > 0) {
                ix = wrapi(ix + FACE3[o - 1][0], d);
                iy = wrapi(iy + FACE3[o - 1][1], d);
                iz = wrapi(iz + FACE3[o - 1][2], d);
            }
            base = T + (size_t)((ix * d + iy) * d + iz) * F;
        } else if (s < 46) {
            int grp = (s - 28) / 9;
            int o = (s - 28) % 9;
            if (grp == 0) {
                int a = (int)(p0 * 15.0f), b = (int)(p1 * 15.0f),
                    c = (int)(p2 * 15.0f), e = (int)(tt * 63.0f);
                if (o > 0) {
                    a = wrapi(a + ST8[o - 1][0], 16);
                    b = wrapi(b + ST8[o - 1][1], 16);
                    c = wrapi(c + ST8[o - 1][2], 16);
                    e = wrapi(e + ST8[o - 1][3], 64);
                }
                base = st1 + (size_t)(((a * 16 + b) * 16 + c) * 64 + e) * 64;
            } else {
                int a = (int)(p0 * 63.0f), b = (int)(p1 * 63.0f),
                    c = (int)(p2 * 31.0f), e = (int)(tt * 15.0f);
                if (o > 0) {
                    a = wrapi(a + ST8[o - 1][0], 64);
                    b = wrapi(b + ST8[o - 1][1], 64);
                    c = wrapi(c + ST8[o - 1][2], 32);
                    e = wrapi(e + ST8[o - 1][3], 16);
                }
                base = st2 + (size_t)(((a * 64 + b) * 32 + c) * 16 + e) * 8;
            }
        } else {
            int a = (int)(p0 * 3.0f), b = (int)(p1 * 3.0f),
                c = (int)(p2 * 3.0f), e = (int)(tt * 65535.0f);
            base = tf + (size_t)(((a * 4 + b) * 4 + c) * 65536 + e) * 8;
        }
        segp[s] = base;
    }
    __syncthreads();

    float ss = 0.f;
    for (int f = threadIdx.x; f < TOTAL; f += 128) {
        int seg, off;
        if (f < 112)       { seg = f >> 4;                off = f & 15; }
        else if (f < 336)  { int g = f - 112;  seg = 7  + (g >> 5); off = g & 31; }
        else if (f < 784)  { int g = f - 336;  seg = 14 + (g >> 6); off = g & 63; }
        else if (f < 1680) { int g = f - 784;  seg = 21 + (g >> 7); off = g & 127; }
        else if (f < 2256) { int g = f - 1680; seg = 28 + (g >> 6); off = g & 63; }
        else if (f < 2328) { int g = f - 2256; seg = 37 + (g >> 3); off = g & 7; }
        else               { seg = 46;                    off = f - 2328; }
        float v = segp[seg][off];
        feat[f] = v;
        ss += v * v;
    }
    red[threadIdx.x] = ss;
    __syncthreads();
    for (int w = 64; w > 0; w >>= 1) {
        if (threadIdx.x < w) red[threadIdx.x] += red[threadIdx.x + w];
        __syncthreads();
    }
    float rms = sqrtf(red[0] / (float)TOTAL);
    float sc = 1.0f / (rms + 1e-8f);
    __nv_bfloat16* orow = g_Abf + (size_t)i * AW;
    for (int f = threadIdx.x; f < TOTAL; f += 128) {
        float v = vn1[f] * feat[f] * sc;
        __nv_bfloat16 h = __float2bfloat16(v);
        float hf = __bfloat162float(h);
        __nv_bfloat16 l = __float2bfloat16(v - hf);
        orow[f] = h;
        orow[KPAD + f] = l;
    }
}

// ---------------- K2b: transpose + split vw1 -> g_WT --------------------------
__global__ void k_convW(const float* __restrict__ vw1)
{
    __shared__ float sh[32][33];
    int n0 = blockIdx.x * 32, k0 = blockIdx.y * 32;
    int tx = threadIdx.x, ty = threadIdx.y;   // 32 x 8
#pragma unroll
    for (int ii = 0; ii < 4; ii++) {
        int r = ty + ii * 8;
        int n = n0 + tx;
        float v = 0.f;
        if (n < TWOTOTAL) v = vw1[(size_t)(k0 + r) * TWOTOTAL + n];
        sh[r][tx] = v;
    }
    __syncthreads();
#pragma unroll
    for (int ii = 0; ii < 4; ii++) {
        int r = ty + ii * 8;
        int n = n0 + r;
        int k = k0 + tx;
        float v = sh[tx][r];
        __nv_bfloat16 h = __float2bfloat16(v);
        float hf = __bfloat162float(h);
        __nv_bfloat16 l = __float2bfloat16(v - hf);
        g_WT[(size_t)n * WTS + k] = h;
        g_WT[(size_t)n * WTS + KPAD + k] = l;
    }
}

// ---------------- K3: GEMM1 (dual path: tcgen05 or mma.sync) -----------------
// Tile per CTA: 128m x 256n; K' = 3 segments of 2368 (hi/lo split).
#define KSTAGE 64
#define STAGES_PER_SEG 37
#define NSTAGES (3 * STAGES_PER_SEG)
#define SMEM_DYN 111616

#if defined(__CUDA_ARCH_FEAT_SM103_ALL)
// --- tcgen05 helpers ---
__device__ __forceinline__ uint32_t elect_one() {
    uint32_t p;
    asm volatile("{ .reg .pred p; elect.sync _|p, 0xFFFFFFFF; selp.b32 %0,1,0,p; }" : "=r"(p));
    return p;
}
#define MBARRIER_INIT(addr, cnt) \
    asm volatile("mbarrier.init.shared.b64 [%0], %1;" :: "r"(addr), "r"(cnt) : "memory")
#define MBARRIER_WAIT_PARITY(addr, parity) do { \
    uint32_t _m = (addr); uint32_t _p = (parity); uint32_t _d; \
    asm volatile("{ .reg .pred p; mbarrier.try_wait.parity.acquire.cta.shared::cta.b64 p, [%1], %2; selp.b32 %0,1,0,p; }" \
        : "=r"(_d) : "r"(_m), "r"(_p) : "memory"); \
    if (!_d) { \
        asm volatile("{ .reg .pred P1; WL_%=: mbarrier.try_wait.parity.acquire.cta.shared::cta.b64 P1, [%0], %1, 0x989680; @P1 bra.uni WD_%=; bra.uni WL_%=; WD_%=: }" \
            :: "r"(_m), "r"(_p) : "memory"); \
    } } while (0)
#define TC_ALLOC(slot, n)  asm volatile("tcgen05.alloc.cta_group::1.sync.aligned.shared::cta.b32 [%0], %1;" :: "r"(slot), "r"(n) : "memory")
#define TC_DEALLOC(t, n)   asm volatile("tcgen05.dealloc.cta_group::1.sync.aligned.b32 %0, %1;" :: "r"(t), "r"(n))
#define TC_RELINQ()        asm volatile("tcgen05.relinquish_alloc_permit.cta_group::1.sync.aligned;")
#define TC_COMMIT(mbar)    asm volatile("tcgen05.commit.cta_group::1.mbarrier::arrive::one.shared::cluster.b64 [%0];" :: "r"(mbar) : "memory")
#define TC_WAIT_LD()       asm volatile("tcgen05.wait::ld.sync.aligned;" ::: "memory")
#define TC_FENCE_AFTER()   asm volatile("tcgen05.fence::after_thread_sync;" ::: "memory")
#define FENCE_ASYNC_SH()   asm volatile("fence.proxy.async.shared::cta;" ::: "memory")
#define TC_LD_X32(r, addr) \
    asm volatile("tcgen05.ld.sync.aligned.32x32b.x32.b32 " \
        "{%0,%1,%2,%3,%4,%5,%6,%7,%8,%9,%10,%11,%12,%13,%14,%15," \
        "%16,%17,%18,%19,%20,%21,%22,%23,%24,%25,%26,%27,%28,%29,%30,%31}, [%32];" \
        : "=r"((r)[0]),"=r"((r)[1]),"=r"((r)[2]),"=r"((r)[3]),"=r"((r)[4]),"=r"((r)[5]),"=r"((r)[6]),"=r"((r)[7]), \
          "=r"((r)[8]),"=r"((r)[9]),"=r"((r)[10]),"=r"((r)[11]),"=r"((r)[12]),"=r"((r)[13]),"=r"((r)[14]),"=r"((r)[15]), \
          "=r"((r)[16]),"=r"((r)[17]),"=r"((r)[18]),"=r"((r)[19]),"=r"((r)[20]),"=r"((r)[21]),"=r"((r)[22]),"=r"((r)[23]), \
          "=r"((r)[24]),"=r"((r)[25]),"=r"((r)[26]),"=r"((r)[27]),"=r"((r)[28]),"=r"((r)[29]),"=r"((r)[30]),"=r"((r)[31]) \
        : "r"(addr))
static constexpr uint64_t SMEM_DESC_BASE =
    (uint64_t(2) << 61) | (uint64_t(1) << 46) | (uint64_t(64) << 32) | (uint64_t(1) << 16);
__device__ __forceinline__ uint64_t make_desc(uint32_t addr) {
    return SMEM_DESC_BASE | ((uint64_t)(addr >> 4) & 0x3FFF);
}
__device__ __forceinline__ void mma_f16_ss(uint32_t d, uint64_t a, uint64_t b,
                                           uint32_t idesc, uint32_t en) {
    asm volatile("{ .reg .pred p; setp.ne.u32 p, %4, 0;"
                 "tcgen05.mma.cta_group::1.kind::f16 [%0], %1, %2, %3, {%5,%5,%5,%5}, p; }"
                 :: "r"(d), "l"(a), "l"(b), "r"(idesc), "r"(en), "r"(0u) : "memory");
}
#endif

// --- mma.sync helpers (baseline PTX, always legal) ---
#define CP_ASYNC16(smem, gmem) \
    asm volatile("cp.async.cg.shared.global [%0], [%1], 16;" :: "r"(smem), "l"(gmem) : "memory")
#define CP_COMMIT() asm volatile("cp.async.commit_group;" ::: "memory")
#define CP_WAIT1()  asm volatile("cp.async.wait_group 1;" ::: "memory")
#define CP_WAIT0()  asm volatile("cp.async.wait_group 0;" ::: "memory")
#define LDMX4(r0, r1, r2, r3, addr) \
    asm volatile("ldmatrix.sync.aligned.m8n8.x4.shared.b16 {%0,%1,%2,%3}, [%4];" \
        : "=r"(r0), "=r"(r1), "=r"(r2), "=r"(r3) : "r"(addr))
#define MMA16816(d, a, b) \
    asm volatile("mma.sync.aligned.m16n8k16.row.col.f32.bf16.bf16.f32 " \
        "{%0,%1,%2,%3},{%4,%5,%6,%7},{%8,%9},{%0,%1,%2,%3};" \
        : "+f"((d)[0]), "+f"((d)[1]), "+f"((d)[2]), "+f"((d)[3]) \
        : "r"((a)[0]), "r"((a)[1]), "r"((a)[2]), "r"((a)[3]), "r"((b)[0]), "r"((b)[1]))

__global__ void __launch_bounds__(256, 1) k3_gemm1(const __nv_bfloat16* __restrict__ Abf,
                                                   const __nv_bfloat16* __restrict__ WT,
                                                   float* __restrict__ C)
{
    extern __shared__ char smem[];
    uint32_t sbase = smem_u32(smem);
    int tid = threadIdx.x;
    int wid = tid >> 5, lid = tid & 31;
    int bm = blockIdx.y * 128;
    int bn = blockIdx.x * 256;

#if defined(__CUDA_ARCH_FEAT_SM103_ALL)
    // ---------------- tcgen05 path ----------------
    const uint32_t TSLOT = sbase;
    const uint32_t MBAR0 = sbase + 16;
    const uint32_t MBAR1 = sbase + 24;
    const uint32_t SA = sbase + 1024;              // 2 x 16KB
    const uint32_t SB = sbase + 1024 + 32768;      // 2 x 32KB
    char* sa_ptr = smem + 1024;
    char* sb_ptr = smem + 1024 + 32768;

    if (wid == 0) TC_ALLOC(TSLOT, 512);
    if (tid == 0) { MBARRIER_INIT(MBAR0, 1); MBARRIER_INIT(MBAR1, 1); }
    __syncthreads();
    uint32_t tmem;
    asm volatile("ld.shared.b32 %0, [%1];" : "=r"(tmem) : "r"(TSLOT));

    // dtype F32, a/b BF16, N=256, M=128
    const uint32_t IDESC = (1u << 4) | (1u << 7) | (1u << 10) | (32u << 17) | (8u << 24);
    int ph0 = 0, ph1 = 0;

    for (int s = 0; s < NSTAGES; s++) {
        int b = s & 1;
        if (s >= 2) {
            if (b == 0) { MBARRIER_WAIT_PARITY(MBAR0, ph0); ph0 ^= 1; }
            else        { MBARRIER_WAIT_PARITY(MBAR1, ph1); ph1 ^= 1; }
        }
        int seg = s / STAGES_PER_SEG;
        int tst = s - seg * STAGES_PER_SEG;
        int ks = tst * KSTAGE;
        int aoff = (seg == 1) ? KPAD : 0;
        int boff = (seg == 2) ? KPAD : 0;
        char* abuf = sa_ptr + b * 16384;
        char* bbuf = sb_ptr + b * 32768;

#pragma unroll
        for (int j = 0; j < 4; j++) {
            int idx = tid + j * 256;          // A: 1024 vecs (128 rows x 8)
            int row = idx >> 3, c = idx & 7;
            uint32_t off = (uint32_t)(row * 128 + c * 16);
            uint32_t sw = off ^ ((off >> 3) & 0x70);
            *(uint4*)(abuf + sw) =
                *(const uint4*)(Abf + (size_t)(bm + row) * AW + aoff + ks + c * 8);
        }
#pragma unroll
        for (int j = 0; j < 8; j++) {
            int idx = tid + j * 256;          // B: 2048 vecs (256 rows x 8)
            int row = idx >> 3, c = idx & 7;
            uint32_t off = (uint32_t)(row * 128 + c * 16);
            uint32_t sw = off ^ ((off >> 3) & 0x70);
            *(uint4*)(bbuf + sw) =
                *(const uint4*)(WT + (size_t)(bn + row) * WTS + boff + ks + c * 8);
        }
        FENCE_ASYNC_SH();
        __syncthreads();
        if (wid == 0) {
            if (elect_one()) {
                uint64_t ad = make_desc(SA + b * 16384);
                uint64_t bd = make_desc(SB + b * 32768);
#pragma unroll
                for (int c = 0; c < 4; c++) {
                    uint32_t en = (s > 0 || c > 0) ? 1u : 0u;
                    mma_f16_ss(tmem, ad + c * 2, bd + c * 2, IDESC, en);
                }
                if (b == 0) TC_COMMIT(MBAR0); else TC_COMMIT(MBAR1);
            }
        }
    }
    MBARRIER_WAIT_PARITY(MBAR0, ph0);   // last stage (s=110) is buffer 0
    TC_FENCE_AFTER();

    // epilogue: warp w -> subpartition w&3 (m rows), col half w>>2
    {
        int sub = wid & 3, colh = wid >> 2;
        int m = bm + sub * 32 + lid;
        uint32_t dbase = tmem + colh * 128;
#pragma unroll
        for (int base = 0; base < 128; base += 32) {
            uint32_t r[32];
            TC_LD_X32(r, dbase + base);
            TC_WAIT_LD();
            float4* dst = (float4*)(C + (size_t)m * YW + bn + colh * 128 + base);
#pragma unroll
            for (int j = 0; j < 8; j++)
                dst[j] = make_float4(__uint_as_float(r[4 * j + 0]), __uint_as_float(r[4 * j + 1]),
                                     __uint_as_float(r[4 * j + 2]), __uint_as_float(r[4 * j + 3]));
        }
    }
    __syncthreads();
    if (wid == 0) {
        TC_RELINQ();
        TC_DEALLOC(tmem, 512);
    }
#else
    // ---------------- mma.sync bf16 fallback ----------------
    // smem: buf b: A at 1024 + b*55296 (128 x 72 bf16), B at +18432 (256 x 72 bf16)
    const uint32_t SBASE = sbase + 1024;
    int wm = wid & 1;            // 2 m-warps
    int wn = wid >> 1;           // 4 n-warps

    float acc[4][8][4];
#pragma unroll
    for (int a = 0; a < 4; a++)
#pragma unroll
        for (int b = 0; b < 8; b++)
#pragma unroll
            for (int c = 0; c < 4; c++) acc[a][b][c] = 0.f;

    // per-thread copy slots
    int arow = tid >> 1, acol = tid & 1;            // A: 2 vec16/row pass 1 (use 2 passes)
    // A stage: 128 rows x 4 vec16 = 512 ops -> 2/thread; B: 256 x 4 = 1024 -> 4/thread
    auto load_stage = [&](int s) {
        int seg = s / STAGES_PER_SEG;
        int tst = s - seg * STAGES_PER_SEG;
        int ks = tst * KSTAGE;
        int aoff = (seg == 1) ? KPAD : 0;
        int boff = (seg == 2) ? KPAD : 0;
        uint32_t ab = SBASE + (s & 1) * 55296;
        uint32_t bb = ab + 18432;
#pragma unroll
        for (int j = 0; j < 2; j++) {
            int idx = tid + j * 256;                 // 0..511
            int row = idx >> 2, c = idx & 3;
            uint32_t sm = ab + row * 144 + c * 16;
            const void* gm = (const void*)(Abf + (size_t)(bm + row) * AW + aoff + ks + c * 8);
            CP_ASYNC16(sm, gm);
        }
#pragma unroll
        for (int j = 0; j < 4; j++) {
            int idx = tid + j * 256;                 // 0..1023
            int row = idx >> 2, c = idx & 3;
            uint32_t sm = bb + row * 144 + c * 16;
            const void* gm = (const void*)(WT + (size_t)(bn + row) * WTS + boff + ks + c * 8);
            CP_ASYNC16(sm, gm);
        }
        CP_COMMIT();
    };
    (void)arow; (void)acol;

    load_stage(0);
    for (int s = 0; s < NSTAGES; s++) {
        __syncthreads();                      // everyone done reading buf (s+1)&1
        if (s + 1 < NSTAGES) { load_stage(s + 1); CP_WAIT1(); }
        else                 { CP_WAIT0(); }
        __syncthreads();

        uint32_t ab = SBASE + (s & 1) * 55296;
        uint32_t bb = ab + 18432;
#pragma unroll
        for (int kk = 0; kk < 4; kk++) {
            uint32_t colb = (kk * 16 + ((lid >> 4) << 3)) * 2;
            uint32_t afr[4][4], bfr[8][2];
#pragma unroll
            for (int mt = 0; mt < 4; mt++) {
                uint32_t addr = ab + (wm * 64 + mt * 16 + (lid & 15)) * 144 + colb;
                LDMX4(afr[mt][0], afr[mt][1], afr[mt][2], afr[mt][3], addr);
            }
#pragma unroll
            for (int ng = 0; ng < 4; ng++) {
                uint32_t r0, r1, r2, r3;
                uint32_t addr = bb + (wn * 64 + ng * 16 + (lid & 15)) * 144 + colb;
                LDMX4(r0, r1, r2, r3, addr);
                bfr[2 * ng][0] = r0;     bfr[2 * ng][1] = r2;
                bfr[2 * ng + 1][0] = r1; bfr[2 * ng + 1][1] = r3;
            }
#pragma unroll
            for (int mt = 0; mt < 4; mt++)
#pragma unroll
                for (int nt = 0; nt < 8; nt++)
                    MMA16816(acc[mt][nt], afr[mt], bfr[nt]);
        }
    }

    // epilogue
#pragma unroll
    for (int mt = 0; mt < 4; mt++) {
        int r0 = bm + wm * 64 + mt * 16 + (lid >> 2);
#pragma unroll
        for (int nt = 0; nt < 8; nt++) {
            int col = bn + wn * 64 + nt * 8 + (lid & 3) * 2;
            *(float2*)(C + (size_t)r0 * YW + col) = make_float2(acc[mt][nt][0], acc[mt][nt][1]);
            *(float2*)(C + (size_t)(r0 + 8) * YW + col) = make_float2(acc[mt][nt][2], acc[mt][nt][3]);
        }
    }
#endif
}

// ---------------- K4: geglu + rmsnorm(vn2) -> g_Vn ----------------------------
__global__ void k4_act(const float* __restrict__ vn2)
{
    int i = blockIdx.x;
    __shared__ float vbuf[TOTAL];
    __shared__ float red[256];
    const float* Yr = g_Y + (size_t)i * YW;

    float ss = 0.f;
    for (int j = threadIdx.x; j < TOTAL; j += 256) {
        float a = Yr[j];
        float g = Yr[TOTAL + j];
        float v = a * gelu_tanh(g);
        vbuf[j] = v;
        ss += v * v;
    }
    red[threadIdx.x] = ss;
    __syncthreads();
    for (int w = 128; w > 0; w >>= 1) {
        if (threadIdx.x < w) red[threadIdx.x] += red[threadIdx.x + w];
        __syncthreads();
    }
    float rms = sqrtf(red[0] / (float)TOTAL);
    float sc = 1.0f / (rms + 1e-8f);
    float* out = g_Vn + (size_t)i * TOTAL;
    for (int j = threadIdx.x; j < TOTAL; j += 256)
        out[j] = vn2[j] * vbuf[j] * sc;
}

// ---------------- K5: GEMM2  down[N,64] = Vn[N,2336] @ vw2 (fp32) -------------
#define BM5 128
#define BK5 16
__global__ void __launch_bounds__(256) k5_gemm2(const float* __restrict__ B, int K)
{
    __shared__ float As[BK5][BM5];
    __shared__ float Bs[BK5][64];
    const float* A = g_Vn;
    float* C = g_down;

    int tid = threadIdx.x;
    int tx = tid % 16, ty = tid / 16;
    int bm = blockIdx.y * BM5;

    float acc[8][4];
#pragma unroll
    for (int a = 0; a < 8; a++)
#pragma unroll
        for (int b = 0; b < 4; b++) acc[a][b] = 0.f;

    int ar = tid >> 2;
    int ac = (tid & 3) * 4;
    int br = tid >> 4;
    int bc = (tid & 15) * 4;

    for (int k0 = 0; k0 < K; k0 += BK5) {
#pragma unroll
        for (int ii = 0; ii < 2; ii++) {
            int row = ar + ii * 64;
            float4 v = *(const float4*)&A[(size_t)(bm + row) * K + k0 + ac];
            As[ac + 0][row] = v.x; As[ac + 1][row] = v.y;
            As[ac + 2][row] = v.z; As[ac + 3][row] = v.w;
        }
        {
            float4 v = *(const float4*)&B[(size_t)(k0 + br) * 64 + bc];
            *(float4*)&Bs[br][bc] = v;
        }
        __syncthreads();
#pragma unroll
        for (int k = 0; k < BK5; k++) {
            float af[8], bf[4];
#pragma unroll
            for (int a = 0; a < 8; a++) af[a] = As[k][ty * 8 + a];
#pragma unroll
            for (int b = 0; b < 4; b++) bf[b] = Bs[k][tx * 4 + b];
#pragma unroll
            for (int a = 0; a < 8; a++)
#pragma unroll
                for (int b = 0; b < 4; b++) acc[a][b] += af[a] * bf[b];
        }
        __syncthreads();
    }
#pragma unroll
    for (int a = 0; a < 8; a++) {
        int row = bm + ty * 8 + a;
        *(float4*)&C[(size_t)row * 64 + tx * 4] =
            make_float4(acc[a][0], acc[a][1], acc[a][2], acc[a][3]);
    }
}

// ---------------- K6: final linear --------------------------------------------
__global__ void k6_final(const float* __restrict__ t,
                         const float* __restrict__ fw, const float* __restrict__ fb,
                         float* __restrict__ out)
{
    int i = blockIdx.x * blockDim.x + threadIdx.x;
    if (i >= NPTS) return;
    const float* dr = g_down + (size_t)i * 64;
    float o0 = fb[0], o1 = fb[1], o2 = fb[2], o3 = fb[3];
#pragma unroll 8
    for (int r = 0; r < 64; r++) {
        float a = dr[r];
        o0 += a * fw[r * 4 + 0];
        o1 += a * fw[r * 4 + 1];
        o2 += a * fw[r * 4 + 2];
        o3 += a * fw[r * 4 + 3];
    }
    float p0 = g_p[i * 3 + 0], p1 = g_p[i * 3 + 1], p2 = g_p[i * 3 + 2];
    float tv = t[i];
    o0 += p0 * fw[256 + 0] + p1 * fw[260 + 0] + p2 * fw[264 + 0] + tv * fw[268 + 0];
    o1 += p0 * fw[256 + 1] + p1 * fw[260 + 1] + p2 * fw[264 + 1] + tv * fw[268 + 1];
    o2 += p0 * fw[256 + 2] + p1 * fw[260 + 2] + p2 * fw[264 + 2] + tv * fw[268 + 2];
    o3 += p0 * fw[256 + 3] + p1 * fw[260 + 3] + p2 * fw[264 + 3] + tv * fw[268 + 3];
    out[i * 4 + 0] = o0;
    out[i * 4 + 1] = o1;
    out[i * 4 + 2] = o2;
    out[i * 4 + 3] = o3;
}

// ---------------- launcher ----------------------------------------------------
extern "C" void kernel_launch(void* const* d_in, const int* in_sizes, int n_in,
                              void* d_out, int out_size)
{
    const float* pos      = (const float*)d_in[0];
    const float* t        = (const float*)d_in[2];
    const float* table0   = (const float*)d_in[3];
    const float* table1   = (const float*)d_in[4];
    const float* table2   = (const float*)d_in[5];
    const float* table3   = (const float*)d_in[6];
    const float* st1      = (const float*)d_in[7];
    const float* st2      = (const float*)d_in[8];
    const float* tf       = (const float*)d_in[9];
    const float* sph_proj = (const float*)d_in[10];
    const float* tb1      = (const float*)d_in[11];
    const float* tb2      = (const float*)d_in[12];
    const float* gn1      = (const float*)d_in[13];
    const float* gw1      = (const float*)d_in[14];
    const float* gn2      = (const float*)d_in[15];
    const float* gw2      = (const float*)d_in[16];
    const float* gn3      = (const float*)d_in[17];
    const float* gw3      = (const float*)d_in[18];
    const float* vn1      = (const float*)d_in[19];
    const float* vw1      = (const float*)d_in[20];
    const float* vn2      = (const float*)d_in[21];
    const float* vw2      = (const float*)d_in[22];
    const float* fw       = (const float*)d_in[23];
    const float* fb       = (const float*)d_in[24];
    float* out = (float*)d_out;

    cudaFuncSetAttribute(k3_gemm1, cudaFuncAttributeMaxDynamicSharedMemorySize, SMEM_DYN);

    k1_preamble<<<NPTS / 256, 256>>>(pos, t, sph_proj, tb1, tb2,
                                     gn1, gw1, gn2, gw2, gn3, gw3);

    dim3 gw(WTROWS / 32, TOTAL / 32);
    k_convW<<<gw, dim3(32, 8)>>>(vw1);

    k2_gather<<<NPTS, 128>>>(t, table0, table1, table2, table3, st1, st2, tf, vn1);

    __nv_bfloat16* Abf; cudaGetSymbolAddress((void**)&Abf, g_Abf);
    __nv_bfloat16* WT;  cudaGetSymbolAddress((void**)&WT,  g_WT);
    float* Yp;          cudaGetSymbolAddress((void**)&Yp,  g_Y);

    dim3 g1(YW / 256, NPTS / 128);   // (19, 256)
    k3_gemm1<<<g1, 256, SMEM_DYN>>>(Abf, WT, Yp);

    k4_act<<<NPTS, 256>>>(vn2);

    dim3 g2(1, NPTS / BM5);
    k5_gemm2<<<g2, 256>>>(vw2, TOTAL);

    k6_final<<<NPTS / 256, 256>>>(t, fw, fb, out);
}

// round 4
// speedup vs baseline: 7.2059x; 2.6417x over previous
#include <cuda_runtime.h>
#include <cuda_bf16.h>
#include <math.h>
#include <stdint.h>

#define NPTS 32768
#define TOTAL 2336
#define KPAD 2368          // TOTAL padded to multiple of 32
#define TWOTOTAL 4672
#define INNER 64
#define YW 4864            // padded GEMM1 output width (19 * 256)
#define AW 4736            // row width in bf16: 74 blocks x [hi32|lo32]
#define WTS 4736
#define WTROWS 4864
#define NST 74             // KPAD / 32 logical-k stages

// ---------------- scratch (static device memory; zero-initialized) -----------
__device__ float g_p[NPTS * 3];
__device__ __align__(128) __nv_bfloat16 g_Abf[(size_t)NPTS * AW];   // A split, later Vn split
__device__ __align__(128) __nv_bfloat16 g_WT[(size_t)WTROWS * WTS]; // vw1^T split
__device__ __align__(128) __nv_bfloat16 g_WT2[(size_t)64 * WTS];    // vw2^T split
__device__ __align__(128) float g_Y[(size_t)NPTS * YW];
__device__ float g_down[NPTS * INNER];

// ---------------- common helpers ---------------------------------------------
__device__ __forceinline__ uint32_t smem_u32(const void* p) {
    uint32_t a;
    asm("{ .reg .u64 t; cvta.to.shared.u64 t, %1; cvt.u32.u64 %0, t; }" : "=r"(a) : "l"(p));
    return a;
}
__device__ __forceinline__ float sigmoidf_(float x) { return 1.0f / (1.0f + expf(-x)); }
__device__ __forceinline__ float gelu_tanh(float x) {
    float x3 = x * x * x;
    return 0.5f * x * (1.0f + tanhf(0.7978845608028654f * (x + 0.044715f * x3)));
}
__device__ __forceinline__ int wrapi(int v, int d) {
    if (v < 0) v += d; else if (v >= d) v -= d; return v;
}
__device__ const int FACE3[6][3] = {{1,0,0},{-1,0,0},{0,1,0},{0,-1,0},{0,0,1},{0,0,-1}};
__device__ const int ST8[8][4]   = {{1,0,0,0},{-1,0,0,0},{0,1,0,0},{0,-1,0,0},
                                    {0,0,1,0},{0,0,-1,0},{0,0,0,1},{0,0,0,-1}};

// cp.async helpers (baseline PTX)
#define CP_ASYNC16(smem, gmem) \
    asm volatile("cp.async.cg.shared.global [%0], [%1], 16;" :: "r"(smem), "l"(gmem) : "memory")
#define CP_COMMIT() asm volatile("cp.async.commit_group;" ::: "memory")
#define CP_WAIT1()  asm volatile("cp.async.wait_group 1;" ::: "memory")
#define CP_WAIT0()  asm volatile("cp.async.wait_group 0;" ::: "memory")

#if defined(__CUDA_ARCH_FEAT_SM103_ALL)
// ---------------- tcgen05 helpers (sm_103a pass only) -------------------------
__device__ __forceinline__ uint32_t elect_one() {
    uint32_t p;
    asm volatile("{ .reg .pred p; elect.sync _|p, 0xFFFFFFFF; selp.b32 %0,1,0,p; }" : "=r"(p));
    return p;
}
#define MBARRIER_INIT(addr, cnt) \
    asm volatile("mbarrier.init.shared.b64 [%0], %1;" :: "r"(addr), "r"(cnt) : "memory")
#define MBARRIER_WAIT_PARITY(addr, parity) do { \
    uint32_t _m = (addr); uint32_t _p = (parity); uint32_t _d; \
    asm volatile("{ .reg .pred p; mbarrier.try_wait.parity.acquire.cta.shared::cta.b64 p, [%1], %2; selp.b32 %0,1,0,p; }" \
        : "=r"(_d) : "r"(_m), "r"(_p) : "memory"); \
    if (!_d) { \
        asm volatile("{ .reg .pred P1; WL_%=: mbarrier.try_wait.parity.acquire.cta.shared::cta.b64 P1, [%0], %1, 0x989680; @P1 bra.uni WD_%=; bra.uni WL_%=; WD_%=: }" \
            :: "r"(_m), "r"(_p) : "memory"); \
    } } while (0)
#define TC_ALLOC(slot, n)  asm volatile("tcgen05.alloc.cta_group::1.sync.aligned.shared::cta.b32 [%0], %1;" :: "r"(slot), "r"(n) : "memory")
#define TC_DEALLOC(t, n)   asm volatile("tcgen05.dealloc.cta_group::1.sync.aligned.b32 %0, %1;" :: "r"(t), "r"(n))
#define TC_RELINQ()        asm volatile("tcgen05.relinquish_alloc_permit.cta_group::1.sync.aligned;")
#define TC_COMMIT(mbar)    asm volatile("tcgen05.commit.cta_group::1.mbarrier::arrive::one.shared::cluster.b64 [%0];" :: "r"(mbar) : "memory")
#define TC_WAIT_LD()       asm volatile("tcgen05.wait::ld.sync.aligned;" ::: "memory")
#define TC_FENCE_AFTER()   asm volatile("tcgen05.fence::after_thread_sync;" ::: "memory")
#define FENCE_ASYNC_SH()   asm volatile("fence.proxy.async.shared::cta;" ::: "memory")
#define TC_LD_X32(r, addr) \
    asm volatile("tcgen05.ld.sync.aligned.32x32b.x32.b32 " \
        "{%0,%1,%2,%3,%4,%5,%6,%7,%8,%9,%10,%11,%12,%13,%14,%15," \
        "%16,%17,%18,%19,%20,%21,%22,%23,%24,%25,%26,%27,%28,%29,%30,%31}, [%32];" \
        : "=r"((r)[0]),"=r"((r)[1]),"=r"((r)[2]),"=r"((r)[3]),"=r"((r)[4]),"=r"((r)[5]),"=r"((r)[6]),"=r"((r)[7]), \
          "=r"((r)[8]),"=r"((r)[9]),"=r"((r)[10]),"=r"((r)[11]),"=r"((r)[12]),"=r"((r)[13]),"=r"((r)[14]),"=r"((r)[15]), \
          "=r"((r)[16]),"=r"((r)[17]),"=r"((r)[18]),"=r"((r)[19]),"=r"((r)[20]),"=r"((r)[21]),"=r"((r)[22]),"=r"((r)[23]), \
          "=r"((r)[24]),"=r"((r)[25]),"=r"((r)[26]),"=r"((r)[27]),"=r"((r)[28]),"=r"((r)[29]),"=r"((r)[30]),"=r"((r)[31]) \
        : "r"(addr))
static constexpr uint64_t SMEM_DESC_BASE =
    (uint64_t(2) << 61) | (uint64_t(1) << 46) | (uint64_t(64) << 32) | (uint64_t(1) << 16);
__device__ __forceinline__ uint64_t make_desc(uint32_t addr) {
    return SMEM_DESC_BASE | ((uint64_t)(addr >> 4) & 0x3FFF);
}
__device__ __forceinline__ void mma_f16_ss(uint32_t d, uint64_t a, uint64_t b,
                                           uint32_t idesc, uint32_t en) {
    asm volatile("{ .reg .pred p; setp.ne.u32 p, %4, 0;"
                 "tcgen05.mma.cta_group::1.kind::f16 [%0], %1, %2, %3, {%5,%5,%5,%5}, p; }"
                 :: "r"(d), "l"(a), "l"(b), "r"(idesc), "r"(en), "r"(0u) : "memory");
}
#endif

// ---------------- K1: per-point preamble MLP -> p ----------------------------
__global__ void k1_preamble(const float* __restrict__ pos, const float* __restrict__ t,
                            const float* __restrict__ sph_proj,
                            const float* __restrict__ tb1, const float* __restrict__ tb2,
                            const float* __restrict__ gn1, const float* __restrict__ gw1,
                            const float* __restrict__ gn2, const float* __restrict__ gw2,
                            const float* __restrict__ gn3, const float* __restrict__ gw3)
{
    int i = blockIdx.x * blockDim.x + threadIdx.x;
    if (i >= NPTS) return;

    float x = pos[i * 3 + 0], y = pos[i * 3 + 1], z = pos[i * 3 + 2];
    float rho = sqrtf(x * x + y * y + z * z);
    float phi = atan2f(y, x);
    float cz = z / rho;
    cz = fminf(1.0f, fmaxf(-1.0f, cz));
    float theta = acosf(cz);

    float h[12];
#pragma unroll
    for (int j = 0; j < 8; j++)
        h[j] = rho * sph_proj[j] + phi * sph_proj[8 + j] + theta * sph_proj[16 + j];
    float tv = t[i];
    float ct = cosf(tv + tb1[0]);
    float st = sinf(tv + tb2[0]);
    h[8] = ct; h[9] = st;
    h[10] = ct * sigmoidf_(ct);
    h[11] = st * sigmoidf_(st);

    float ss = 0.f;
#pragma unroll
    for (int j = 0; j < 12; j++) ss += h[j] * h[j];
    float sc = 1.0f / (sqrtf(ss / 12.0f) + 1e-8f);
    float hn[12];
#pragma unroll
    for (int j = 0; j < 12; j++) hn[j] = gn1[j] * h[j] * sc;
    float y1[32];
#pragma unroll
    for (int j = 0; j < 32; j++) y1[j] = 0.f;
#pragma unroll
    for (int r = 0; r < 12; r++) {
        float a = hn[r];
#pragma unroll
        for (int j = 0; j < 32; j++) y1[j] += a * gw1[r * 32 + j];
    }
    float h2[16];
#pragma unroll
    for (int k = 0; k < 16; k++) h2[k] = y1[k] * gelu_tanh(y1[16 + k]);

    ss = 0.f;
#pragma unroll
    for (int j = 0; j < 16; j++) ss += h2[j] * h2[j];
    sc = 1.0f / (sqrtf(ss / 16.0f) + 1e-8f);
    float hn2[16];
#pragma unroll
    for (int j = 0; j < 16; j++) hn2[j] = gn2[j] * h2[j] * sc;
    float y2[32];
#pragma unroll
    for (int j = 0; j < 32; j++) y2[j] = 0.f;
#pragma unroll
    for (int r = 0; r < 16; r++) {
        float a = hn2[r];
#pragma unroll
        for (int j = 0; j < 32; j++) y2[j] += a * gw2[r * 32 + j];
    }
    float h3[16];
#pragma unroll
    for (int k = 0; k < 16; k++) h3[k] = y2[k] * gelu_tanh(y2[16 + k]);

    ss = 0.f;
#pragma unroll
    for (int j = 0; j < 16; j++) ss += h3[j] * h3[j];
    sc = 1.0f / (sqrtf(ss / 16.0f) + 1e-8f);
    float z3[3] = {0.f, 0.f, 0.f};
#pragma unroll
    for (int r = 0; r < 16; r++) {
        float a = gn3[r] * h3[r] * sc;
#pragma unroll
        for (int j = 0; j < 3; j++) z3[j] += a * gw3[r * 3 + j];
    }
    g_p[i * 3 + 0] = sigmoidf_(z3[0]);
    g_p[i * 3 + 1] = sigmoidf_(z3[1]);
    g_p[i * 3 + 2] = sigmoidf_(z3[2]);
}

// ---------------- K2: gather + rmsnorm(vn1) -> interleaved hi/lo bf16 ---------
__global__ void k2_gather(const float* __restrict__ t,
                          const float* __restrict__ table0, const float* __restrict__ table1,
                          const float* __restrict__ table2, const float* __restrict__ table3,
                          const float* __restrict__ st1, const float* __restrict__ st2,
                          const float* __restrict__ tf, const float* __restrict__ vn1)
{
    int i = blockIdx.x;
    __shared__ const float* segp[47];
    __shared__ float feat[TOTAL];
    __shared__ float red[128];

    float p0 = g_p[i * 3 + 0], p1 = g_p[i * 3 + 1], p2 = g_p[i * 3 + 2];
    float tt = t[i];

    int s = threadIdx.x;
    if (s < 47) {
        const float* base = nullptr;
        if (s < 28) {
            int tb = s / 7;
            int o = s % 7;
            int d, F; const float* T;
            if (tb == 0)      { d = 128; F = 16;  T = table0; }
            else if (tb == 1) { d = 64;  F = 32;  T = table1; }
            else if (tb == 2) { d = 32;  F = 64;  T = table2; }
            else              { d = 16;  F = 128; T = table3; }
            int ix = (int)(p0 * (float)(d - 1));
            int iy = (int)(p1 * (float)(d - 1));
            int iz = (int)(p2 * (float)(d - 1));
            if (o > 0) {
                ix = wrapi(ix + FACE3[o - 1][0], d);
                iy = wrapi(iy + FACE3[o - 1][1], d);
                iz = wrapi(iz + FACE3[o - 1][2], d);
            }
            base = T + (size_t)((ix * d + iy) * d + iz) * F;
        } else if (s < 46) {
            int grp = (s - 28) / 9;
            int o = (s - 28) % 9;
            if (grp == 0) {
                int a = (int)(p0 * 15.0f), b = (int)(p1 * 15.0f),
                    c = (int)(p2 * 15.0f), e = (int)(tt * 63.0f);
                if (o > 0) {
                    a = wrapi(a + ST8[o - 1][0], 16);
                    b = wrapi(b + ST8[o - 1][1], 16);
                    c = wrapi(c + ST8[o - 1][2], 16);
                    e = wrapi(e + ST8[o - 1][3], 64);
                }
                base = st1 + (size_t)(((a * 16 + b) * 16 + c) * 64 + e) * 64;
            } else {
                int a = (int)(p0 * 63.0f), b = (int)(p1 * 63.0f),
                    c = (int)(p2 * 31.0f), e = (int)(tt * 15.0f);
                if (o > 0) {
                    a = wrapi(a + ST8[o - 1][0], 64);
                    b = wrapi(b + ST8[o - 1][1], 64);
                    c = wrapi(c + ST8[o - 1][2], 32);
                    e = wrapi(e + ST8[o - 1][3], 16);
                }
                base = st2 + (size_t)(((a * 64 + b) * 32 + c) * 16 + e) * 8;
            }
        } else {
            int a = (int)(p0 * 3.0f), b = (int)(p1 * 3.0f),
                c = (int)(p2 * 3.0f), e = (int)(tt * 65535.0f);
            base = tf + (size_t)(((a * 4 + b) * 4 + c) * 65536 + e) * 8;
        }
        segp[s] = base;
    }
    __syncthreads();

    float ss = 0.f;
    for (int f = threadIdx.x; f < TOTAL; f += 128) {
        int seg, off;
        if (f < 112)       { seg = f >> 4;                off = f & 15; }
        else if (f < 336)  { int g = f - 112;  seg = 7  + (g >> 5); off = g & 31; }
        else if (f < 784)  { int g = f - 336;  seg = 14 + (g >> 6); off = g & 63; }
        else if (f < 1680) { int g = f - 784;  seg = 21 + (g >> 7); off = g & 127; }
        else if (f < 2256) { int g = f - 1680; seg = 28 + (g >> 6); off = g & 63; }
        else if (f < 2328) { int g = f - 2256; seg = 37 + (g >> 3); off = g & 7; }
        else               { seg = 46;                    off = f - 2328; }
        float v = segp[seg][off];
        feat[f] = v;
        ss += v * v;
    }
    red[threadIdx.x] = ss;
    __syncthreads();
    for (int w = 64; w > 0; w >>= 1) {
        if (threadIdx.x < w) red[threadIdx.x] += red[threadIdx.x + w];
        __syncthreads();
    }
    float rms = sqrtf(red[0] / (float)TOTAL);
    float sc = 1.0f / (rms + 1e-8f);
    __nv_bfloat16* orow = g_Abf + (size_t)i * AW;
    for (int f = threadIdx.x; f < TOTAL; f += 128) {
        float v = vn1[f] * feat[f] * sc;
        __nv_bfloat16 h = __float2bfloat16(v);
        float hf = __bfloat162float(h);
        __nv_bfloat16 l = __float2bfloat16(v - hf);
        int blk = f >> 5, pos = f & 31;
        orow[blk * 64 + pos] = h;
        orow[blk * 64 + 32 + pos] = l;
    }
}

// ---------------- K2b: transpose + split vw1 -> g_WT (interleaved) ------------
__global__ void k_convW(const float* __restrict__ vw1)
{
    __shared__ float sh[32][33];
    int n0 = blockIdx.x * 32, k0 = blockIdx.y * 32;
    int tx = threadIdx.x, ty = threadIdx.y;   // 32 x 8
#pragma unroll
    for (int ii = 0; ii < 4; ii++) {
        int r = ty + ii * 8;
        int n = n0 + tx;
        float v = 0.f;
        if (n < TWOTOTAL) v = vw1[(size_t)(k0 + r) * TWOTOTAL + n];
        sh[r][tx] = v;
    }
    __syncthreads();
#pragma unroll
    for (int ii = 0; ii < 4; ii++) {
        int r = ty + ii * 8;
        int n = n0 + r;
        float v = sh[tx][r];
        __nv_bfloat16 h = __float2bfloat16(v);
        float hf = __bfloat162float(h);
        __nv_bfloat16 l = __float2bfloat16(v - hf);
        // logical k = k0 + tx; block = k0/32, pos = tx
        size_t base = (size_t)n * WTS + (size_t)(k0 * 2);
        g_WT[base + tx] = h;
        g_WT[base + 32 + tx] = l;
    }
}

// ---------------- K2c: transpose + split vw2 -> g_WT2 -------------------------
__global__ void k_convW2(const float* __restrict__ vw2)
{
    int idx = blockIdx.x * blockDim.x + threadIdx.x;
    if (idx >= TOTAL * 64) return;
    int k = idx >> 6, n = idx & 63;
    float v = vw2[idx];
    __nv_bfloat16 h = __float2bfloat16(v);
    float hf = __bfloat162float(h);
    __nv_bfloat16 l = __float2bfloat16(v - hf);
    size_t base = (size_t)n * WTS + (size_t)((k >> 5) * 64);
    g_WT2[base + (k & 31)] = h;
    g_WT2[base + 32 + (k & 31)] = l;
}

// ---------------- K3: GEMM1  Y[32768,4864] = A @ W (fused 3-segment split) ----
// Per CTA: 256m x 256n. Stage = 32 logical k = 64 physical elems (128B rows).
#define SMEM1 (1024 + 4 * 32768)

__global__ void __launch_bounds__(256, 1) k3_gemm1(const __nv_bfloat16* __restrict__ Abf,
                                                   const __nv_bfloat16* __restrict__ WT,
                                                   float* __restrict__ C)
{
    extern __shared__ char smem[];
    uint32_t sbase = smem_u32(smem);
    int tid = threadIdx.x;
    int wid = tid >> 5, lid = tid & 31;
    int bm = blockIdx.y * 256;
    int bn = blockIdx.x * 256;

#if defined(__CUDA_ARCH_FEAT_SM103_ALL)
    const uint32_t TSLOT = sbase;
    const uint32_t MBAR0 = sbase + 16;
    const uint32_t MBAR1 = sbase + 24;
    const uint32_t SDATA = sbase + 1024;

    if (wid == 0) TC_ALLOC(TSLOT, 512);
    if (tid == 0) { MBARRIER_INIT(MBAR0, 1); MBARRIER_INIT(MBAR1, 1); }
    __syncthreads();
    uint32_t tmem;
    asm volatile("ld.shared.b32 %0, [%1];" : "=r"(tmem) : "r"(TSLOT));

    const uint32_t IDESC = (1u << 4) | (1u << 7) | (1u << 10) | (32u << 17) | (8u << 24);

    // stage load: A tile 256x64 @ buf, W tile 256x64 @ buf+32KB
    auto load_stage = [&](int s) {
        int buf = s & 1;
        int ks = s * 64;                        // physical elem offset
        uint32_t ab = SDATA + buf * 65536;
        uint32_t wb = ab + 32768;
        const __nv_bfloat16* Asrc = Abf + (size_t)bm * AW + ks;
        const __nv_bfloat16* Wsrc = WT + (size_t)bn * WTS + ks;
#pragma unroll
        for (int j = 0; j < 8; j++) {
            int idx = tid + j * 256;            // 0..2047
            int row = idx >> 3, c = idx & 7;
            uint32_t off = (uint32_t)(row * 128 + c * 16);
            uint32_t sw = off ^ ((off >> 3) & 0x70);
            CP_ASYNC16(ab + sw, (const void*)(Asrc + (size_t)row * AW + c * 8));
        }
#pragma unroll
        for (int j = 0; j < 8; j++) {
            int idx = tid + j * 256;
            int row = idx >> 3, c = idx & 7;
            uint32_t off = (uint32_t)(row * 128 + c * 16);
            uint32_t sw = off ^ ((off >> 3) & 0x70);
            CP_ASYNC16(wb + sw, (const void*)(Wsrc + (size_t)row * WTS + c * 8));
        }
        CP_COMMIT();
    };

    int ph0 = 0, ph1 = 0;
    load_stage(0);
    for (int s = 0; s < NST; s++) {
        int b = s & 1;
        // before overwriting buffer b^1 with stage s+1, MMA(s-1) (reads b^1) must be done
        if (s >= 1 && s + 1 < NST) {
            if ((b ^ 1) == 0) { MBARRIER_WAIT_PARITY(MBAR0, ph0); ph0 ^= 1; }
            else              { MBARRIER_WAIT_PARITY(MBAR1, ph1); ph1 ^= 1; }
        }
        if (s + 1 < NST) { load_stage(s + 1); CP_WAIT1(); }
        else             { CP_WAIT0(); }
        __syncthreads();
        FENCE_ASYNC_SH();
        if (wid == 0) {
            if (elect_one()) {
                uint32_t ab = SDATA + b * 65536;
                uint64_t bd = make_desc(ab + 32768);
#pragma unroll
                for (int half = 0; half < 2; half++) {
                    uint64_t ad = make_desc(ab + half * 16384);
                    uint32_t dt = tmem + half * 256;
                    uint32_t en0 = (s > 0) ? 1u : 0u;
                    // seg0: Ahi x Whi
                    mma_f16_ss(dt, ad + 0, bd + 0, IDESC, en0);
                    mma_f16_ss(dt, ad + 2, bd + 2, IDESC, 1u);
                    // seg1: Alo x Whi
                    mma_f16_ss(dt, ad + 4, bd + 0, IDESC, 1u);
                    mma_f16_ss(dt, ad + 6, bd + 2, IDESC, 1u);
                    // seg2: Ahi x Wlo
                    mma_f16_ss(dt, ad + 0, bd + 4, IDESC, 1u);
                    mma_f16_ss(dt, ad + 2, bd + 6, IDESC, 1u);
                }
                if (b == 0) TC_COMMIT(MBAR0); else TC_COMMIT(MBAR1);
            }
        }
    }
    // last stage s=73 -> buffer 1
    MBARRIER_WAIT_PARITY(MBAR1, ph1);
    TC_FENCE_AFTER();

    // epilogue: warps 0-3 -> D0 (rows bm..bm+127), warps 4-7 -> D1 (+128)
    {
        int m = bm + ((wid < 4) ? 0 : 128) + (wid & 3) * 32 + lid;
        uint32_t dbase = tmem + ((wid < 4) ? 0 : 256);
#pragma unroll
        for (int base = 0; base < 256; base += 32) {
            uint32_t r[32];
            TC_LD_X32(r, dbase + base);
            TC_WAIT_LD();
            float4* dst = (float4*)(C + (size_t)m * YW + bn + base);
#pragma unroll
            for (int j = 0; j < 8; j++)
                dst[j] = make_float4(__uint_as_float(r[4 * j + 0]), __uint_as_float(r[4 * j + 1]),
                                     __uint_as_float(r[4 * j + 2]), __uint_as_float(r[4 * j + 3]));
        }
    }
    __syncthreads();
    if (wid == 0) {
        TC_RELINQ();
        TC_DEALLOC(tmem, 512);
    }
#else
    // ---- FFMA fallback (compiles on generic pass; not selected on sm_103a) ----
    float* As = (float*)smem;            // [16][128]
    float* Bs = (float*)(smem + 16 * 128 * 4);
    int tx = tid % 16, ty = tid / 16;
    for (int pass = 0; pass < 4; pass++) {
        int pm = bm + (pass >> 1) * 128;
        int pn = bn + (pass & 1) * 128;
        float acc[8][8];
#pragma unroll
        for (int a = 0; a < 8; a++)
#pragma unroll
            for (int b = 0; b < 8; b++) acc[a][b] = 0.f;
        for (int k0 = 0; k0 < KPAD; k0 += 16) {
            __syncthreads();
            for (int idx = tid; idx < 2048; idx += 256) {
                int row = idx >> 4, kk = idx & 15;
                int k = k0 + kk;
                size_t pbase = (size_t)(k >> 5) * 64 + (k & 31);
                const __nv_bfloat16* ar = Abf + (size_t)(pm + row) * AW + pbase;
                const __nv_bfloat16* wr = WT + (size_t)(pn + row) * WTS + pbase;
                As[kk * 128 + row] = __bfloat162float(ar[0]) + __bfloat162float(ar[32]);
                Bs[kk * 128 + row] = __bfloat162float(wr[0]) + __bfloat162float(wr[32]);
            }
            __syncthreads();
#pragma unroll
            for (int k = 0; k < 16; k++) {
                float af[8], bf[8];
#pragma unroll
                for (int a = 0; a < 8; a++) af[a] = As[k * 128 + ty * 8 + a];
#pragma unroll
                for (int b = 0; b < 8; b++) bf[b] = Bs[k * 128 + tx * 8 + b];
#pragma unroll
                for (int a = 0; a < 8; a++)
#pragma unroll
                    for (int b = 0; b < 8; b++) acc[a][b] += af[a] * bf[b];
            }
        }
#pragma unroll
        for (int a = 0; a < 8; a++) {
            int row = pm + ty * 8 + a;
#pragma unroll
            for (int b = 0; b < 8; b += 4)
                *(float4*)&C[(size_t)row * YW + pn + tx * 8 + b] =
                    make_float4(acc[a][b], acc[a][b + 1], acc[a][b + 2], acc[a][b + 3]);
        }
        __syncthreads();
    }
#endif
}

// ---------------- K4: geglu + rmsnorm(vn2) -> hi/lo bf16 into g_Abf -----------
__global__ void k4_act(const float* __restrict__ vn2)
{
    int i = blockIdx.x;
    __shared__ float vbuf[TOTAL];
    __shared__ float red[256];
    const float* Yr = g_Y + (size_t)i * YW;

    float ss = 0.f;
    for (int j = threadIdx.x; j < TOTAL; j += 256) {
        float a = Yr[j];
        float g = Yr[TOTAL + j];
        float v = a * gelu_tanh(g);
        vbuf[j] = v;
        ss += v * v;
    }
    red[threadIdx.x] = ss;
    __syncthreads();
    for (int w = 128; w > 0; w >>= 1) {
        if (threadIdx.x < w) red[threadIdx.x] += red[threadIdx.x + w];
        __syncthreads();
    }
    float rms = sqrtf(red[0] / (float)TOTAL);
    float sc = 1.0f / (rms + 1e-8f);
    __nv_bfloat16* orow = g_Abf + (size_t)i * AW;
    for (int j = threadIdx.x; j < TOTAL; j += 256) {
        float v = vn2[j] * vbuf[j] * sc;
        __nv_bfloat16 h = __float2bfloat16(v);
        float hf = __bfloat162float(h);
        __nv_bfloat16 l = __float2bfloat16(v - hf);
        int blk = j >> 5, pos = j & 31;
        orow[blk * 64 + pos] = h;
        orow[blk * 64 + 32 + pos] = l;
    }
}

// ---------------- K5: GEMM2  down[32768,64] = Vn @ vw2 (tcgen05) --------------
#define SMEM5 (1024 + 2 * 24576)
__global__ void __launch_bounds__(128, 1) k5_gemm2(const __nv_bfloat16* __restrict__ Vbf,
                                                   const __nv_bfloat16* __restrict__ WT2,
                                                   float* __restrict__ C)
{
    extern __shared__ char smem[];
    uint32_t sbase = smem_u32(smem);
    int tid = threadIdx.x;
    int wid = tid >> 5, lid = tid & 31;
    int bm = blockIdx.x * 128;

#if defined(__CUDA_ARCH_FEAT_SM103_ALL)
    const uint32_t TSLOT = sbase;
    const uint32_t MBAR0 = sbase + 16;
    const uint32_t MBAR1 = sbase + 24;
    const uint32_t SDATA = sbase + 1024;

    if (wid == 0) TC_ALLOC(TSLOT, 64);
    if (tid == 0) { MBARRIER_INIT(MBAR0, 1); MBARRIER_INIT(MBAR1, 1); }
    __syncthreads();
    uint32_t tmem;
    asm volatile("ld.shared.b32 %0, [%1];" : "=r"(tmem) : "r"(TSLOT));

    const uint32_t IDESC = (1u << 4) | (1u << 7) | (1u << 10) | (8u << 17) | (8u << 24);

    auto load_stage = [&](int s) {
        int buf = s & 1;
        int ks = s * 64;
        uint32_t ab = SDATA + buf * 24576;
        uint32_t wb = ab + 16384;
        const __nv_bfloat16* Asrc = Vbf + (size_t)bm * AW + ks;
        const __nv_bfloat16* Wsrc = WT2 + ks;
#pragma unroll
        for (int j = 0; j < 8; j++) {
            int idx = tid + j * 128;            // 0..1023 (128 rows x 8)
            int row = idx >> 3, c = idx & 7;
            uint32_t off = (uint32_t)(row * 128 + c * 16);
            uint32_t sw = off ^ ((off >> 3) & 0x70);
            CP_ASYNC16(ab + sw, (const void*)(Asrc + (size_t)row * AW + c * 8));
        }
#pragma unroll
        for (int j = 0; j < 4; j++) {
            int idx = tid + j * 128;            // 0..511 (64 rows x 8)
            int row = idx >> 3, c = idx & 7;
            uint32_t off = (uint32_t)(row * 128 + c * 16);
            uint32_t sw = off ^ ((off >> 3) & 0x70);
            CP_ASYNC16(wb + sw, (const void*)(Wsrc + (size_t)row * WTS + c * 8));
        }
        CP_COMMIT();
    };

    int ph0 = 0, ph1 = 0;
    load_stage(0);
    for (int s = 0; s < NST; s++) {
        int b = s & 1;
        if (s >= 1 && s + 1 < NST) {
            if ((b ^ 1) == 0) { MBARRIER_WAIT_PARITY(MBAR0, ph0); ph0 ^= 1; }
            else              { MBARRIER_WAIT_PARITY(MBAR1, ph1); ph1 ^= 1; }
        }
        if (s + 1 < NST) { load_stage(s + 1); CP_WAIT1(); }
        else             { CP_WAIT0(); }
        __syncthreads();
        FENCE_ASYNC_SH();
        if (wid == 0) {
            if (elect_one()) {
                uint32_t ab = SDATA + b * 24576;
                uint64_t ad = make_desc(ab);
                uint64_t bd = make_desc(ab + 16384);
                uint32_t en0 = (s > 0) ? 1u : 0u;
                mma_f16_ss(tmem, ad + 0, bd + 0, IDESC, en0);
                mma_f16_ss(tmem, ad + 2, bd + 2, IDESC, 1u);
                mma_f16_ss(tmem, ad + 4, bd + 0, IDESC, 1u);
                mma_f16_ss(tmem, ad + 6, bd + 2, IDESC, 1u);
                mma_f16_ss(tmem, ad + 0, bd + 4, IDESC, 1u);
                mma_f16_ss(tmem, ad + 2, bd + 6, IDESC, 1u);
                if (b == 0) TC_COMMIT(MBAR0); else TC_COMMIT(MBAR1);
            }
        }
    }
    MBARRIER_WAIT_PARITY(MBAR1, ph1);   // last stage s=73 -> buffer 1
    TC_FENCE_AFTER();

    {
        int m = bm + wid * 32 + lid;
        uint32_t r[32];
        TC_LD_X32(r, tmem);
        TC_WAIT_LD();
        float4* dst = (float4*)(C + (size_t)m * 64);
#pragma unroll
        for (int j = 0; j < 8; j++)
            dst[j] = make_float4(__uint_as_float(r[4 * j + 0]), __uint_as_float(r[4 * j + 1]),
                                 __uint_as_float(r[4 * j + 2]), __uint_as_float(r[4 * j + 3]));
        uint32_t r2[32];
        TC_LD_X32(r2, tmem + 32);
        TC_WAIT_LD();
#pragma unroll
        for (int j = 0; j < 8; j++)
            dst[8 + j] = make_float4(__uint_as_float(r2[4 * j + 0]), __uint_as_float(r2[4 * j + 1]),
                                     __uint_as_float(r2[4 * j + 2]), __uint_as_float(r2[4 * j + 3]));
    }
    __syncthreads();
    if (wid == 0) {
        TC_RELINQ();
        TC_DEALLOC(tmem, 64);
    }
#else
    // ---- FFMA fallback ----
    float* Bs = (float*)smem;            // [16][64]
    for (int m0 = 0; m0 < 128; m0 += 32) {
        int m = bm + m0 + (tid >> 2);    // 32 rows per pass, 4 threads/row
        int nq = (tid & 3) * 16;         // each thread: 16 cols
        float acc[16];
#pragma unroll
        for (int a = 0; a < 16; a++) acc[a] = 0.f;
        for (int k0 = 0; k0 < KPAD; k0 += 16) {
            __syncthreads();
            for (int idx = tid; idx < 1024; idx += 128) {
                int kk = idx >> 6, n = idx & 63;
                int k = k0 + kk;
                const __nv_bfloat16* wr = WT2 + (size_t)n * WTS + (size_t)(k >> 5) * 64 + (k & 31);
                Bs[kk * 64 + n] = __bfloat162float(wr[0]) + __bfloat162float(wr[32]);
            }
            __syncthreads();
#pragma unroll
            for (int kk = 0; kk < 16; kk++) {
                int k = k0 + kk;
                const __nv_bfloat16* ar = Vbf + (size_t)m * AW + (size_t)(k >> 5) * 64 + (k & 31);
                float av = __bfloat162float(ar[0]) + __bfloat162float(ar[32]);
#pragma unroll
                for (int a = 0; a < 16; a++) acc[a] += av * Bs[kk * 64 + nq + a];
            }
        }
        for (int a = 0; a < 16; a++) C[(size_t)m * 64 + nq + a] = acc[a];
        __syncthreads();
    }
#endif
}

// ---------------- K6: final linear --------------------------------------------
__global__ void k6_final(const float* __restrict__ t,
                         const float* __restrict__ fw, const float* __restrict__ fb,
                         float* __restrict__ out)
{
    int i = blockIdx.x * blockDim.x + threadIdx.x;
    if (i >= NPTS) return;
    const float* dr = g_down + (size_t)i * 64;
    float o0 = fb[0], o1 = fb[1], o2 = fb[2], o3 = fb[3];
#pragma unroll 8
    for (int r = 0; r < 64; r++) {
        float a = dr[r];
        o0 += a * fw[r * 4 + 0];
        o1 += a * fw[r * 4 + 1];
        o2 += a * fw[r * 4 + 2];
        o3 += a * fw[r * 4 + 3];
    }
    float p0 = g_p[i * 3 + 0], p1 = g_p[i * 3 + 1], p2 = g_p[i * 3 + 2];
    float tv = t[i];
    o0 += p0 * fw[256 + 0] + p1 * fw[260 + 0] + p2 * fw[264 + 0] + tv * fw[268 + 0];
    o1 += p0 * fw[256 + 1] + p1 * fw[260 + 1] + p2 * fw[264 + 1] + tv * fw[268 + 1];
    o2 += p0 * fw[256 + 2] + p1 * fw[260 + 2] + p2 * fw[264 + 2] + tv * fw[268 + 2];
    o3 += p0 * fw[256 + 3] + p1 * fw[260 + 3] + p2 * fw[264 + 3] + tv * fw[268 + 3];
    out[i * 4 + 0] = o0;
    out[i * 4 + 1] = o1;
    out[i * 4 + 2] = o2;
    out[i * 4 + 3] = o3;
}

// ---------------- launcher ----------------------------------------------------
extern "C" void kernel_launch(void* const* d_in, const int* in_sizes, int n_in,
                              void* d_out, int out_size)
{
    const float* pos      = (const float*)d_in[0];
    const float* t        = (const float*)d_in[2];
    const float* table0   = (const float*)d_in[3];
    const float* table1   = (const float*)d_in[4];
    const float* table2   = (const float*)d_in[5];
    const float* table3   = (const float*)d_in[6];
    const float* st1      = (const float*)d_in[7];
    const float* st2      = (const float*)d_in[8];
    const float* tf       = (const float*)d_in[9];
    const float* sph_proj = (const float*)d_in[10];
    const float* tb1      = (const float*)d_in[11];
    const float* tb2      = (const float*)d_in[12];
    const float* gn1      = (const float*)d_in[13];
    const float* gw1      = (const float*)d_in[14];
    const float* gn2      = (const float*)d_in[15];
    const float* gw2      = (const float*)d_in[16];
    const float* gn3      = (const float*)d_in[17];
    const float* gw3      = (const float*)d_in[18];
    const float* vn1      = (const float*)d_in[19];
    const float* vw1      = (const float*)d_in[20];
    const float* vn2      = (const float*)d_in[21];
    const float* vw2      = (const float*)d_in[22];
    const float* fw       = (const float*)d_in[23];
    const float* fb       = (const float*)d_in[24];
    float* out = (float*)d_out;

    cudaFuncSetAttribute(k3_gemm1, cudaFuncAttributeMaxDynamicSharedMemorySize, SMEM1);
    cudaFuncSetAttribute(k5_gemm2, cudaFuncAttributeMaxDynamicSharedMemorySize, SMEM5);

    k1_preamble<<<NPTS / 256, 256>>>(pos, t, sph_proj, tb1, tb2,
                                     gn1, gw1, gn2, gw2, gn3, gw3);

    dim3 gw(WTROWS / 32, TOTAL / 32);
    k_convW<<<gw, dim3(32, 8)>>>(vw1);
    k_convW2<<<(TOTAL * 64 + 255) / 256, 256>>>(vw2);

    k2_gather<<<NPTS, 128>>>(t, table0, table1, table2, table3, st1, st2, tf, vn1);

    __nv_bfloat16* Abf; cudaGetSymbolAddress((void**)&Abf, g_Abf);
    __nv_bfloat16* WT;  cudaGetSymbolAddress((void**)&WT,  g_WT);
    __nv_bfloat16* WT2; cudaGetSymbolAddress((void**)&WT2, g_WT2);
    float* Yp;          cudaGetSymbolAddress((void**)&Yp,  g_Y);
    float* Dn;          cudaGetSymbolAddress((void**)&Dn,  g_down);

    dim3 g1(YW / 256, NPTS / 256);   // (19, 128)
    k3_gemm1<<<g1, 256, SMEM1>>>(Abf, WT, Yp);

    k4_act<<<NPTS, 256>>>(vn2);

    k5_gemm2<<<NPTS / 128, 128, SMEM5>>>(Abf, WT2, Dn);

    k6_final<<<NPTS / 256, 256>>>(t, fw, fb, out);
}

// round 5
// speedup vs baseline: 8.0462x; 1.1166x over previous
#include <cuda_runtime.h>
#include <cuda_bf16.h>
#include <math.h>
#include <stdint.h>

#define NPTS 32768
#define TOTAL 2336
#define KPAD1 2368         // GEMM1 K padded (74 blocks of 32)
#define NST1 74
#define HALFP 2432         // padded half width (19*128)
#define KPAD2 2432         // GEMM2 K (76 blocks)
#define NST2 76
#define TWOTOTAL 4672
#define INNER 64
#define AW1 4736           // g_Abf row: 74 blocks x [hi32|lo32]
#define VW 4864            // g_Vbf / g_WT2 row: 76 blocks x [hi32|lo32]
#define WTS 4736           // g_WT row width (74 blocks)
#define WTROWS 4864        // permuted W1 rows (19 tiles x 256)
#define NTILES 19

// ---------------- scratch (static device memory; zero-initialized) -----------
__device__ float g_p[NPTS * 3];
__device__ __align__(128) __nv_bfloat16 g_Abf[(size_t)NPTS * AW1];  // GEMM1 A split
__device__ __align__(128) __nv_bfloat16 g_Vbf[(size_t)NPTS * VW];   // V split (GEMM2 A)
__device__ __align__(128) __nv_bfloat16 g_WT[(size_t)WTROWS * WTS]; // permuted vw1^T split
__device__ __align__(128) __nv_bfloat16 g_WT2[(size_t)64 * VW];     // (vn2*vw2)^T split
__device__ float g_sspart[(size_t)NPTS * NTILES];                   // per-(row,tile) sum v^2
__device__ float g_down[NPTS * INNER];

// ---------------- common helpers ---------------------------------------------
__device__ __forceinline__ uint32_t smem_u32(const void* p) {
    uint32_t a;
    asm("{ .reg .u64 t; cvta.to.shared.u64 t, %1; cvt.u32.u64 %0, t; }" : "=r"(a) : "l"(p));
    return a;
}
__device__ __forceinline__ float sigmoidf_(float x) { return 1.0f / (1.0f + expf(-x)); }
__device__ __forceinline__ float gelu_tanh(float x) {
    float x3 = x * x * x;
    return 0.5f * x * (1.0f + tanhf(0.7978845608028654f * (x + 0.044715f * x3)));
}
__device__ __forceinline__ int wrapi(int v, int d) {
    if (v < 0) v += d; else if (v >= d) v -= d; return v;
}
__device__ const int FACE3[6][3] = {{1,0,0},{-1,0,0},{0,1,0},{0,-1,0},{0,0,1},{0,0,-1}};
__device__ const int ST8[8][4]   = {{1,0,0,0},{-1,0,0,0},{0,1,0,0},{0,-1,0,0},
                                    {0,0,1,0},{0,0,-1,0},{0,0,0,1},{0,0,0,-1}};

// cp.async helpers (baseline PTX)
#define CP_ASYNC16(smem, gmem) \
    asm volatile("cp.async.cg.shared.global [%0], [%1], 16;" :: "r"(smem), "l"(gmem) : "memory")
#define CP_COMMIT() asm volatile("cp.async.commit_group;" ::: "memory")
#define CP_WAIT2()  asm volatile("cp.async.wait_group 2;" ::: "memory")
#define CP_WAIT1()  asm volatile("cp.async.wait_group 1;" ::: "memory")
#define CP_WAIT0()  asm volatile("cp.async.wait_group 0;" ::: "memory")

#if defined(__CUDA_ARCH_FEAT_SM103_ALL)
// ---------------- tcgen05 helpers (sm_103a pass only) -------------------------
__device__ __forceinline__ uint32_t elect_one() {
    uint32_t p;
    asm volatile("{ .reg .pred p; elect.sync _|p, 0xFFFFFFFF; selp.b32 %0,1,0,p; }" : "=r"(p));
    return p;
}
#define MBARRIER_INIT(addr, cnt) \
    asm volatile("mbarrier.init.shared.b64 [%0], %1;" :: "r"(addr), "r"(cnt) : "memory")
#define MBARRIER_WAIT_PARITY(addr, parity) do { \
    uint32_t _m = (addr); uint32_t _p = (parity); uint32_t _d; \
    asm volatile("{ .reg .pred p; mbarrier.try_wait.parity.acquire.cta.shared::cta.b64 p, [%1], %2; selp.b32 %0,1,0,p; }" \
        : "=r"(_d) : "r"(_m), "r"(_p) : "memory"); \
    if (!_d) { \
        asm volatile("{ .reg .pred P1; WL_%=: mbarrier.try_wait.parity.acquire.cta.shared::cta.b64 P1, [%0], %1, 0x989680; @P1 bra.uni WD_%=; bra.uni WL_%=; WD_%=: }" \
            :: "r"(_m), "r"(_p) : "memory"); \
    } } while (0)
#define TC_ALLOC(slot, n)  asm volatile("tcgen05.alloc.cta_group::1.sync.aligned.shared::cta.b32 [%0], %1;" :: "r"(slot), "r"(n) : "memory")
#define TC_DEALLOC(t, n)   asm volatile("tcgen05.dealloc.cta_group::1.sync.aligned.b32 %0, %1;" :: "r"(t), "r"(n))
#define TC_RELINQ()        asm volatile("tcgen05.relinquish_alloc_permit.cta_group::1.sync.aligned;")
#define TC_COMMIT(mbar)    asm volatile("tcgen05.commit.cta_group::1.mbarrier::arrive::one.shared::cluster.b64 [%0];" :: "r"(mbar) : "memory")
#define TC_WAIT_LD()       asm volatile("tcgen05.wait::ld.sync.aligned;" ::: "memory")
#define TC_FENCE_AFTER()   asm volatile("tcgen05.fence::after_thread_sync;" ::: "memory")
#define FENCE_ASYNC_SH()   asm volatile("fence.proxy.async.shared::cta;" ::: "memory")
#define TC_LD_X32(r, addr) \
    asm volatile("tcgen05.ld.sync.aligned.32x32b.x32.b32 " \
        "{%0,%1,%2,%3,%4,%5,%6,%7,%8,%9,%10,%11,%12,%13,%14,%15," \
        "%16,%17,%18,%19,%20,%21,%22,%23,%24,%25,%26,%27,%28,%29,%30,%31}, [%32];" \
        : "=r"((r)[0]),"=r"((r)[1]),"=r"((r)[2]),"=r"((r)[3]),"=r"((r)[4]),"=r"((r)[5]),"=r"((r)[6]),"=r"((r)[7]), \
          "=r"((r)[8]),"=r"((r)[9]),"=r"((r)[10]),"=r"((r)[11]),"=r"((r)[12]),"=r"((r)[13]),"=r"((r)[14]),"=r"((r)[15]), \
          "=r"((r)[16]),"=r"((r)[17]),"=r"((r)[18]),"=r"((r)[19]),"=r"((r)[20]),"=r"((r)[21]),"=r"((r)[22]),"=r"((r)[23]), \
          "=r"((r)[24]),"=r"((r)[25]),"=r"((r)[26]),"=r"((r)[27]),"=r"((r)[28]),"=r"((r)[29]),"=r"((r)[30]),"=r"((r)[31]) \
        : "r"(addr))
static constexpr uint64_t SMEM_DESC_BASE =
    (uint64_t(2) << 61) | (uint64_t(1) << 46) | (uint64_t(64) << 32) | (uint64_t(1) << 16);
__device__ __forceinline__ uint64_t make_desc(uint32_t addr) {
    return SMEM_DESC_BASE | ((uint64_t)(addr >> 4) & 0x3FFF);
}
__device__ __forceinline__ void mma_f16_ss(uint32_t d, uint64_t a, uint64_t b,
                                           uint32_t idesc, uint32_t en) {
    asm volatile("{ .reg .pred p; setp.ne.u32 p, %4, 0;"
                 "tcgen05.mma.cta_group::1.kind::f16 [%0], %1, %2, %3, {%5,%5,%5,%5}, p; }"
                 :: "r"(d), "l"(a), "l"(b), "r"(idesc), "r"(en), "r"(0u) : "memory");
}
#endif

// ---------------- K1: per-point preamble MLP -> p ----------------------------
__global__ void k1_preamble(const float* __restrict__ pos, const float* __restrict__ t,
                            const float* __restrict__ sph_proj,
                            const float* __restrict__ tb1, const float* __restrict__ tb2,
                            const float* __restrict__ gn1, const float* __restrict__ gw1,
                            const float* __restrict__ gn2, const float* __restrict__ gw2,
                            const float* __restrict__ gn3, const float* __restrict__ gw3)
{
    int i = blockIdx.x * blockDim.x + threadIdx.x;
    if (i >= NPTS) return;

    float x = pos[i * 3 + 0], y = pos[i * 3 + 1], z = pos[i * 3 + 2];
    float rho = sqrtf(x * x + y * y + z * z);
    float phi = atan2f(y, x);
    float cz = z / rho;
    cz = fminf(1.0f, fmaxf(-1.0f, cz));
    float theta = acosf(cz);

    float h[12];
#pragma unroll
    for (int j = 0; j < 8; j++)
        h[j] = rho * sph_proj[j] + phi * sph_proj[8 + j] + theta * sph_proj[16 + j];
    float tv = t[i];
    float ct = cosf(tv + tb1[0]);
    float st = sinf(tv + tb2[0]);
    h[8] = ct; h[9] = st;
    h[10] = ct * sigmoidf_(ct);
    h[11] = st * sigmoidf_(st);

    float ss = 0.f;
#pragma unroll
    for (int j = 0; j < 12; j++) ss += h[j] * h[j];
    float sc = 1.0f / (sqrtf(ss / 12.0f) + 1e-8f);
    float hn[12];
#pragma unroll
    for (int j = 0; j < 12; j++) hn[j] = gn1[j] * h[j] * sc;
    float y1[32];
#pragma unroll
    for (int j = 0; j < 32; j++) y1[j] = 0.f;
#pragma unroll
    for (int r = 0; r < 12; r++) {
        float a = hn[r];
#pragma unroll
        for (int j = 0; j < 32; j++) y1[j] += a * gw1[r * 32 + j];
    }
    float h2[16];
#pragma unroll
    for (int k = 0; k < 16; k++) h2[k] = y1[k] * gelu_tanh(y1[16 + k]);

    ss = 0.f;
#pragma unroll
    for (int j = 0; j < 16; j++) ss += h2[j] * h2[j];
    sc = 1.0f / (sqrtf(ss / 16.0f) + 1e-8f);
    float hn2[16];
#pragma unroll
    for (int j = 0; j < 16; j++) hn2[j] = gn2[j] * h2[j] * sc;
    float y2[32];
#pragma unroll
    for (int j = 0; j < 32; j++) y2[j] = 0.f;
#pragma unroll
    for (int r = 0; r < 16; r++) {
        float a = hn2[r];
#pragma unroll
        for (int j = 0; j < 32; j++) y2[j] += a * gw2[r * 32 + j];
    }
    float h3[16];
#pragma unroll
    for (int k = 0; k < 16; k++) h3[k] = y2[k] * gelu_tanh(y2[16 + k]);

    ss = 0.f;
#pragma unroll
    for (int j = 0; j < 16; j++) ss += h3[j] * h3[j];
    sc = 1.0f / (sqrtf(ss / 16.0f) + 1e-8f);
    float z3[3] = {0.f, 0.f, 0.f};
#pragma unroll
    for (int r = 0; r < 16; r++) {
        float a = gn3[r] * h3[r] * sc;
#pragma unroll
        for (int j = 0; j < 3; j++) z3[j] += a * gw3[r * 3 + j];
    }
    g_p[i * 3 + 0] = sigmoidf_(z3[0]);
    g_p[i * 3 + 1] = sigmoidf_(z3[1]);
    g_p[i * 3 + 2] = sigmoidf_(z3[2]);
}

// ---------------- K2: gather + rmsnorm(vn1) -> interleaved hi/lo bf16 ---------
__global__ void k2_gather(const float* __restrict__ t,
                          const float* __restrict__ table0, const float* __restrict__ table1,
                          const float* __restrict__ table2, const float* __restrict__ table3,
                          const float* __restrict__ st1, const float* __restrict__ st2,
                          const float* __restrict__ tf, const float* __restrict__ vn1)
{
    int i = blockIdx.x;
    __shared__ const float* segp[47];
    __shared__ float feat[TOTAL];
    __shared__ float red[128];

    float p0 = g_p[i * 3 + 0], p1 = g_p[i * 3 + 1], p2 = g_p[i * 3 + 2];
    float tt = t[i];

    int s = threadIdx.x;
    if (s < 47) {
        const float* base = nullptr;
        if (s < 28) {
            int tb = s / 7;
            int o = s % 7;
            int d, F; const float* T;
            if (tb == 0)      { d = 128; F = 16;  T = table0; }
            else if (tb == 1) { d = 64;  F = 32;  T = table1; }
            else if (tb == 2) { d = 32;  F = 64;  T = table2; }
            else              { d = 16;  F = 128; T = table3; }
            int ix = (int)(p0 * (float)(d - 1));
            int iy = (int)(p1 * (float)(d - 1));
            int iz = (int)(p2 * (float)(d - 1));
            if (o > 0) {
                ix = wrapi(ix + FACE3[o - 1][0], d);
                iy = wrapi(iy + FACE3[o - 1][1], d);
                iz = wrapi(iz + FACE3[o - 1][2], d);
            }
            base = T + (size_t)((ix * d + iy) * d + iz) * F;
        } else if (s < 46) {
            int grp = (s - 28) / 9;
            int o = (s - 28) % 9;
            if (grp == 0) {
                int a = (int)(p0 * 15.0f), b = (int)(p1 * 15.0f),
                    c = (int)(p2 * 15.0f), e = (int)(tt * 63.0f);
                if (o > 0) {
                    a = wrapi(a + ST8[o - 1][0], 16);
                    b = wrapi(b + ST8[o - 1][1], 16);
                    c = wrapi(c + ST8[o - 1][2], 16);
                    e = wrapi(e + ST8[o - 1][3], 64);
                }
                base = st1 + (size_t)(((a * 16 + b) * 16 + c) * 64 + e) * 64;
            } else {
                int a = (int)(p0 * 63.0f), b = (int)(p1 * 63.0f),
                    c = (int)(p2 * 31.0f), e = (int)(tt * 15.0f);
                if (o > 0) {
                    a = wrapi(a + ST8[o - 1][0], 64);
                    b = wrapi(b + ST8[o - 1][1], 64);
                    c = wrapi(c + ST8[o - 1][2], 32);
                    e = wrapi(e + ST8[o - 1][3], 16);
                }
                base = st2 + (size_t)(((a * 64 + b) * 32 + c) * 16 + e) * 8;
            }
        } else {
            int a = (int)(p0 * 3.0f), b = (int)(p1 * 3.0f),
                c = (int)(p2 * 3.0f), e = (int)(tt * 65535.0f);
            base = tf + (size_t)(((a * 4 + b) * 4 + c) * 65536 + e) * 8;
        }
        segp[s] = base;
    }
    __syncthreads();

    float ss = 0.f;
    for (int f = threadIdx.x; f < TOTAL; f += 128) {
        int seg, off;
        if (f < 112)       { seg = f >> 4;                off = f & 15; }
        else if (f < 336)  { int g = f - 112;  seg = 7  + (g >> 5); off = g & 31; }
        else if (f < 784)  { int g = f - 336;  seg = 14 + (g >> 6); off = g & 63; }
        else if (f < 1680) { int g = f - 784;  seg = 21 + (g >> 7); off = g & 127; }
        else if (f < 2256) { int g = f - 1680; seg = 28 + (g >> 6); off = g & 63; }
        else if (f < 2328) { int g = f - 2256; seg = 37 + (g >> 3); off = g & 7; }
        else               { seg = 46;                    off = f - 2328; }
        float v = segp[seg][off];
        feat[f] = v;
        ss += v * v;
    }
    red[threadIdx.x] = ss;
    __syncthreads();
    for (int w = 64; w > 0; w >>= 1) {
        if (threadIdx.x < w) red[threadIdx.x] += red[threadIdx.x + w];
        __syncthreads();
    }
    float rms = sqrtf(red[0] / (float)TOTAL);
    float sc = 1.0f / (rms + 1e-8f);
    __nv_bfloat16* orow = g_Abf + (size_t)i * AW1;
    for (int f = threadIdx.x; f < TOTAL; f += 128) {
        float v = vn1[f] * feat[f] * sc;
        __nv_bfloat16 h = __float2bfloat16(v);
        float hf = __bfloat162float(h);
        __nv_bfloat16 l = __float2bfloat16(v - hf);
        int blk = f >> 5, pos = f & 31;
        orow[blk * 64 + pos] = h;
        orow[blk * 64 + 32 + pos] = l;
    }
}

// ---------------- K2b: permuted transpose + split vw1 -> g_WT -----------------
// output row n: tile=n>>8, half=(n>>7)&1, i=n&127 -> src col = half*2336 + tile*128+i
__global__ void k_convW(const float* __restrict__ vw1)
{
    __shared__ float sh[32][33];
    int n0 = blockIdx.x * 32, k0 = blockIdx.y * 32;
    int tx = threadIdx.x, ty = threadIdx.y;   // 32 x 8
    int tile = n0 >> 8, half = (n0 >> 7) & 1;
    int f0 = tile * 128 + (n0 & 127);
#pragma unroll
    for (int ii = 0; ii < 4; ii++) {
        int r = ty + ii * 8;
        int k = k0 + r;
        int f = f0 + tx;
        float v = 0.f;
        if (f < TOTAL && k < TOTAL)
            v = vw1[(size_t)k * TWOTOTAL + half * TOTAL + f];
        sh[r][tx] = v;
    }
    __syncthreads();
#pragma unroll
    for (int ii = 0; ii < 4; ii++) {
        int r = ty + ii * 8;
        int n = n0 + r;
        float v = sh[tx][r];     // element (k = k0+tx, n)
        __nv_bfloat16 h = __float2bfloat16(v);
        float hf = __bfloat162float(h);
        __nv_bfloat16 l = __float2bfloat16(v - hf);
        size_t base = (size_t)n * WTS + (size_t)(k0 * 2);
        g_WT[base + tx] = h;
        g_WT[base + 32 + tx] = l;
    }
}

// ---------------- K2c: (vn2 * vw2)^T split -> g_WT2 ---------------------------
__global__ void k_convW2(const float* __restrict__ vw2, const float* __restrict__ vn2)
{
    int idx = blockIdx.x * blockDim.x + threadIdx.x;
    if (idx >= TOTAL * 64) return;
    int k = idx >> 6, n = idx & 63;
    float v = vn2[k] * vw2[idx];
    __nv_bfloat16 h = __float2bfloat16(v);
    float hf = __bfloat162float(h);
    __nv_bfloat16 l = __float2bfloat16(v - hf);
    size_t base = (size_t)n * VW + (size_t)((k >> 5) * 64);
    g_WT2[base + (k & 31)] = h;
    g_WT2[base + 32 + (k & 31)] = l;
}

// ---------------- K3: GEMM1 + fused geglu epilogue -> g_Vbf, g_sspart ---------
// Per CTA: 256m x 256n (a-cols 0-127, g-cols 128-255 of tile). 3-stage pipeline.
#define SMEM1 (1024 + 3 * 65536)

__global__ void __launch_bounds__(256, 1) k3_gemm1(const __nv_bfloat16* __restrict__ Abf,
                                                   const __nv_bfloat16* __restrict__ WT,
                                                   __nv_bfloat16* __restrict__ Vbf,
                                                   float* __restrict__ sspart)
{
    extern __shared__ char smem[];
    uint32_t sbase = smem_u32(smem);
    int tid = threadIdx.x;
    int wid = tid >> 5, lid = tid & 31;
    int tile = blockIdx.x;
    int bm = blockIdx.y * 256;
    int bn = tile * 256;

#if defined(__CUDA_ARCH_FEAT_SM103_ALL)
    const uint32_t TSLOT = sbase;
    const uint32_t MB0 = sbase + 16;
    const uint32_t MB1 = sbase + 24;
    const uint32_t MB2 = sbase + 32;
    const uint32_t SDATA = sbase + 1024;

    if (wid == 0) TC_ALLOC(TSLOT, 512);
    if (tid == 0) { MBARRIER_INIT(MB0, 1); MBARRIER_INIT(MB1, 1); MBARRIER_INIT(MB2, 1); }
    __syncthreads();
    uint32_t tmem;
    asm volatile("ld.shared.b32 %0, [%1];" : "=r"(tmem) : "r"(TSLOT));

    const uint32_t IDESC = (1u << 4) | (1u << 7) | (1u << 10) | (32u << 17) | (8u << 24);

    auto load_stage = [&](int s) {
        int buf = s % 3;
        int ks = s * 64;
        uint32_t ab = SDATA + buf * 65536;
        uint32_t wb = ab + 32768;
        const __nv_bfloat16* Asrc = Abf + (size_t)bm * AW1 + ks;
        const __nv_bfloat16* Wsrc = WT + (size_t)bn * WTS + ks;
#pragma unroll
        for (int j = 0; j < 8; j++) {
            int idx = tid + j * 256;
            int row = idx >> 3, c = idx & 7;
            uint32_t off = (uint32_t)(row * 128 + c * 16);
            uint32_t sw = off ^ ((off >> 3) & 0x70);
            CP_ASYNC16(ab + sw, (const void*)(Asrc + (size_t)row * AW1 + c * 8));
        }
#pragma unroll
        for (int j = 0; j < 8; j++) {
            int idx = tid + j * 256;
            int row = idx >> 3, c = idx & 7;
            uint32_t off = (uint32_t)(row * 128 + c * 16);
            uint32_t sw = off ^ ((off >> 3) & 0x70);
            CP_ASYNC16(wb + sw, (const void*)(Wsrc + (size_t)row * WTS + c * 8));
        }
        CP_COMMIT();
    };

    int ph0 = 0, ph1 = 0, ph2 = 0;
    load_stage(0);
    load_stage(1);
    for (int s = 0; s < NST1; s++) {
        if (s + 2 < NST1) {
            if (s >= 1) {
                int b = (s - 1) % 3;
                if (b == 0)      { MBARRIER_WAIT_PARITY(MB0, ph0); ph0 ^= 1; }
                else if (b == 1) { MBARRIER_WAIT_PARITY(MB1, ph1); ph1 ^= 1; }
                else             { MBARRIER_WAIT_PARITY(MB2, ph2); ph2 ^= 1; }
            }
            load_stage(s + 2);
        }
        if (s + 2 < NST1)      CP_WAIT2();
        else if (s + 1 < NST1) CP_WAIT1();
        else                   CP_WAIT0();
        __syncthreads();
        FENCE_ASYNC_SH();
        if (wid == 0) {
            if (elect_one()) {
                int buf = s % 3;
                uint32_t ab = SDATA + buf * 65536;
                uint64_t bd = make_desc(ab + 32768);
#pragma unroll
                for (int half = 0; half < 2; half++) {
                    uint64_t ad = make_desc(ab + half * 16384);
                    uint32_t dt = tmem + half * 256;
                    uint32_t en0 = (s > 0) ? 1u : 0u;
                    mma_f16_ss(dt, ad + 0, bd + 0, IDESC, en0);
                    mma_f16_ss(dt, ad + 2, bd + 2, IDESC, 1u);
                    mma_f16_ss(dt, ad + 4, bd + 0, IDESC, 1u);
                    mma_f16_ss(dt, ad + 6, bd + 2, IDESC, 1u);
                    mma_f16_ss(dt, ad + 0, bd + 4, IDESC, 1u);
                    mma_f16_ss(dt, ad + 2, bd + 6, IDESC, 1u);
                }
                if (buf == 0) TC_COMMIT(MB0);
                else if (buf == 1) TC_COMMIT(MB1);
                else TC_COMMIT(MB2);
            }
        }
    }
    {
        int b = (NST1 - 1) % 3;   // 73 % 3 = 1
        if (b == 0)      MBARRIER_WAIT_PARITY(MB0, ph0);
        else if (b == 1) MBARRIER_WAIT_PARITY(MB1, ph1);
        else             MBARRIER_WAIT_PARITY(MB2, ph2);
    }
    TC_FENCE_AFTER();

    // fused epilogue: a = cols 0-127, g = cols 128-255 -> v = a*gelu(g)
    {
        int m = bm + ((wid < 4) ? 0 : 128) + (wid & 3) * 32 + lid;
        uint32_t dbase = tmem + ((wid < 4) ? 0 : 256);
        float ssacc = 0.f;
#pragma unroll
        for (int cp = 0; cp < 4; cp++) {
            uint32_t ra[32], rg[32];
            TC_LD_X32(ra, dbase + cp * 32);
            TC_LD_X32(rg, dbase + 128 + cp * 32);
            TC_WAIT_LD();
            uint32_t o[32];
#pragma unroll
            for (int j = 0; j < 32; j += 2) {
                float a0 = __uint_as_float(ra[j]),     a1 = __uint_as_float(ra[j + 1]);
                float g0 = __uint_as_float(rg[j]),     g1 = __uint_as_float(rg[j + 1]);
                float v0 = a0 * gelu_tanh(g0), v1 = a1 * gelu_tanh(g1);
                ssacc += v0 * v0 + v1 * v1;
                __nv_bfloat16 h0 = __float2bfloat16(v0);
                __nv_bfloat16 h1 = __float2bfloat16(v1);
                __nv_bfloat16 l0 = __float2bfloat16(v0 - __bfloat162float(h0));
                __nv_bfloat16 l1 = __float2bfloat16(v1 - __bfloat162float(h1));
                unsigned short uh0 = *(unsigned short*)&h0, uh1 = *(unsigned short*)&h1;
                unsigned short ul0 = *(unsigned short*)&l0, ul1 = *(unsigned short*)&l1;
                o[j >> 1]        = (uint32_t)uh0 | ((uint32_t)uh1 << 16);
                o[16 + (j >> 1)] = (uint32_t)ul0 | ((uint32_t)ul1 << 16);
            }
            int fb = tile * 4 + cp;
            uint4* dst = (uint4*)(Vbf + (size_t)m * VW + fb * 64);
#pragma unroll
            for (int q = 0; q < 8; q++)
                dst[q] = make_uint4(o[4 * q], o[4 * q + 1], o[4 * q + 2], o[4 * q + 3]);
        }
        sspart[(size_t)m * NTILES + tile] = ssacc;
    }
    __syncthreads();
    if (wid == 0) {
        TC_RELINQ();
        TC_DEALLOC(tmem, 512);
    }
#else
    // ---- FFMA fallback (generic pass; never selected on sm_103a) ----
    float* Da   = (float*)smem;                    // 128 x 128
    float* As   = Da + 128 * 128;                  // 16 x 128
    float* Bs   = As + 16 * 128;                   // 16 x 128
    float* ssrd = Bs + 16 * 128;                   // 128 x 16
    int tx = tid % 16, ty = tid / 16;
    for (int pass = 0; pass < 2; pass++) {
        int pm = bm + pass * 128;
        for (int half = 0; half < 2; half++) {
            int pn = bn + half * 128;
            float acc[8][8];
#pragma unroll
            for (int a = 0; a < 8; a++)
#pragma unroll
                for (int b = 0; b < 8; b++) acc[a][b] = 0.f;
            for (int k0 = 0; k0 < KPAD1; k0 += 16) {
                __syncthreads();
                for (int idx = tid; idx < 2048; idx += 256) {
                    int row = idx >> 4, kk = idx & 15;
                    int k = k0 + kk;
                    size_t pb = (size_t)(k >> 5) * 64 + (k & 31);
                    const __nv_bfloat16* ar = Abf + (size_t)(pm + row) * AW1 + pb;
                    const __nv_bfloat16* wr = WT + (size_t)(pn + row) * WTS + pb;
                    As[kk * 128 + row] = __bfloat162float(ar[0]) + __bfloat162float(ar[32]);
                    Bs[kk * 128 + row] = __bfloat162float(wr[0]) + __bfloat162float(wr[32]);
                }
                __syncthreads();
#pragma unroll
                for (int k = 0; k < 16; k++) {
                    float af[8], bf[8];
#pragma unroll
                    for (int a = 0; a < 8; a++) af[a] = As[k * 128 + ty * 8 + a];
#pragma unroll
                    for (int b = 0; b < 8; b++) bf[b] = Bs[k * 128 + tx * 8 + b];
#pragma unroll
                    for (int a = 0; a < 8; a++)
#pragma unroll
                        for (int b = 0; b < 8; b++) acc[a][b] += af[a] * bf[b];
                }
            }
            __syncthreads();
            if (half == 0) {
#pragma unroll
                for (int a = 0; a < 8; a++)
#pragma unroll
                    for (int b = 0; b < 8; b++)
                        Da[(ty * 8 + a) * 128 + tx * 8 + b] = acc[a][b];
            } else {
#pragma unroll
                for (int a = 0; a < 8; a++) {
                    int row = ty * 8 + a;
                    float ssp = 0.f;
#pragma unroll
                    for (int b = 0; b < 8; b++) {
                        int col = tx * 8 + b;
                        float av = Da[row * 128 + col];
                        float v = av * gelu_tanh(acc[a][b]);
                        ssp += v * v;
                        __nv_bfloat16 h = __float2bfloat16(v);
                        __nv_bfloat16 l = __float2bfloat16(v - __bfloat162float(h));
                        int f = tile * 128 + col;
                        int fb = f >> 5, pos = f & 31;
                        Vbf[(size_t)(pm + row) * VW + fb * 64 + pos] = h;
                        Vbf[(size_t)(pm + row) * VW + fb * 64 + 32 + pos] = l;
                    }
                    ssrd[row * 16 + tx] = ssp;
                }
            }
            __syncthreads();
        }
        if (tid < 128) {
            float sm = 0.f;
            for (int j = 0; j < 16; j++) sm += ssrd[tid * 16 + j];
            sspart[(size_t)(pm + tid) * NTILES + tile] = sm;
        }
        __syncthreads();
    }
#endif
}

// ---------------- K5: GEMM2  down = V @ (vn2*vw2) (unscaled) ------------------
#define SMEM5 (1024 + 2 * 24576)
__global__ void __launch_bounds__(128, 1) k5_gemm2(const __nv_bfloat16* __restrict__ Vbf,
                                                   const __nv_bfloat16* __restrict__ WT2,
                                                   float* __restrict__ C)
{
    extern __shared__ char smem[];
    uint32_t sbase = smem_u32(smem);
    int tid = threadIdx.x;
    int wid = tid >> 5, lid = tid & 31;
    int bm = blockIdx.x * 128;

#if defined(__CUDA_ARCH_FEAT_SM103_ALL)
    const uint32_t TSLOT = sbase;
    const uint32_t MBAR0 = sbase + 16;
    const uint32_t MBAR1 = sbase + 24;
    const uint32_t SDATA = sbase + 1024;

    if (wid == 0) TC_ALLOC(TSLOT, 64);
    if (tid == 0) { MBARRIER_INIT(MBAR0, 1); MBARRIER_INIT(MBAR1, 1); }
    __syncthreads();
    uint32_t tmem;
    asm volatile("ld.shared.b32 %0, [%1];" : "=r"(tmem) : "r"(TSLOT));

    const uint32_t IDESC = (1u << 4) | (1u << 7) | (1u << 10) | (8u << 17) | (8u << 24);

    auto load_stage = [&](int s) {
        int buf = s & 1;
        int ks = s * 64;
        uint32_t ab = SDATA + buf * 24576;
        uint32_t wb = ab + 16384;
        const __nv_bfloat16* Asrc = Vbf + (size_t)bm * VW + ks;
        const __nv_bfloat16* Wsrc = WT2 + ks;
#pragma unroll
        for (int j = 0; j < 8; j++) {
            int idx = tid + j * 128;
            int row = idx >> 3, c = idx & 7;
            uint32_t off = (uint32_t)(row * 128 + c * 16);
            uint32_t sw = off ^ ((off >> 3) & 0x70);
            CP_ASYNC16(ab + sw, (const void*)(Asrc + (size_t)row * VW + c * 8));
        }
#pragma unroll
        for (int j = 0; j < 4; j++) {
            int idx = tid + j * 128;
            int row = idx >> 3, c = idx & 7;
            uint32_t off = (uint32_t)(row * 128 + c * 16);
            uint32_t sw = off ^ ((off >> 3) & 0x70);
            CP_ASYNC16(wb + sw, (const void*)(Wsrc + (size_t)row * VW + c * 8));
        }
        CP_COMMIT();
    };

    int ph0 = 0, ph1 = 0;
    load_stage(0);
    for (int s = 0; s < NST2; s++) {
        int b = s & 1;
        if (s >= 1 && s + 1 < NST2) {
            if ((b ^ 1) == 0) { MBARRIER_WAIT_PARITY(MBAR0, ph0); ph0 ^= 1; }
            else              { MBARRIER_WAIT_PARITY(MBAR1, ph1); ph1 ^= 1; }
        }
        if (s + 1 < NST2) { load_stage(s + 1); CP_WAIT1(); }
        else              { CP_WAIT0(); }
        __syncthreads();
        FENCE_ASYNC_SH();
        if (wid == 0) {
            if (elect_one()) {
                uint32_t ab = SDATA + b * 24576;
                uint64_t ad = make_desc(ab);
                uint64_t bd = make_desc(ab + 16384);
                uint32_t en0 = (s > 0) ? 1u : 0u;
                mma_f16_ss(tmem, ad + 0, bd + 0, IDESC, en0);
                mma_f16_ss(tmem, ad + 2, bd + 2, IDESC, 1u);
                mma_f16_ss(tmem, ad + 4, bd + 0, IDESC, 1u);
                mma_f16_ss(tmem, ad + 6, bd + 2, IDESC, 1u);
                mma_f16_ss(tmem, ad + 0, bd + 4, IDESC, 1u);
                mma_f16_ss(tmem, ad + 2, bd + 6, IDESC, 1u);
                if (b == 0) TC_COMMIT(MBAR0); else TC_COMMIT(MBAR1);
            }
        }
    }
    MBARRIER_WAIT_PARITY(MBAR1, ph1);   // last stage s=75 -> buffer 1
    TC_FENCE_AFTER();

    {
        int m = bm + wid * 32 + lid;
        uint32_t r[32];
        TC_LD_X32(r, tmem);
        TC_WAIT_LD();
        float4* dst = (float4*)(C + (size_t)m * 64);
#pragma unroll
        for (int j = 0; j < 8; j++)
            dst[j] = make_float4(__uint_as_float(r[4 * j + 0]), __uint_as_float(r[4 * j + 1]),
                                 __uint_as_float(r[4 * j + 2]), __uint_as_float(r[4 * j + 3]));
        uint32_t r2[32];
        TC_LD_X32(r2, tmem + 32);
        TC_WAIT_LD();
#pragma unroll
        for (int j = 0; j < 8; j++)
            dst[8 + j] = make_float4(__uint_as_float(r2[4 * j + 0]), __uint_as_float(r2[4 * j + 1]),
                                     __uint_as_float(r2[4 * j + 2]), __uint_as_float(r2[4 * j + 3]));
    }
    __syncthreads();
    if (wid == 0) {
        TC_RELINQ();
        TC_DEALLOC(tmem, 64);
    }
#else
    // ---- FFMA fallback ----
    float* Bs = (float*)smem;            // [16][64]
    for (int m0 = 0; m0 < 128; m0 += 32) {
        int m = bm + m0 + (tid >> 2);
        int nq = (tid & 3) * 16;
        float acc[16];
#pragma unroll
        for (int a = 0; a < 16; a++) acc[a] = 0.f;
        for (int k0 = 0; k0 < KPAD2; k0 += 16) {
            __syncthreads();
            for (int idx = tid; idx < 1024; idx += 128) {
                int kk = idx >> 6, n = idx & 63;
                int k = k0 + kk;
                const __nv_bfloat16* wr = WT2 + (size_t)n * VW + (size_t)(k >> 5) * 64 + (k & 31);
                Bs[kk * 64 + n] = __bfloat162float(wr[0]) + __bfloat162float(wr[32]);
            }
            __syncthreads();
#pragma unroll
            for (int kk = 0; kk < 16; kk++) {
                int k = k0 + kk;
                const __nv_bfloat16* ar = Vbf + (size_t)m * VW + (size_t)(k >> 5) * 64 + (k & 31);
                float av = __bfloat162float(ar[0]) + __bfloat162float(ar[32]);
#pragma unroll
                for (int a = 0; a < 16; a++) acc[a] += av * Bs[kk * 64 + nq + a];
            }
        }
        for (int a = 0; a < 16; a++) C[(size_t)m * 64 + nq + a] = acc[a];
        __syncthreads();
    }
#endif
}

// ---------------- K6: row-scale + final linear ---------------------------------
__global__ void k6_final(const float* __restrict__ t,
                         const float* __restrict__ fw, const float* __restrict__ fb,
                         float* __restrict__ out)
{
    int i = blockIdx.x * blockDim.x + threadIdx.x;
    if (i >= NPTS) return;

    const float* sp = g_sspart + (size_t)i * NTILES;
    float ss = 0.f;
#pragma unroll
    for (int r = 0; r < NTILES; r++) ss += sp[r];
    float sc = 1.0f / (sqrtf(ss / (float)TOTAL) + 1e-8f);

    const float* dr = g_down + (size_t)i * 64;
    float o0 = 0.f, o1 = 0.f, o2 = 0.f, o3 = 0.f;
#pragma unroll 8
    for (int r = 0; r < 64; r++) {
        float a = dr[r];
        o0 += a * fw[r * 4 + 0];
        o1 += a * fw[r * 4 + 1];
        o2 += a * fw[r * 4 + 2];
        o3 += a * fw[r * 4 + 3];
    }
    o0 *= sc; o1 *= sc; o2 *= sc; o3 *= sc;
    o0 += fb[0]; o1 += fb[1]; o2 += fb[2]; o3 += fb[3];
    float p0 = g_p[i * 3 + 0], p1 = g_p[i * 3 + 1], p2 = g_p[i * 3 + 2];
    float tv = t[i];
    o0 += p0 * fw[256 + 0] + p1 * fw[260 + 0] + p2 * fw[264 + 0] + tv * fw[268 + 0];
    o1 += p0 * fw[256 + 1] + p1 * fw[260 + 1] + p2 * fw[264 + 1] + tv * fw[268 + 1];
    o2 += p0 * fw[256 + 2] + p1 * fw[260 + 2] + p2 * fw[264 + 2] + tv * fw[268 + 2];
    o3 += p0 * fw[256 + 3] + p1 * fw[260 + 3] + p2 * fw[264 + 3] + tv * fw[268 + 3];
    out[i * 4 + 0] = o0;
    out[i * 4 + 1] = o1;
    out[i * 4 + 2] = o2;
    out[i * 4 + 3] = o3;
}

// ---------------- launcher ----------------------------------------------------
extern "C" void kernel_launch(void* const* d_in, const int* in_sizes, int n_in,
                              void* d_out, int out_size)
{
    const float* pos      = (const float*)d_in[0];
    const float* t        = (const float*)d_in[2];
    const float* table0   = (const float*)d_in[3];
    const float* table1   = (const float*)d_in[4];
    const float* table2   = (const float*)d_in[5];
    const float* table3   = (const float*)d_in[6];
    const float* st1      = (const float*)d_in[7];
    const float* st2      = (const float*)d_in[8];
    const float* tf       = (const float*)d_in[9];
    const float* sph_proj = (const float*)d_in[10];
    const float* tb1      = (const float*)d_in[11];
    const float* tb2      = (const float*)d_in[12];
    const float* gn1      = (const float*)d_in[13];
    const float* gw1      = (const float*)d_in[14];
    const float* gn2      = (const float*)d_in[15];
    const float* gw2      = (const float*)d_in[16];
    const float* gn3      = (const float*)d_in[17];
    const float* gw3      = (const float*)d_in[18];
    const float* vn1      = (const float*)d_in[19];
    const float* vw1      = (const float*)d_in[20];
    const float* vn2      = (const float*)d_in[21];
    const float* vw2      = (const float*)d_in[22];
    const float* fw       = (const float*)d_in[23];
    const float* fb       = (const float*)d_in[24];
    float* out = (float*)d_out;

    cudaFuncSetAttribute(k3_gemm1, cudaFuncAttributeMaxDynamicSharedMemorySize, SMEM1);
    cudaFuncSetAttribute(k5_gemm2, cudaFuncAttributeMaxDynamicSharedMemorySize, SMEM5);

    k1_preamble<<<NPTS / 256, 256>>>(pos, t, sph_proj, tb1, tb2,
                                     gn1, gw1, gn2, gw2, gn3, gw3);

    dim3 gw(WTROWS / 32, KPAD1 / 32);     // (152, 74)
    k_convW<<<gw, dim3(32, 8)>>>(vw1);
    k_convW2<<<(TOTAL * 64 + 255) / 256, 256>>>(vw2, vn2);

    k2_gather<<<NPTS, 128>>>(t, table0, table1, table2, table3, st1, st2, tf, vn1);

    __nv_bfloat16* Abf; cudaGetSymbolAddress((void**)&Abf, g_Abf);
    __nv_bfloat16* Vbf; cudaGetSymbolAddress((void**)&Vbf, g_Vbf);
    __nv_bfloat16* WT;  cudaGetSymbolAddress((void**)&WT,  g_WT);
    __nv_bfloat16* WT2; cudaGetSymbolAddress((void**)&WT2, g_WT2);
    float* Dn;          cudaGetSymbolAddress((void**)&Dn,  g_down);
    float* Sp;          cudaGetSymbolAddress((void**)&Sp,  g_sspart);

    dim3 g1(NTILES, NPTS / 256);          // (19, 128)
    k3_gemm1<<<g1, 256, SMEM1>>>(Abf, WT, Vbf, Sp);

    k5_gemm2<<<NPTS / 128, 128, SMEM5>>>(Vbf, WT2, Dn);

    k6_final<<<NPTS / 256, 256>>>(t, fw, fb, out);
}

// round 8
// speedup vs baseline: 10.6262x; 1.3206x over previous
#include <cuda_runtime.h>
#include <cuda_bf16.h>
#include <math.h>
#include <stdint.h>

#define NPTS 32768
#define TOTAL 2336
#define KPAD1 2368         // GEMM1 K padded (74 blocks of 32)
#define NST1 74
#define KPAD2 2432         // GEMM2 K (76 blocks)
#define NST2 76
#define TWOTOTAL 4672
#define INNER 64
#define AW1 4736           // g_Abf row: 74 blocks x [hi32|lo32]
#define VW 4864            // g_Vbf / g_WT2 row: 76 blocks x [hi32|lo32]
#define WTS 4736           // g_WT row width (74 blocks)
#define WTROWS 4864        // permuted W1 rows (19 tiles x 256)
#define NTILES 19
#define NGRP 292           // TOTAL / 8

// ---------------- scratch (static device memory; zero-initialized) -----------
__device__ float g_p[NPTS * 3];
__device__ __align__(128) __nv_bfloat16 g_Abf[(size_t)NPTS * AW1];  // GEMM1 A split
__device__ __align__(128) __nv_bfloat16 g_Vbf[(size_t)NPTS * VW];   // V split (GEMM2 A)
__device__ __align__(128) __nv_bfloat16 g_WT[(size_t)WTROWS * WTS]; // permuted vw1^T split
__device__ __align__(128) __nv_bfloat16 g_WT2[(size_t)64 * VW];     // (vn2*vw2)^T split
__device__ float g_sspart[(size_t)NPTS * NTILES];                   // per-(row,tile) sum v^2
__device__ float g_down[NPTS * INNER];

// ---------------- common helpers ---------------------------------------------
__device__ __forceinline__ uint32_t smem_u32(const void* p) {
    uint32_t a;
    asm("{ .reg .u64 t; cvta.to.shared.u64 t, %1; cvt.u32.u64 %0, t; }" : "=r"(a) : "l"(p));
    return a;
}
__device__ __forceinline__ float sigmoidf_(float x) { return 1.0f / (1.0f + expf(-x)); }
__device__ __forceinline__ float gelu_tanh(float x) {
    float x3 = x * x * x;
    return 0.5f * x * (1.0f + tanhf(0.7978845608028654f * (x + 0.044715f * x3)));
}
__device__ __forceinline__ int wrapi(int v, int d) {
    if (v < 0) v += d; else if (v >= d) v -= d; return v;
}
__device__ const int FACE3[6][3] = {{1,0,0},{-1,0,0},{0,1,0},{0,-1,0},{0,0,1},{0,0,-1}};
__device__ const int ST8[8][4]   = {{1,0,0,0},{-1,0,0,0},{0,1,0,0},{0,-1,0,0},
                                    {0,0,1,0},{0,0,-1,0},{0,0,0,1},{0,0,0,-1}};

// cp.async helpers (baseline PTX)
#define CP_ASYNC16(smem, gmem) \
    asm volatile("cp.async.cg.shared.global [%0], [%1], 16;" :: "r"(smem), "l"(gmem) : "memory")
#define CP_COMMIT() asm volatile("cp.async.commit_group;" ::: "memory")
#define CP_WAIT1()  asm volatile("cp.async.wait_group 1;" ::: "memory")
#define CP_WAIT0()  asm volatile("cp.async.wait_group 0;" ::: "memory")

#if defined(__CUDA_ARCH_FEAT_SM103_ALL)
// ---------------- tcgen05 helpers (sm_103a pass only) -------------------------
__device__ __forceinline__ uint32_t elect_one() {
    uint32_t p;
    asm volatile("{ .reg .pred p; elect.sync _|p, 0xFFFFFFFF; selp.b32 %0,1,0,p; }" : "=r"(p));
    return p;
}
#define MBARRIER_INIT(addr, cnt) \
    asm volatile("mbarrier.init.shared.b64 [%0], %1;" :: "r"(addr), "r"(cnt) : "memory")
#define MBARRIER_WAIT_PARITY(addr, parity) do { \
    uint32_t _m = (addr); uint32_t _p = (parity); uint32_t _d; \
    asm volatile("{ .reg .pred p; mbarrier.try_wait.parity.acquire.cta.shared::cta.b64 p, [%1], %2; selp.b32 %0,1,0,p; }" \
        : "=r"(_d) : "r"(_m), "r"(_p) : "memory"); \
    if (!_d) { \
        asm volatile("{ .reg .pred P1; WL_%=: mbarrier.try_wait.parity.acquire.cta.shared::cta.b64 P1, [%0], %1, 0x989680; @P1 bra.uni WD_%=; bra.uni WL_%=; WD_%=: }" \
            :: "r"(_m), "r"(_p) : "memory"); \
    } } while (0)
// .noinc: the async arrive CONSUMES one of the init-count arrivals (required
// for counting producer completions; the default form is init-count-neutral
// and deadlocks this ring).
#define CPA_MBAR_ARRIVE_NOINC(mbar) \
    asm volatile("cp.async.mbarrier.arrive.noinc.shared::cta.b64 [%0];" :: "r"(mbar) : "memory")
#define TC_ALLOC(slot, n)  asm volatile("tcgen05.alloc.cta_group::1.sync.aligned.shared::cta.b32 [%0], %1;" :: "r"(slot), "r"(n) : "memory")
#define TC_DEALLOC(t, n)   asm volatile("tcgen05.dealloc.cta_group::1.sync.aligned.b32 %0, %1;" :: "r"(t), "r"(n))
#define TC_RELINQ()        asm volatile("tcgen05.relinquish_alloc_permit.cta_group::1.sync.aligned;")
#define TC_COMMIT(mbar)    asm volatile("tcgen05.commit.cta_group::1.mbarrier::arrive::one.shared::cluster.b64 [%0];" :: "r"(mbar) : "memory")
#define TC_WAIT_LD()       asm volatile("tcgen05.wait::ld.sync.aligned;" ::: "memory")
#define TC_FENCE_AFTER()   asm volatile("tcgen05.fence::after_thread_sync;" ::: "memory")
#define FENCE_ASYNC_SH()   asm volatile("fence.proxy.async.shared::cta;" ::: "memory")
#define TC_LD_X32(r, addr) \
    asm volatile("tcgen05.ld.sync.aligned.32x32b.x32.b32 " \
        "{%0,%1,%2,%3,%4,%5,%6,%7,%8,%9,%10,%11,%12,%13,%14,%15," \
        "%16,%17,%18,%19,%20,%21,%22,%23,%24,%25,%26,%27,%28,%29,%30,%31}, [%32];" \
        : "=r"((r)[0]),"=r"((r)[1]),"=r"((r)[2]),"=r"((r)[3]),"=r"((r)[4]),"=r"((r)[5]),"=r"((r)[6]),"=r"((r)[7]), \
          "=r"((r)[8]),"=r"((r)[9]),"=r"((r)[10]),"=r"((r)[11]),"=r"((r)[12]),"=r"((r)[13]),"=r"((r)[14]),"=r"((r)[15]), \
          "=r"((r)[16]),"=r"((r)[17]),"=r"((r)[18]),"=r"((r)[19]),"=r"((r)[20]),"=r"((r)[21]),"=r"((r)[22]),"=r"((r)[23]), \
          "=r"((r)[24]),"=r"((r)[25]),"=r"((r)[26]),"=r"((r)[27]),"=r"((r)[28]),"=r"((r)[29]),"=r"((r)[30]),"=r"((r)[31]) \
        : "r"(addr))
static constexpr uint64_t SMEM_DESC_BASE =
    (uint64_t(2) << 61) | (uint64_t(1) << 46) | (uint64_t(64) << 32) | (uint64_t(1) << 16);
__device__ __forceinline__ uint64_t make_desc(uint32_t addr) {
    return SMEM_DESC_BASE | ((uint64_t)(addr >> 4) & 0x3FFF);
}
__device__ __forceinline__ void mma_f16_ss(uint32_t d, uint64_t a, uint64_t b,
                                           uint32_t idesc, uint32_t en) {
    asm volatile("{ .reg .pred p; setp.ne.u32 p, %4, 0;"
                 "tcgen05.mma.cta_group::1.kind::f16 [%0], %1, %2, %3, {%5,%5,%5,%5}, p; }"
                 :: "r"(d), "l"(a), "l"(b), "r"(idesc), "r"(en), "r"(0u) : "memory");
}
#endif

// ---------------- K1: per-point preamble MLP -> p ----------------------------
__global__ void k1_preamble(const float* __restrict__ pos, const float* __restrict__ t,
                            const float* __restrict__ sph_proj,
                            const float* __restrict__ tb1, const float* __restrict__ tb2,
                            const float* __restrict__ gn1, const float* __restrict__ gw1,
                            const float* __restrict__ gn2, const float* __restrict__ gw2,
                            const float* __restrict__ gn3, const float* __restrict__ gw3)
{
    int i = blockIdx.x * blockDim.x + threadIdx.x;
    if (i >= NPTS) return;

    float x = pos[i * 3 + 0], y = pos[i * 3 + 1], z = pos[i * 3 + 2];
    float rho = sqrtf(x * x + y * y + z * z);
    float phi = atan2f(y, x);
    float cz = z / rho;
    cz = fminf(1.0f, fmaxf(-1.0f, cz));
    float theta = acosf(cz);

    float h[12];
#pragma unroll
    for (int j = 0; j < 8; j++)
        h[j] = rho * sph_proj[j] + phi * sph_proj[8 + j] + theta * sph_proj[16 + j];
    float tv = t[i];
    float ct = cosf(tv + tb1[0]);
    float st = sinf(tv + tb2[0]);
    h[8] = ct; h[9] = st;
    h[10] = ct * sigmoidf_(ct);
    h[11] = st * sigmoidf_(st);

    float ss = 0.f;
#pragma unroll
    for (int j = 0; j < 12; j++) ss += h[j] * h[j];
    float sc = 1.0f / (sqrtf(ss / 12.0f) + 1e-8f);
    float hn[12];
#pragma unroll
    for (int j = 0; j < 12; j++) hn[j] = gn1[j] * h[j] * sc;
    float y1[32];
#pragma unroll
    for (int j = 0; j < 32; j++) y1[j] = 0.f;
#pragma unroll
    for (int r = 0; r < 12; r++) {
        float a = hn[r];
#pragma unroll
        for (int j = 0; j < 32; j++) y1[j] += a * gw1[r * 32 + j];
    }
    float h2[16];
#pragma unroll
    for (int k = 0; k < 16; k++) h2[k] = y1[k] * gelu_tanh(y1[16 + k]);

    ss = 0.f;
#pragma unroll
    for (int j = 0; j < 16; j++) ss += h2[j] * h2[j];
    sc = 1.0f / (sqrtf(ss / 16.0f) + 1e-8f);
    float hn2[16];
#pragma unroll
    for (int j = 0; j < 16; j++) hn2[j] = gn2[j] * h2[j] * sc;
    float y2[32];
#pragma unroll
    for (int j = 0; j < 32; j++) y2[j] = 0.f;
#pragma unroll
    for (int r = 0; r < 16; r++) {
        float a = hn2[r];
#pragma unroll
        for (int j = 0; j < 32; j++) y2[j] += a * gw2[r * 32 + j];
    }
    float h3[16];
#pragma unroll
    for (int k = 0; k < 16; k++) h3[k] = y2[k] * gelu_tanh(y2[16 + k]);

    ss = 0.f;
#pragma unroll
    for (int j = 0; j < 16; j++) ss += h3[j] * h3[j];
    sc = 1.0f / (sqrtf(ss / 16.0f) + 1e-8f);
    float z3[3] = {0.f, 0.f, 0.f};
#pragma unroll
    for (int r = 0; r < 16; r++) {
        float a = gn3[r] * h3[r] * sc;
#pragma unroll
        for (int j = 0; j < 3; j++) z3[j] += a * gw3[r * 3 + j];
    }
    g_p[i * 3 + 0] = sigmoidf_(z3[0]);
    g_p[i * 3 + 1] = sigmoidf_(z3[1]);
    g_p[i * 3 + 2] = sigmoidf_(z3[2]);
}

// ---------------- K2: gather (group-of-8 decode) + rmsnorm -> hi/lo bf16 ------
__global__ void k2_gather(const float* __restrict__ t,
                          const float* __restrict__ table0, const float* __restrict__ table1,
                          const float* __restrict__ table2, const float* __restrict__ table3,
                          const float* __restrict__ st1, const float* __restrict__ st2,
                          const float* __restrict__ tf, const float* __restrict__ vn1)
{
    int i = blockIdx.x;
    __shared__ const float* segp[47];
    __shared__ __align__(16) float feat[TOTAL];   // 16B aligned: float4 access below
    __shared__ __align__(16) float red[128];

    float p0 = g_p[i * 3 + 0], p1 = g_p[i * 3 + 1], p2 = g_p[i * 3 + 2];
    float tt = t[i];

    int s = threadIdx.x;
    if (s < 47) {
        const float* base = nullptr;
        if (s < 28) {
            int tb = s / 7;
            int o = s % 7;
            int d, F; const float* T;
            if (tb == 0)      { d = 128; F = 16;  T = table0; }
            else if (tb == 1) { d = 64;  F = 32;  T = table1; }
            else if (tb == 2) { d = 32;  F = 64;  T = table2; }
            else              { d = 16;  F = 128; T = table3; }
            int ix = (int)(p0 * (float)(d - 1));
            int iy = (int)(p1 * (float)(d - 1));
            int iz = (int)(p2 * (float)(d - 1));
            if (o > 0) {
                ix = wrapi(ix + FACE3[o - 1][0], d);
                iy = wrapi(iy + FACE3[o - 1][1], d);
                iz = wrapi(iz + FACE3[o - 1][2], d);
            }
            base = T + (size_t)((ix * d + iy) * d + iz) * F;
        } else if (s < 46) {
            int grp = (s - 28) / 9;
            int o = (s - 28) % 9;
            if (grp == 0) {
                int a = (int)(p0 * 15.0f), b = (int)(p1 * 15.0f),
                    c = (int)(p2 * 15.0f), e = (int)(tt * 63.0f);
                if (o > 0) {
                    a = wrapi(a + ST8[o - 1][0], 16);
                    b = wrapi(b + ST8[o - 1][1], 16);
                    c = wrapi(c + ST8[o - 1][2], 16);
                    e = wrapi(e + ST8[o - 1][3], 64);
                }
                base = st1 + (size_t)(((a * 16 + b) * 16 + c) * 64 + e) * 64;
            } else {
                int a = (int)(p0 * 63.0f), b = (int)(p1 * 63.0f),
                    c = (int)(p2 * 31.0f), e = (int)(tt * 15.0f);
                if (o > 0) {
                    a = wrapi(a + ST8[o - 1][0], 64);
                    b = wrapi(b + ST8[o - 1][1], 64);
                    c = wrapi(c + ST8[o - 1][2], 32);
                    e = wrapi(e + ST8[o - 1][3], 16);
                }
                base = st2 + (size_t)(((a * 64 + b) * 32 + c) * 16 + e) * 8;
            }
        } else {
            int a = (int)(p0 * 3.0f), b = (int)(p1 * 3.0f),
                c = (int)(p2 * 3.0f), e = (int)(tt * 65535.0f);
            base = tf + (size_t)(((a * 4 + b) * 4 + c) * 65536 + e) * 8;
        }
        segp[s] = base;
    }
    __syncthreads();

    // gather in groups of 8 (all segments are 8-aligned multiples of 8)
    float ss = 0.f;
    for (int g = threadIdx.x; g < NGRP; g += 128) {
        int f0 = g * 8;
        int seg, off;
        if (f0 < 112)       { seg = f0 >> 4;                 off = f0 & 15; }
        else if (f0 < 336)  { int q = f0 - 112;  seg = 7  + (q >> 5); off = q & 31; }
        else if (f0 < 784)  { int q = f0 - 336;  seg = 14 + (q >> 6); off = q & 63; }
        else if (f0 < 1680) { int q = f0 - 784;  seg = 21 + (q >> 7); off = q & 127; }
        else if (f0 < 2256) { int q = f0 - 1680; seg = 28 + (q >> 6); off = q & 63; }
        else if (f0 < 2328) { int q = f0 - 2256; seg = 37 + (q >> 3); off = q & 7; }
        else                { seg = 46;                      off = f0 - 2328; }
        const float* sp = segp[seg] + off;
        float4 v0 = *(const float4*)sp;
        float4 v1 = *(const float4*)(sp + 4);
        *(float4*)&feat[f0] = v0;
        *(float4*)&feat[f0 + 4] = v1;
        ss += v0.x * v0.x + v0.y * v0.y + v0.z * v0.z + v0.w * v0.w
            + v1.x * v1.x + v1.y * v1.y + v1.z * v1.z + v1.w * v1.w;
    }
    red[threadIdx.x] = ss;
    __syncthreads();
    for (int w = 64; w > 0; w >>= 1) {
        if (threadIdx.x < w) red[threadIdx.x] += red[threadIdx.x + w];
        __syncthreads();
    }
    float rms = sqrtf(red[0] / (float)TOTAL);
    float sc = 1.0f / (rms + 1e-8f);
    __nv_bfloat16* orow = g_Abf + (size_t)i * AW1;
    for (int g = threadIdx.x; g < NGRP; g += 128) {
        int f0 = g * 8;
        float4 a0 = *(const float4*)&feat[f0];
        float4 a1 = *(const float4*)&feat[f0 + 4];
        float4 n0 = *(const float4*)&vn1[f0];
        float4 n1 = *(const float4*)&vn1[f0 + 4];
        float v[8] = { a0.x * n0.x * sc, a0.y * n0.y * sc, a0.z * n0.z * sc, a0.w * n0.w * sc,
                       a1.x * n1.x * sc, a1.y * n1.y * sc, a1.z * n1.z * sc, a1.w * n1.w * sc };
        uint32_t hi[4], lo[4];
#pragma unroll
        for (int j = 0; j < 4; j++) {
            __nv_bfloat16 h0 = __float2bfloat16(v[2 * j]);
            __nv_bfloat16 h1 = __float2bfloat16(v[2 * j + 1]);
            __nv_bfloat16 l0 = __float2bfloat16(v[2 * j] - __bfloat162float(h0));
            __nv_bfloat16 l1 = __float2bfloat16(v[2 * j + 1] - __bfloat162float(h1));
            hi[j] = (uint32_t)(*(unsigned short*)&h0) | ((uint32_t)(*(unsigned short*)&h1) << 16);
            lo[j] = (uint32_t)(*(unsigned short*)&l0) | ((uint32_t)(*(unsigned short*)&l1) << 16);
        }
        int blk = f0 >> 5, pos = f0 & 31;
        *(uint4*)(orow + blk * 64 + pos)      = make_uint4(hi[0], hi[1], hi[2], hi[3]);
        *(uint4*)(orow + blk * 64 + 32 + pos) = make_uint4(lo[0], lo[1], lo[2], lo[3]);
    }
}

// ---------------- K2b: permuted transpose + split vw1 -> g_WT -----------------
__global__ void k_convW(const float* __restrict__ vw1)
{
    __shared__ float sh[32][33];
    int n0 = blockIdx.x * 32, k0 = blockIdx.y * 32;
    int tx = threadIdx.x, ty = threadIdx.y;   // 32 x 8
    int tile = n0 >> 8, half = (n0 >> 7) & 1;
    int f0 = tile * 128 + (n0 & 127);
#pragma unroll
    for (int ii = 0; ii < 4; ii++) {
        int r = ty + ii * 8;
        int k = k0 + r;
        int f = f0 + tx;
        float v = 0.f;
        if (f < TOTAL && k < TOTAL)
            v = vw1[(size_t)k * TWOTOTAL + half * TOTAL + f];
        sh[r][tx] = v;
    }
    __syncthreads();
#pragma unroll
    for (int ii = 0; ii < 4; ii++) {
        int r = ty + ii * 8;
        int n = n0 + r;
        float v = sh[tx][r];
        __nv_bfloat16 h = __float2bfloat16(v);
        float hf = __bfloat162float(h);
        __nv_bfloat16 l = __float2bfloat16(v - hf);
        size_t base = (size_t)n * WTS + (size_t)(k0 * 2);
        g_WT[base + tx] = h;
        g_WT[base + 32 + tx] = l;
    }
}

// ---------------- K2c: (vn2 * vw2)^T split -> g_WT2 ---------------------------
__global__ void k_convW2(const float* __restrict__ vw2, const float* __restrict__ vn2)
{
    int idx = blockIdx.x * blockDim.x + threadIdx.x;
    if (idx >= TOTAL * 64) return;
    int k = idx >> 6, n = idx & 63;
    float v = vn2[k] * vw2[idx];
    __nv_bfloat16 h = __float2bfloat16(v);
    float hf = __bfloat162float(h);
    __nv_bfloat16 l = __float2bfloat16(v - hf);
    size_t base = (size_t)n * VW + (size_t)((k >> 5) * 64);
    g_WT2[base + (k & 31)] = h;
    g_WT2[base + 32 + (k & 31)] = l;
}

// ---------------- K3: warp-specialized GEMM1 + fused geglu epilogue -----------
#define SMEM1 (1024 + 3 * 65536)

__global__ void __launch_bounds__(256, 1) k3_gemm1(const __nv_bfloat16* __restrict__ Abf,
                                                   const __nv_bfloat16* __restrict__ WT,
                                                   __nv_bfloat16* __restrict__ Vbf,
                                                   float* __restrict__ sspart)
{
    extern __shared__ char smem[];
    uint32_t sbase = smem_u32(smem);
    int tid = threadIdx.x;
    int wid = tid >> 5, lid = tid & 31;
    int tile = blockIdx.x;
    int bm = blockIdx.y * 256;
    int bn = tile * 256;

#if defined(__CUDA_ARCH_FEAT_SM103_ALL)
    const uint32_t TSLOT = sbase;
    const uint32_t FUL0 = sbase + 16, FUL1 = sbase + 24, FUL2 = sbase + 32;
    const uint32_t EMP0 = sbase + 40, EMP1 = sbase + 48, EMP2 = sbase + 56;
    const uint32_t DONE = sbase + 64;
    const uint32_t SDATA = sbase + 1024;

    if (wid == 0) TC_ALLOC(TSLOT, 512);
    if (tid == 0) {
        MBARRIER_INIT(FUL0, 224); MBARRIER_INIT(FUL1, 224); MBARRIER_INIT(FUL2, 224);
        MBARRIER_INIT(EMP0, 1);   MBARRIER_INIT(EMP1, 1);   MBARRIER_INIT(EMP2, 1);
        MBARRIER_INIT(DONE, 1);
    }
    __syncthreads();
    uint32_t tmem;
    asm volatile("ld.shared.b32 %0, [%1];" : "=r"(tmem) : "r"(TSLOT));

    const uint32_t IDESC = (1u << 4) | (1u << 7) | (1u << 10) | (32u << 17) | (8u << 24);

    if (wid >= 1) {
        // ---------------- producers: warps 1-7 (224 threads) ----------------
        int ptid = tid - 32;
        int pe0 = 1, pe1 = 1, pe2 = 1;
        const __nv_bfloat16* Abase = Abf + (size_t)bm * AW1;
        const __nv_bfloat16* Wbase = WT + (size_t)bn * WTS;
        for (int s = 0; s < NST1; s++) {
            int b = s % 3;
            uint32_t emp = (b == 0) ? EMP0 : (b == 1) ? EMP1 : EMP2;
            uint32_t ful = (b == 0) ? FUL0 : (b == 1) ? FUL1 : FUL2;
            if (b == 0)      { MBARRIER_WAIT_PARITY(emp, pe0); pe0 ^= 1; }
            else if (b == 1) { MBARRIER_WAIT_PARITY(emp, pe1); pe1 ^= 1; }
            else             { MBARRIER_WAIT_PARITY(emp, pe2); pe2 ^= 1; }
            uint32_t ab = SDATA + b * 65536;
            int ks = s * 64;
            for (int idx = ptid; idx < 4096; idx += 224) {
                int half = idx >> 11;              // 0 = A, 1 = W
                int r = (idx & 2047) >> 3, c = idx & 7;
                uint32_t off = (uint32_t)(r * 128 + c * 16);
                uint32_t sw = off ^ ((off >> 3) & 0x70);
                if (half == 0)
                    CP_ASYNC16(ab + sw, (const void*)(Abase + (size_t)r * AW1 + ks + c * 8));
                else
                    CP_ASYNC16(ab + 32768 + sw, (const void*)(Wbase + (size_t)r * WTS + ks + c * 8));
            }
            CPA_MBAR_ARRIVE_NOINC(ful);
        }
    } else if (elect_one()) {
        // ---------------- consumer: single elected lane of warp 0 -----------
        int pf0 = 0, pf1 = 0, pf2 = 0;
        for (int s = 0; s < NST1; s++) {
            int b = s % 3;
            uint32_t ful = (b == 0) ? FUL0 : (b == 1) ? FUL1 : FUL2;
            uint32_t emp = (b == 0) ? EMP0 : (b == 1) ? EMP1 : EMP2;
            if (b == 0)      { MBARRIER_WAIT_PARITY(ful, pf0); pf0 ^= 1; }
            else if (b == 1) { MBARRIER_WAIT_PARITY(ful, pf1); pf1 ^= 1; }
            else             { MBARRIER_WAIT_PARITY(ful, pf2); pf2 ^= 1; }
            FENCE_ASYNC_SH();
            uint32_t ab = SDATA + b * 65536;
            uint64_t bd = make_desc(ab + 32768);
#pragma unroll
            for (int half = 0; half < 2; half++) {
                uint64_t ad = make_desc(ab + half * 16384);
                uint32_t dt = tmem + half * 256;
                uint32_t en0 = (s > 0) ? 1u : 0u;
                mma_f16_ss(dt, ad + 0, bd + 0, IDESC, en0);
                mma_f16_ss(dt, ad + 2, bd + 2, IDESC, 1u);
                mma_f16_ss(dt, ad + 4, bd + 0, IDESC, 1u);
                mma_f16_ss(dt, ad + 6, bd + 2, IDESC, 1u);
                mma_f16_ss(dt, ad + 0, bd + 4, IDESC, 1u);
                mma_f16_ss(dt, ad + 2, bd + 6, IDESC, 1u);
            }
            TC_COMMIT(emp);
        }
        TC_COMMIT(DONE);
    }
    MBARRIER_WAIT_PARITY(DONE, 0);
    TC_FENCE_AFTER();

    // fused epilogue: a = cols 0-127, g = cols 128-255 -> v = a*gelu(g)
    {
        int m = bm + ((wid < 4) ? 0 : 128) + (wid & 3) * 32 + lid;
        uint32_t dbase = tmem + ((wid < 4) ? 0 : 256);
        float ssacc = 0.f;
#pragma unroll
        for (int cp = 0; cp < 4; cp++) {
            uint32_t ra[32], rg[32];
            TC_LD_X32(ra, dbase + cp * 32);
            TC_LD_X32(rg, dbase + 128 + cp * 32);
            TC_WAIT_LD();
            uint32_t o[32];
#pragma unroll
            for (int j = 0; j < 32; j += 2) {
                float a0 = __uint_as_float(ra[j]),     a1 = __uint_as_float(ra[j + 1]);
                float g0 = __uint_as_float(rg[j]),     g1 = __uint_as_float(rg[j + 1]);
                float v0 = a0 * gelu_tanh(g0), v1 = a1 * gelu_tanh(g1);
                ssacc += v0 * v0 + v1 * v1;
                __nv_bfloat16 h0 = __float2bfloat16(v0);
                __nv_bfloat16 h1 = __float2bfloat16(v1);
                __nv_bfloat16 l0 = __float2bfloat16(v0 - __bfloat162float(h0));
                __nv_bfloat16 l1 = __float2bfloat16(v1 - __bfloat162float(h1));
                unsigned short uh0 = *(unsigned short*)&h0, uh1 = *(unsigned short*)&h1;
                unsigned short ul0 = *(unsigned short*)&l0, ul1 = *(unsigned short*)&l1;
                o[j >> 1]        = (uint32_t)uh0 | ((uint32_t)uh1 << 16);
                o[16 + (j >> 1)] = (uint32_t)ul0 | ((uint32_t)ul1 << 16);
            }
            int fb = tile * 4 + cp;
            uint4* dst = (uint4*)(Vbf + (size_t)m * VW + fb * 64);
#pragma unroll
            for (int q = 0; q < 8; q++)
                dst[q] = make_uint4(o[4 * q], o[4 * q + 1], o[4 * q + 2], o[4 * q + 3]);
        }
        sspart[(size_t)m * NTILES + tile] = ssacc;
    }
    __syncthreads();
    if (wid == 0) {
        TC_RELINQ();
        TC_DEALLOC(tmem, 512);
    }
#else
    // ---- FFMA fallback (generic pass; never selected on sm_103a) ----
    float* Da   = (float*)smem;                    // 128 x 128
    float* As   = Da + 128 * 128;                  // 16 x 128
    float* Bs   = As + 16 * 128;                   // 16 x 128
    float* ssrd = Bs + 16 * 128;                   // 128 x 16
    int tx = tid % 16, ty = tid / 16;
    for (int pass = 0; pass < 2; pass++) {
        int pm = bm + pass * 128;
        for (int half = 0; half < 2; half++) {
            int pn = bn + half * 128;
            float acc[8][8];
#pragma unroll
            for (int a = 0; a < 8; a++)
#pragma unroll
                for (int b = 0; b < 8; b++) acc[a][b] = 0.f;
            for (int k0 = 0; k0 < KPAD1; k0 += 16) {
                __syncthreads();
                for (int idx = tid; idx < 2048; idx += 256) {
                    int row = idx >> 4, kk = idx & 15;
                    int k = k0 + kk;
                    size_t pb = (size_t)(k >> 5) * 64 + (k & 31);
                    const __nv_bfloat16* ar = Abf + (size_t)(pm + row) * AW1 + pb;
                    const __nv_bfloat16* wr = WT + (size_t)(pn + row) * WTS + pb;
                    As[kk * 128 + row] = __bfloat162float(ar[0]) + __bfloat162float(ar[32]);
                    Bs[kk * 128 + row] = __bfloat162float(wr[0]) + __bfloat162float(wr[32]);
                }
                __syncthreads();
#pragma unroll
                for (int k = 0; k < 16; k++) {
                    float af[8], bf[8];
#pragma unroll
                    for (int a = 0; a < 8; a++) af[a] = As[k * 128 + ty * 8 + a];
#pragma unroll
                    for (int b = 0; b < 8; b++) bf[b] = Bs[k * 128 + tx * 8 + b];
#pragma unroll
                    for (int a = 0; a < 8; a++)
#pragma unroll
                        for (int b = 0; b < 8; b++) acc[a][b] += af[a] * bf[b];
                }
            }
            __syncthreads();
            if (half == 0) {
#pragma unroll
                for (int a = 0; a < 8; a++)
#pragma unroll
                    for (int b = 0; b < 8; b++)
                        Da[(ty * 8 + a) * 128 + tx * 8 + b] = acc[a][b];
            } else {
#pragma unroll
                for (int a = 0; a < 8; a++) {
                    int row = ty * 8 + a;
                    float ssp = 0.f;
#pragma unroll
                    for (int b = 0; b < 8; b++) {
                        int col = tx * 8 + b;
                        float av = Da[row * 128 + col];
                        float v = av * gelu_tanh(acc[a][b]);
                        ssp += v * v;
                        __nv_bfloat16 h = __float2bfloat16(v);
                        __nv_bfloat16 l = __float2bfloat16(v - __bfloat162float(h));
                        int f = tile * 128 + col;
                        int fb = f >> 5, pos = f & 31;
                        Vbf[(size_t)(pm + row) * VW + fb * 64 + pos] = h;
                        Vbf[(size_t)(pm + row) * VW + fb * 64 + 32 + pos] = l;
                    }
                    ssrd[row * 16 + tx] = ssp;
                }
            }
            __syncthreads();
        }
        if (tid < 128) {
            float sm = 0.f;
            for (int j = 0; j < 16; j++) sm += ssrd[tid * 16 + j];
            sspart[(size_t)(pm + tid) * NTILES + tile] = sm;
        }
        __syncthreads();
    }
#endif
}

// ---------------- K5: GEMM2  down = V @ (vn2*vw2) (unscaled) ------------------
#define SMEM5 (1024 + 2 * 24576)
__global__ void __launch_bounds__(128, 1) k5_gemm2(const __nv_bfloat16* __restrict__ Vbf,
                                                   const __nv_bfloat16* __restrict__ WT2,
                                                   float* __restrict__ C)
{
    extern __shared__ char smem[];
    uint32_t sbase = smem_u32(smem);
    int tid = threadIdx.x;
    int wid = tid >> 5, lid = tid & 31;
    int bm = blockIdx.x * 128;

#if defined(__CUDA_ARCH_FEAT_SM103_ALL)
    const uint32_t TSLOT = sbase;
    const uint32_t MBAR0 = sbase + 16;
    const uint32_t MBAR1 = sbase + 24;
    const uint32_t SDATA = sbase + 1024;

    if (wid == 0) TC_ALLOC(TSLOT, 64);
    if (tid == 0) { MBARRIER_INIT(MBAR0, 1); MBARRIER_INIT(MBAR1, 1); }
    __syncthreads();
    uint32_t tmem;
    asm volatile("ld.shared.b32 %0, [%1];" : "=r"(tmem) : "r"(TSLOT));

    const uint32_t IDESC = (1u << 4) | (1u << 7) | (1u << 10) | (8u << 17) | (8u << 24);

    auto load_stage = [&](int s) {
        int buf = s & 1;
        int ks = s * 64;
        uint32_t ab = SDATA + buf * 24576;
        uint32_t wb = ab + 16384;
        const __nv_bfloat16* Asrc = Vbf + (size_t)bm * VW + ks;
        const __nv_bfloat16* Wsrc = WT2 + ks;
#pragma unroll
        for (int j = 0; j < 8; j++) {
            int idx = tid + j * 128;
            int row = idx >> 3, c = idx & 7;
            uint32_t off = (uint32_t)(row * 128 + c * 16);
            uint32_t sw = off ^ ((off >> 3) & 0x70);
            CP_ASYNC16(ab + sw, (const void*)(Asrc + (size_t)row * VW + c * 8));
        }
#pragma unroll
        for (int j = 0; j < 4; j++) {
            int idx = tid + j * 128;
            int row = idx >> 3, c = idx & 7;
            uint32_t off = (uint32_t)(row * 128 + c * 16);
            uint32_t sw = off ^ ((off >> 3) & 0x70);
            CP_ASYNC16(wb + sw, (const void*)(Wsrc + (size_t)row * VW + c * 8));
        }
        CP_COMMIT();
    };

    int ph0 = 0, ph1 = 0;
    load_stage(0);
    for (int s = 0; s < NST2; s++) {
        int b = s & 1;
        if (s >= 1 && s + 1 < NST2) {
            if ((b ^ 1) == 0) { MBARRIER_WAIT_PARITY(MBAR0, ph0); ph0 ^= 1; }
            else              { MBARRIER_WAIT_PARITY(MBAR1, ph1); ph1 ^= 1; }
        }
        if (s + 1 < NST2) { load_stage(s + 1); CP_WAIT1(); }
        else              { CP_WAIT0(); }
        __syncthreads();
        FENCE_ASYNC_SH();
        if (wid == 0) {
            if (elect_one()) {
                uint32_t ab = SDATA + b * 24576;
                uint64_t ad = make_desc(ab);
                uint64_t bd = make_desc(ab + 16384);
                uint32_t en0 = (s > 0) ? 1u : 0u;
                mma_f16_ss(tmem, ad + 0, bd + 0, IDESC, en0);
                mma_f16_ss(tmem, ad + 2, bd + 2, IDESC, 1u);
                mma_f16_ss(tmem, ad + 4, bd + 0, IDESC, 1u);
                mma_f16_ss(tmem, ad + 6, bd + 2, IDESC, 1u);
                mma_f16_ss(tmem, ad + 0, bd + 4, IDESC, 1u);
                mma_f16_ss(tmem, ad + 2, bd + 6, IDESC, 1u);
                if (b == 0) TC_COMMIT(MBAR0); else TC_COMMIT(MBAR1);
            }
        }
    }
    MBARRIER_WAIT_PARITY(MBAR1, ph1);   // last stage s=75 -> buffer 1
    TC_FENCE_AFTER();

    {
        int m = bm + wid * 32 + lid;
        uint32_t r[32];
        TC_LD_X32(r, tmem);
        TC_WAIT_LD();
        float4* dst = (float4*)(C + (size_t)m * 64);
#pragma unroll
        for (int j = 0; j < 8; j++)
            dst[j] = make_float4(__uint_as_float(r[4 * j + 0]), __uint_as_float(r[4 * j + 1]),
                                 __uint_as_float(r[4 * j + 2]), __uint_as_float(r[4 * j + 3]));
        uint32_t r2[32];
        TC_LD_X32(r2, tmem + 32);
        TC_WAIT_LD();
#pragma unroll
        for (int j = 0; j < 8; j++)
            dst[8 + j] = make_float4(__uint_as_float(r2[4 * j + 0]), __uint_as_float(r2[4 * j + 1]),
                                     __uint_as_float(r2[4 * j + 2]), __uint_as_float(r2[4 * j + 3]));
    }
    __syncthreads();
    if (wid == 0) {
        TC_RELINQ();
        TC_DEALLOC(tmem, 64);
    }
#else
    // ---- FFMA fallback ----
    float* Bs = (float*)smem;            // [16][64]
    for (int m0 = 0; m0 < 128; m0 += 32) {
        int m = bm + m0 + (tid >> 2);
        int nq = (tid & 3) * 16;
        float acc[16];
#pragma unroll
        for (int a = 0; a < 16; a++) acc[a] = 0.f;
        for (int k0 = 0; k0 < KPAD2; k0 += 16) {
            __syncthreads();
            for (int idx = tid; idx < 1024; idx += 128) {
                int kk = idx >> 6, n = idx & 63;
                int k = k0 + kk;
                const __nv_bfloat16* wr = WT2 + (size_t)n * VW + (size_t)(k >> 5) * 64 + (k & 31);
                Bs[kk * 64 + n] = __bfloat162float(wr[0]) + __bfloat162float(wr[32]);
            }
            __syncthreads();
#pragma unroll
            for (int kk = 0; kk < 16; kk++) {
                int k = k0 + kk;
                const __nv_bfloat16* ar = Vbf + (size_t)m * VW + (size_t)(k >> 5) * 64 + (k & 31);
                float av = __bfloat162float(ar[0]) + __bfloat162float(ar[32]);
#pragma unroll
                for (int a = 0; a < 16; a++) acc[a] += av * Bs[kk * 64 + nq + a];
            }
        }
        for (int a = 0; a < 16; a++) C[(size_t)m * 64 + nq + a] = acc[a];
        __syncthreads();
    }
#endif
}

// ---------------- K6: row-scale + final linear ---------------------------------
__global__ void k6_final(const float* __restrict__ t,
                         const float* __restrict__ fw, const float* __restrict__ fb,
                         float* __restrict__ out)
{
    int i = blockIdx.x * blockDim.x + threadIdx.x;
    if (i >= NPTS) return;

    const float* sp = g_sspart + (size_t)i * NTILES;
    float ss = 0.f;
#pragma unroll
    for (int r = 0; r < NTILES; r++) ss += sp[r];
    float sc = 1.0f / (sqrtf(ss / (float)TOTAL) + 1e-8f);

    const float* dr = g_down + (size_t)i * 64;
    float o0 = 0.f, o1 = 0.f, o2 = 0.f, o3 = 0.f;
#pragma unroll 8
    for (int r = 0; r < 64; r++) {
        float a = dr[r];
        o0 += a * fw[r * 4 + 0];
        o1 += a * fw[r * 4 + 1];
        o2 += a * fw[r * 4 + 2];
        o3 += a * fw[r * 4 + 3];
    }
    o0 *= sc; o1 *= sc; o2 *= sc; o3 *= sc;
    o0 += fb[0]; o1 += fb[1]; o2 += fb[2]; o3 += fb[3];
    float p0 = g_p[i * 3 + 0], p1 = g_p[i * 3 + 1], p2 = g_p[i * 3 + 2];
    float tv = t[i];
    o0 += p0 * fw[256 + 0] + p1 * fw[260 + 0] + p2 * fw[264 + 0] + tv * fw[268 + 0];
    o1 += p0 * fw[256 + 1] + p1 * fw[260 + 1] + p2 * fw[264 + 1] + tv * fw[268 + 1];
    o2 += p0 * fw[256 + 2] + p1 * fw[260 + 2] + p2 * fw[264 + 2] + tv * fw[268 + 2];
    o3 += p0 * fw[256 + 3] + p1 * fw[260 + 3] + p2 * fw[264 + 3] + tv * fw[268 + 3];
    out[i * 4 + 0] = o0;
    out[i * 4 + 1] = o1;
    out[i * 4 + 2] = o2;
    out[i * 4 + 3] = o3;
}

// ---------------- launcher ----------------------------------------------------
extern "C" void kernel_launch(void* const* d_in, const int* in_sizes, int n_in,
                              void* d_out, int out_size)
{
    const float* pos      = (const float*)d_in[0];
    const float* t        = (const float*)d_in[2];
    const float* table0   = (const float*)d_in[3];
    const float* table1   = (const float*)d_in[4];
    const float* table2   = (const float*)d_in[5];
    const float* table3   = (const float*)d_in[6];
    const float* st1      = (const float*)d_in[7];
    const float* st2      = (const float*)d_in[8];
    const float* tf       = (const float*)d_in[9];
    const float* sph_proj = (const float*)d_in[10];
    const float* tb1      = (const float*)d_in[11];
    const float* tb2      = (const float*)d_in[12];
    const float* gn1      = (const float*)d_in[13];
    const float* gw1      = (const float*)d_in[14];
    const float* gn2      = (const float*)d_in[15];
    const float* gw2      = (const float*)d_in[16];
    const float* gn3      = (const float*)d_in[17];
    const float* gw3      = (const float*)d_in[18];
    const float* vn1      = (const float*)d_in[19];
    const float* vw1      = (const float*)d_in[20];
    const float* vn2      = (const float*)d_in[21];
    const float* vw2      = (const float*)d_in[22];
    const float* fw       = (const float*)d_in[23];
    const float* fb       = (const float*)d_in[24];
    float* out = (float*)d_out;

    cudaFuncSetAttribute(k3_gemm1, cudaFuncAttributeMaxDynamicSharedMemorySize, SMEM1);
    cudaFuncSetAttribute(k5_gemm2, cudaFuncAttributeMaxDynamicSharedMemorySize, SMEM5);

    k1_preamble<<<NPTS / 256, 256>>>(pos, t, sph_proj, tb1, tb2,
                                     gn1, gw1, gn2, gw2, gn3, gw3);

    dim3 gw(WTROWS / 32, KPAD1 / 32);     // (152, 74)
    k_convW<<<gw, dim3(32, 8)>>>(vw1);
    k_convW2<<<(TOTAL * 64 + 255) / 256, 256>>>(vw2, vn2);

    k2_gather<<<NPTS, 128>>>(t, table0, table1, table2, table3, st1, st2, tf, vn1);

    __nv_bfloat16* Abf; cudaGetSymbolAddress((void**)&Abf, g_Abf);
    __nv_bfloat16* Vbf; cudaGetSymbolAddress((void**)&Vbf, g_Vbf);
    __nv_bfloat16* WT;  cudaGetSymbolAddress((void**)&WT,  g_WT);
    __nv_bfloat16* WT2; cudaGetSymbolAddress((void**)&WT2, g_WT2);
    float* Dn;          cudaGetSymbolAddress((void**)&Dn,  g_down);
    float* Sp;          cudaGetSymbolAddress((void**)&Sp,  g_sspart);

    dim3 g1(NTILES, NPTS / 256);          // (19, 128)
    k3_gemm1<<<g1, 256, SMEM1>>>(Abf, WT, Vbf, Sp);

    k5_gemm2<<<NPTS / 128, 128, SMEM5>>>(Vbf, WT2, Dn);

    k6_final<<<NPTS / 256, 256>>>(t, fw, fb, out);
}

// round 9
// speedup vs baseline: 11.0705x; 1.0418x over previous
#include <cuda_runtime.h>
#include <cuda_bf16.h>
#include <math.h>
#include <stdint.h>

#define NPTS 32768
#define TOTAL 2336
#define KPAD1 2368         // GEMM1 K padded (74 blocks of 32)
#define NST1 74
#define KPAD2 2432         // GEMM2 K (76 blocks)
#define NST2 76
#define TWOTOTAL 4672
#define INNER 64
#define AW1 4736           // g_Abf row: 74 blocks x [hi32|lo32]
#define VW 4864            // g_Vbf / g_WT2 row: 76 blocks x [hi32|lo32]
#define WTS 4736           // g_WT row width (74 blocks)
#define WTROWS 4864        // permuted W1 rows (19 tiles x 256)
#define NTILES 19
#define NGRP 292           // TOTAL / 8

// ---------------- scratch (static device memory; zero-initialized) -----------
__device__ float g_p[NPTS * 3];
__device__ __align__(128) __nv_bfloat16 g_Abf[(size_t)NPTS * AW1];  // GEMM1 A split
__device__ __align__(128) __nv_bfloat16 g_Vbf[(size_t)NPTS * VW];   // V split (GEMM2 A)
__device__ __align__(128) __nv_bfloat16 g_WT[(size_t)WTROWS * WTS]; // permuted vw1^T split
__device__ __align__(128) __nv_bfloat16 g_WT2[(size_t)64 * VW];     // (vn2*vw2)^T split
__device__ float g_sspart[(size_t)NPTS * NTILES];                   // per-(row,tile) sum v^2
__device__ float g_down[NPTS * INNER];

// ---------------- common helpers ---------------------------------------------
__device__ __forceinline__ uint32_t smem_u32(const void* p) {
    uint32_t a;
    asm("{ .reg .u64 t; cvta.to.shared.u64 t, %1; cvt.u32.u64 %0, t; }" : "=r"(a) : "l"(p));
    return a;
}
__device__ __forceinline__ float sigmoidf_(float x) { return 1.0f / (1.0f + expf(-x)); }
__device__ __forceinline__ float gelu_tanh(float x) {
    float x3 = x * x * x;
    return 0.5f * x * (1.0f + tanhf(0.7978845608028654f * (x + 0.044715f * x3)));
}
__device__ __forceinline__ int wrapi(int v, int d) {
    if (v < 0) v += d; else if (v >= d) v -= d; return v;
}
__device__ const int FACE3[6][3] = {{1,0,0},{-1,0,0},{0,1,0},{0,-1,0},{0,0,1},{0,0,-1}};
__device__ const int ST8[8][4]   = {{1,0,0,0},{-1,0,0,0},{0,1,0,0},{0,-1,0,0},
                                    {0,0,1,0},{0,0,-1,0},{0,0,0,1},{0,0,0,-1}};

// cp.async helpers (baseline PTX)
#define CP_ASYNC16(smem, gmem) \
    asm volatile("cp.async.cg.shared.global [%0], [%1], 16;" :: "r"(smem), "l"(gmem) : "memory")
#define CP_COMMIT() asm volatile("cp.async.commit_group;" ::: "memory")
#define CP_WAIT2()  asm volatile("cp.async.wait_group 2;" ::: "memory")
#define CP_WAIT1()  asm volatile("cp.async.wait_group 1;" ::: "memory")
#define CP_WAIT0()  asm volatile("cp.async.wait_group 0;" ::: "memory")

#if defined(__CUDA_ARCH_FEAT_SM103_ALL)
// ---------------- tcgen05 helpers (sm_103a pass only) -------------------------
__device__ __forceinline__ uint32_t elect_one() {
    uint32_t p;
    asm volatile("{ .reg .pred p; elect.sync _|p, 0xFFFFFFFF; selp.b32 %0,1,0,p; }" : "=r"(p));
    return p;
}
#define MBARRIER_INIT(addr, cnt) \
    asm volatile("mbarrier.init.shared.b64 [%0], %1;" :: "r"(addr), "r"(cnt) : "memory")
#define MBARRIER_WAIT_PARITY(addr, parity) do { \
    uint32_t _m = (addr); uint32_t _p = (parity); uint32_t _d; \
    asm volatile("{ .reg .pred p; mbarrier.try_wait.parity.acquire.cta.shared::cta.b64 p, [%1], %2; selp.b32 %0,1,0,p; }" \
        : "=r"(_d) : "r"(_m), "r"(_p) : "memory"); \
    if (!_d) { \
        asm volatile("{ .reg .pred P1; WL_%=: mbarrier.try_wait.parity.acquire.cta.shared::cta.b64 P1, [%0], %1, 0x989680; @P1 bra.uni WD_%=; bra.uni WL_%=; WD_%=: }" \
            :: "r"(_m), "r"(_p) : "memory"); \
    } } while (0)
// .noinc: the async arrive CONSUMES one of the init-count arrivals.
#define CPA_MBAR_ARRIVE_NOINC(mbar) \
    asm volatile("cp.async.mbarrier.arrive.noinc.shared::cta.b64 [%0];" :: "r"(mbar) : "memory")
#define TC_ALLOC(slot, n)  asm volatile("tcgen05.alloc.cta_group::1.sync.aligned.shared::cta.b32 [%0], %1;" :: "r"(slot), "r"(n) : "memory")
#define TC_DEALLOC(t, n)   asm volatile("tcgen05.dealloc.cta_group::1.sync.aligned.b32 %0, %1;" :: "r"(t), "r"(n))
#define TC_RELINQ()        asm volatile("tcgen05.relinquish_alloc_permit.cta_group::1.sync.aligned;")
#define TC_COMMIT(mbar)    asm volatile("tcgen05.commit.cta_group::1.mbarrier::arrive::one.shared::cluster.b64 [%0];" :: "r"(mbar) : "memory")
#define TC_WAIT_LD()       asm volatile("tcgen05.wait::ld.sync.aligned;" ::: "memory")
#define TC_FENCE_AFTER()   asm volatile("tcgen05.fence::after_thread_sync;" ::: "memory")
#define FENCE_ASYNC_SH()   asm volatile("fence.proxy.async.shared::cta;" ::: "memory")
#define TC_LD_X32(r, addr) \
    asm volatile("tcgen05.ld.sync.aligned.32x32b.x32.b32 " \
        "{%0,%1,%2,%3,%4,%5,%6,%7,%8,%9,%10,%11,%12,%13,%14,%15," \
        "%16,%17,%18,%19,%20,%21,%22,%23,%24,%25,%26,%27,%28,%29,%30,%31}, [%32];" \
        : "=r"((r)[0]),"=r"((r)[1]),"=r"((r)[2]),"=r"((r)[3]),"=r"((r)[4]),"=r"((r)[5]),"=r"((r)[6]),"=r"((r)[7]), \
          "=r"((r)[8]),"=r"((r)[9]),"=r"((r)[10]),"=r"((r)[11]),"=r"((r)[12]),"=r"((r)[13]),"=r"((r)[14]),"=r"((r)[15]), \
          "=r"((r)[16]),"=r"((r)[17]),"=r"((r)[18]),"=r"((r)[19]),"=r"((r)[20]),"=r"((r)[21]),"=r"((r)[22]),"=r"((r)[23]), \
          "=r"((r)[24]),"=r"((r)[25]),"=r"((r)[26]),"=r"((r)[27]),"=r"((r)[28]),"=r"((r)[29]),"=r"((r)[30]),"=r"((r)[31]) \
        : "r"(addr))
static constexpr uint64_t SMEM_DESC_BASE =
    (uint64_t(2) << 61) | (uint64_t(1) << 46) | (uint64_t(64) << 32) | (uint64_t(1) << 16);
__device__ __forceinline__ uint64_t make_desc(uint32_t addr) {
    return SMEM_DESC_BASE | ((uint64_t)(addr >> 4) & 0x3FFF);
}
__device__ __forceinline__ void mma_f16_ss(uint32_t d, uint64_t a, uint64_t b,
                                           uint32_t idesc, uint32_t en) {
    asm volatile("{ .reg .pred p; setp.ne.u32 p, %4, 0;"
                 "tcgen05.mma.cta_group::1.kind::f16 [%0], %1, %2, %3, {%5,%5,%5,%5}, p; }"
                 :: "r"(d), "l"(a), "l"(b), "r"(idesc), "r"(en), "r"(0u) : "memory");
}
#endif

// ---------------- K1: per-point preamble MLP -> p ----------------------------
__global__ void k1_preamble(const float* __restrict__ pos, const float* __restrict__ t,
                            const float* __restrict__ sph_proj,
                            const float* __restrict__ tb1, const float* __restrict__ tb2,
                            const float* __restrict__ gn1, const float* __restrict__ gw1,
                            const float* __restrict__ gn2, const float* __restrict__ gw2,
                            const float* __restrict__ gn3, const float* __restrict__ gw3)
{
    int i = blockIdx.x * blockDim.x + threadIdx.x;
    if (i >= NPTS) return;

    float x = pos[i * 3 + 0], y = pos[i * 3 + 1], z = pos[i * 3 + 2];
    float rho = sqrtf(x * x + y * y + z * z);
    float phi = atan2f(y, x);
    float cz = z / rho;
    cz = fminf(1.0f, fmaxf(-1.0f, cz));
    float theta = acosf(cz);

    float h[12];
#pragma unroll
    for (int j = 0; j < 8; j++)
        h[j] = rho * sph_proj[j] + phi * sph_proj[8 + j] + theta * sph_proj[16 + j];
    float tv = t[i];
    float ct = cosf(tv + tb1[0]);
    float st = sinf(tv + tb2[0]);
    h[8] = ct; h[9] = st;
    h[10] = ct * sigmoidf_(ct);
    h[11] = st * sigmoidf_(st);

    float ss = 0.f;
#pragma unroll
    for (int j = 0; j < 12; j++) ss += h[j] * h[j];
    float sc = 1.0f / (sqrtf(ss / 12.0f) + 1e-8f);
    float hn[12];
#pragma unroll
    for (int j = 0; j < 12; j++) hn[j] = gn1[j] * h[j] * sc;
    float y1[32];
#pragma unroll
    for (int j = 0; j < 32; j++) y1[j] = 0.f;
#pragma unroll
    for (int r = 0; r < 12; r++) {
        float a = hn[r];
#pragma unroll
        for (int j = 0; j < 32; j++) y1[j] += a * gw1[r * 32 + j];
    }
    float h2[16];
#pragma unroll
    for (int k = 0; k < 16; k++) h2[k] = y1[k] * gelu_tanh(y1[16 + k]);

    ss = 0.f;
#pragma unroll
    for (int j = 0; j < 16; j++) ss += h2[j] * h2[j];
    sc = 1.0f / (sqrtf(ss / 16.0f) + 1e-8f);
    float hn2[16];
#pragma unroll
    for (int j = 0; j < 16; j++) hn2[j] = gn2[j] * h2[j] * sc;
    float y2[32];
#pragma unroll
    for (int j = 0; j < 32; j++) y2[j] = 0.f;
#pragma unroll
    for (int r = 0; r < 16; r++) {
        float a = hn2[r];
#pragma unroll
        for (int j = 0; j < 32; j++) y2[j] += a * gw2[r * 32 + j];
    }
    float h3[16];
#pragma unroll
    for (int k = 0; k < 16; k++) h3[k] = y2[k] * gelu_tanh(y2[16 + k]);

    ss = 0.f;
#pragma unroll
    for (int j = 0; j < 16; j++) ss += h3[j] * h3[j];
    sc = 1.0f / (sqrtf(ss / 16.0f) + 1e-8f);
    float z3[3] = {0.f, 0.f, 0.f};
#pragma unroll
    for (int r = 0; r < 16; r++) {
        float a = gn3[r] * h3[r] * sc;
#pragma unroll
        for (int j = 0; j < 3; j++) z3[j] += a * gw3[r * 3 + j];
    }
    g_p[i * 3 + 0] = sigmoidf_(z3[0]);
    g_p[i * 3 + 1] = sigmoidf_(z3[1]);
    g_p[i * 3 + 2] = sigmoidf_(z3[2]);
}

// ---------------- K2: gather (register-resident) + rmsnorm -> hi/lo bf16 ------
__global__ void k2_gather(const float* __restrict__ t,
                          const float* __restrict__ table0, const float* __restrict__ table1,
                          const float* __restrict__ table2, const float* __restrict__ table3,
                          const float* __restrict__ st1, const float* __restrict__ st2,
                          const float* __restrict__ tf, const float* __restrict__ vn1)
{
    int i = blockIdx.x;
    __shared__ const float* segp[47];
    __shared__ __align__(16) float red[128];

    float p0 = g_p[i * 3 + 0], p1 = g_p[i * 3 + 1], p2 = g_p[i * 3 + 2];
    float tt = t[i];

    int s = threadIdx.x;
    if (s < 47) {
        const float* base = nullptr;
        if (s < 28) {
            int tb = s / 7;
            int o = s % 7;
            int d, F; const float* T;
            if (tb == 0)      { d = 128; F = 16;  T = table0; }
            else if (tb == 1) { d = 64;  F = 32;  T = table1; }
            else if (tb == 2) { d = 32;  F = 64;  T = table2; }
            else              { d = 16;  F = 128; T = table3; }
            int ix = (int)(p0 * (float)(d - 1));
            int iy = (int)(p1 * (float)(d - 1));
            int iz = (int)(p2 * (float)(d - 1));
            if (o > 0) {
                ix = wrapi(ix + FACE3[o - 1][0], d);
                iy = wrapi(iy + FACE3[o - 1][1], d);
                iz = wrapi(iz + FACE3[o - 1][2], d);
            }
            base = T + (size_t)((ix * d + iy) * d + iz) * F;
        } else if (s < 46) {
            int grp = (s - 28) / 9;
            int o = (s - 28) % 9;
            if (grp == 0) {
                int a = (int)(p0 * 15.0f), b = (int)(p1 * 15.0f),
                    c = (int)(p2 * 15.0f), e = (int)(tt * 63.0f);
                if (o > 0) {
                    a = wrapi(a + ST8[o - 1][0], 16);
                    b = wrapi(b + ST8[o - 1][1], 16);
                    c = wrapi(c + ST8[o - 1][2], 16);
                    e = wrapi(e + ST8[o - 1][3], 64);
                }
                base = st1 + (size_t)(((a * 16 + b) * 16 + c) * 64 + e) * 64;
            } else {
                int a = (int)(p0 * 63.0f), b = (int)(p1 * 63.0f),
                    c = (int)(p2 * 31.0f), e = (int)(tt * 15.0f);
                if (o > 0) {
                    a = wrapi(a + ST8[o - 1][0], 64);
                    b = wrapi(b + ST8[o - 1][1], 64);
                    c = wrapi(c + ST8[o - 1][2], 32);
                    e = wrapi(e + ST8[o - 1][3], 16);
                }
                base = st2 + (size_t)(((a * 64 + b) * 32 + c) * 16 + e) * 8;
            }
        } else {
            int a = (int)(p0 * 3.0f), b = (int)(p1 * 3.0f),
                c = (int)(p2 * 3.0f), e = (int)(tt * 65535.0f);
            base = tf + (size_t)(((a * 4 + b) * 4 + c) * 65536 + e) * 8;
        }
        segp[s] = base;
    }
    __syncthreads();

    // each thread owns up to 3 groups of 8; values stay in registers
    float4 v0[3], v1[3];
    float ss = 0.f;
#pragma unroll
    for (int gi = 0; gi < 3; gi++) {
        int g = threadIdx.x + gi * 128;
        if (g < NGRP) {
            int f0 = g * 8;
            int seg, off;
            if (f0 < 112)       { seg = f0 >> 4;                 off = f0 & 15; }
            else if (f0 < 336)  { int q = f0 - 112;  seg = 7  + (q >> 5); off = q & 31; }
            else if (f0 < 784)  { int q = f0 - 336;  seg = 14 + (q >> 6); off = q & 63; }
            else if (f0 < 1680) { int q = f0 - 784;  seg = 21 + (q >> 7); off = q & 127; }
            else if (f0 < 2256) { int q = f0 - 1680; seg = 28 + (q >> 6); off = q & 63; }
            else if (f0 < 2328) { int q = f0 - 2256; seg = 37 + (q >> 3); off = q & 7; }
            else                { seg = 46;                      off = f0 - 2328; }
            const float* sp = segp[seg] + off;
            float4 a = *(const float4*)sp;
            float4 b = *(const float4*)(sp + 4);
            v0[gi] = a; v1[gi] = b;
            ss += a.x * a.x + a.y * a.y + a.z * a.z + a.w * a.w
                + b.x * b.x + b.y * b.y + b.z * b.z + b.w * b.w;
        }
    }
    red[threadIdx.x] = ss;
    __syncthreads();
    for (int w = 64; w > 0; w >>= 1) {
        if (threadIdx.x < w) red[threadIdx.x] += red[threadIdx.x + w];
        __syncthreads();
    }
    float rms = sqrtf(red[0] / (float)TOTAL);
    float sc = 1.0f / (rms + 1e-8f);
    __nv_bfloat16* orow = g_Abf + (size_t)i * AW1;
#pragma unroll
    for (int gi = 0; gi < 3; gi++) {
        int g = threadIdx.x + gi * 128;
        if (g < NGRP) {
            int f0 = g * 8;
            float4 n0 = *(const float4*)&vn1[f0];
            float4 n1 = *(const float4*)&vn1[f0 + 4];
            float v[8] = { v0[gi].x * n0.x * sc, v0[gi].y * n0.y * sc,
                           v0[gi].z * n0.z * sc, v0[gi].w * n0.w * sc,
                           v1[gi].x * n1.x * sc, v1[gi].y * n1.y * sc,
                           v1[gi].z * n1.z * sc, v1[gi].w * n1.w * sc };
            uint32_t hi[4], lo[4];
#pragma unroll
            for (int j = 0; j < 4; j++) {
                __nv_bfloat16 h0 = __float2bfloat16(v[2 * j]);
                __nv_bfloat16 h1 = __float2bfloat16(v[2 * j + 1]);
                __nv_bfloat16 l0 = __float2bfloat16(v[2 * j] - __bfloat162float(h0));
                __nv_bfloat16 l1 = __float2bfloat16(v[2 * j + 1] - __bfloat162float(h1));
                hi[j] = (uint32_t)(*(unsigned short*)&h0) | ((uint32_t)(*(unsigned short*)&h1) << 16);
                lo[j] = (uint32_t)(*(unsigned short*)&l0) | ((uint32_t)(*(unsigned short*)&l1) << 16);
            }
            int blk = f0 >> 5, pos = f0 & 31;
            *(uint4*)(orow + blk * 64 + pos)      = make_uint4(hi[0], hi[1], hi[2], hi[3]);
            *(uint4*)(orow + blk * 64 + 32 + pos) = make_uint4(lo[0], lo[1], lo[2], lo[3]);
        }
    }
}

// ---------------- K2b: permuted transpose + split vw1 -> g_WT -----------------
__global__ void k_convW(const float* __restrict__ vw1)
{
    __shared__ float sh[32][33];
    int n0 = blockIdx.x * 32, k0 = blockIdx.y * 32;
    int tx = threadIdx.x, ty = threadIdx.y;   // 32 x 8
    int tile = n0 >> 8, half = (n0 >> 7) & 1;
    int f0 = tile * 128 + (n0 & 127);
#pragma unroll
    for (int ii = 0; ii < 4; ii++) {
        int r = ty + ii * 8;
        int k = k0 + r;
        int f = f0 + tx;
        float v = 0.f;
        if (f < TOTAL && k < TOTAL)
            v = vw1[(size_t)k * TWOTOTAL + half * TOTAL + f];
        sh[r][tx] = v;
    }
    __syncthreads();
#pragma unroll
    for (int ii = 0; ii < 4; ii++) {
        int r = ty + ii * 8;
        int n = n0 + r;
        float v = sh[tx][r];
        __nv_bfloat16 h = __float2bfloat16(v);
        float hf = __bfloat162float(h);
        __nv_bfloat16 l = __float2bfloat16(v - hf);
        size_t base = (size_t)n * WTS + (size_t)(k0 * 2);
        g_WT[base + tx] = h;
        g_WT[base + 32 + tx] = l;
    }
}

// ---------------- K2c: (vn2 * vw2)^T split -> g_WT2 ---------------------------
__global__ void k_convW2(const float* __restrict__ vw2, const float* __restrict__ vn2)
{
    int idx = blockIdx.x * blockDim.x + threadIdx.x;
    if (idx >= TOTAL * 64) return;
    int k = idx >> 6, n = idx & 63;
    float v = vn2[k] * vw2[idx];
    __nv_bfloat16 h = __float2bfloat16(v);
    float hf = __bfloat162float(h);
    __nv_bfloat16 l = __float2bfloat16(v - hf);
    size_t base = (size_t)n * VW + (size_t)((k >> 5) * 64);
    g_WT2[base + (k & 31)] = h;
    g_WT2[base + 32 + (k & 31)] = l;
}

// ---------------- K3: warp-specialized GEMM1 + fused geglu epilogue -----------
#define SMEM1 (1024 + 3 * 65536)

__global__ void __launch_bounds__(256, 1) k3_gemm1(const __nv_bfloat16* __restrict__ Abf,
                                                   const __nv_bfloat16* __restrict__ WT,
                                                   __nv_bfloat16* __restrict__ Vbf,
                                                   float* __restrict__ sspart)
{
    extern __shared__ char smem[];
    uint32_t sbase = smem_u32(smem);
    int tid = threadIdx.x;
    int wid = tid >> 5, lid = tid & 31;
    int tile = blockIdx.x;
    int bm = blockIdx.y * 256;
    int bn = tile * 256;

#if defined(__CUDA_ARCH_FEAT_SM103_ALL)
    const uint32_t TSLOT = sbase;
    const uint32_t FUL0 = sbase + 16, FUL1 = sbase + 24, FUL2 = sbase + 32;
    const uint32_t EMP0 = sbase + 40, EMP1 = sbase + 48, EMP2 = sbase + 56;
    const uint32_t DONE = sbase + 64;
    const uint32_t SDATA = sbase + 1024;

    if (wid == 0) TC_ALLOC(TSLOT, 512);
    if (tid == 0) {
        MBARRIER_INIT(FUL0, 224); MBARRIER_INIT(FUL1, 224); MBARRIER_INIT(FUL2, 224);
        MBARRIER_INIT(EMP0, 1);   MBARRIER_INIT(EMP1, 1);   MBARRIER_INIT(EMP2, 1);
        MBARRIER_INIT(DONE, 1);
    }
    __syncthreads();
    uint32_t tmem;
    asm volatile("ld.shared.b32 %0, [%1];" : "=r"(tmem) : "r"(TSLOT));

    const uint32_t IDESC = (1u << 4) | (1u << 7) | (1u << 10) | (32u << 17) | (8u << 24);

    if (wid >= 1) {
        // ---------------- producers: warps 1-7 (224 threads) ----------------
        int ptid = tid - 32;
        int pe0 = 1, pe1 = 1, pe2 = 1;
        const __nv_bfloat16* Abase = Abf + (size_t)bm * AW1;
        const __nv_bfloat16* Wbase = WT + (size_t)bn * WTS;
        for (int s = 0; s < NST1; s++) {
            int b = s % 3;
            uint32_t emp = (b == 0) ? EMP0 : (b == 1) ? EMP1 : EMP2;
            uint32_t ful = (b == 0) ? FUL0 : (b == 1) ? FUL1 : FUL2;
            if (b == 0)      { MBARRIER_WAIT_PARITY(emp, pe0); pe0 ^= 1; }
            else if (b == 1) { MBARRIER_WAIT_PARITY(emp, pe1); pe1 ^= 1; }
            else             { MBARRIER_WAIT_PARITY(emp, pe2); pe2 ^= 1; }
            uint32_t ab = SDATA + b * 65536;
            int ks = s * 64;
            for (int idx = ptid; idx < 4096; idx += 224) {
                int half = idx >> 11;              // 0 = A, 1 = W
                int r = (idx & 2047) >> 3, c = idx & 7;
                uint32_t off = (uint32_t)(r * 128 + c * 16);
                uint32_t sw = off ^ ((off >> 3) & 0x70);
                if (half == 0)
                    CP_ASYNC16(ab + sw, (const void*)(Abase + (size_t)r * AW1 + ks + c * 8));
                else
                    CP_ASYNC16(ab + 32768 + sw, (const void*)(Wbase + (size_t)r * WTS + ks + c * 8));
            }
            CPA_MBAR_ARRIVE_NOINC(ful);
        }
    } else if (elect_one()) {
        // ---------------- consumer: single elected lane of warp 0 -----------
        int pf0 = 0, pf1 = 0, pf2 = 0;
        for (int s = 0; s < NST1; s++) {
            int b = s % 3;
            uint32_t ful = (b == 0) ? FUL0 : (b == 1) ? FUL1 : FUL2;
            uint32_t emp = (b == 0) ? EMP0 : (b == 1) ? EMP1 : EMP2;
            if (b == 0)      { MBARRIER_WAIT_PARITY(ful, pf0); pf0 ^= 1; }
            else if (b == 1) { MBARRIER_WAIT_PARITY(ful, pf1); pf1 ^= 1; }
            else             { MBARRIER_WAIT_PARITY(ful, pf2); pf2 ^= 1; }
            FENCE_ASYNC_SH();
            uint32_t ab = SDATA + b * 65536;
            uint64_t bd = make_desc(ab + 32768);
#pragma unroll
            for (int half = 0; half < 2; half++) {
                uint64_t ad = make_desc(ab + half * 16384);
                uint32_t dt = tmem + half * 256;
                uint32_t en0 = (s > 0) ? 1u : 0u;
                mma_f16_ss(dt, ad + 0, bd + 0, IDESC, en0);
                mma_f16_ss(dt, ad + 2, bd + 2, IDESC, 1u);
                mma_f16_ss(dt, ad + 4, bd + 0, IDESC, 1u);
                mma_f16_ss(dt, ad + 6, bd + 2, IDESC, 1u);
                mma_f16_ss(dt, ad + 0, bd + 4, IDESC, 1u);
                mma_f16_ss(dt, ad + 2, bd + 6, IDESC, 1u);
            }
            TC_COMMIT(emp);
        }
        TC_COMMIT(DONE);
    }
    MBARRIER_WAIT_PARITY(DONE, 0);
    TC_FENCE_AFTER();

    // fused epilogue: a = cols 0-127, g = cols 128-255 -> v = a*gelu(g)
    {
        int m = bm + ((wid < 4) ? 0 : 128) + (wid & 3) * 32 + lid;
        uint32_t dbase = tmem + ((wid < 4) ? 0 : 256);
        float ssacc = 0.f;
#pragma unroll
        for (int cp = 0; cp < 4; cp++) {
            uint32_t ra[32], rg[32];
            TC_LD_X32(ra, dbase + cp * 32);
            TC_LD_X32(rg, dbase + 128 + cp * 32);
            TC_WAIT_LD();
            uint32_t o[32];
#pragma unroll
            for (int j = 0; j < 32; j += 2) {
                float a0 = __uint_as_float(ra[j]),     a1 = __uint_as_float(ra[j + 1]);
                float g0 = __uint_as_float(rg[j]),     g1 = __uint_as_float(rg[j + 1]);
                float v0 = a0 * gelu_tanh(g0), v1 = a1 * gelu_tanh(g1);
                ssacc += v0 * v0 + v1 * v1;
                __nv_bfloat16 h0 = __float2bfloat16(v0);
                __nv_bfloat16 h1 = __float2bfloat16(v1);
                __nv_bfloat16 l0 = __float2bfloat16(v0 - __bfloat162float(h0));
                __nv_bfloat16 l1 = __float2bfloat16(v1 - __bfloat162float(h1));
                unsigned short uh0 = *(unsigned short*)&h0, uh1 = *(unsigned short*)&h1;
                unsigned short ul0 = *(unsigned short*)&l0, ul1 = *(unsigned short*)&l1;
                o[j >> 1]        = (uint32_t)uh0 | ((uint32_t)uh1 << 16);
                o[16 + (j >> 1)] = (uint32_t)ul0 | ((uint32_t)ul1 << 16);
            }
            int fb = tile * 4 + cp;
            uint4* dst = (uint4*)(Vbf + (size_t)m * VW + fb * 64);
#pragma unroll
            for (int q = 0; q < 8; q++)
                dst[q] = make_uint4(o[4 * q], o[4 * q + 1], o[4 * q + 2], o[4 * q + 3]);
        }
        sspart[(size_t)m * NTILES + tile] = ssacc;
    }
    __syncthreads();
    if (wid == 0) {
        TC_RELINQ();
        TC_DEALLOC(tmem, 512);
    }
#else
    // ---- FFMA fallback (generic pass; never selected on sm_103a) ----
    float* Da   = (float*)smem;                    // 128 x 128
    float* As   = Da + 128 * 128;                  // 16 x 128
    float* Bs   = As + 16 * 128;                   // 16 x 128
    float* ssrd = Bs + 16 * 128;                   // 128 x 16
    int tx = tid % 16, ty = tid / 16;
    for (int pass = 0; pass < 2; pass++) {
        int pm = bm + pass * 128;
        for (int half = 0; half < 2; half++) {
            int pn = bn + half * 128;
            float acc[8][8];
#pragma unroll
            for (int a = 0; a < 8; a++)
#pragma unroll
                for (int b = 0; b < 8; b++) acc[a][b] = 0.f;
            for (int k0 = 0; k0 < KPAD1; k0 += 16) {
                __syncthreads();
                for (int idx = tid; idx < 2048; idx += 256) {
                    int row = idx >> 4, kk = idx & 15;
                    int k = k0 + kk;
                    size_t pb = (size_t)(k >> 5) * 64 + (k & 31);
                    const __nv_bfloat16* ar = Abf + (size_t)(pm + row) * AW1 + pb;
                    const __nv_bfloat16* wr = WT + (size_t)(pn + row) * WTS + pb;
                    As[kk * 128 + row] = __bfloat162float(ar[0]) + __bfloat162float(ar[32]);
                    Bs[kk * 128 + row] = __bfloat162float(wr[0]) + __bfloat162float(wr[32]);
                }
                __syncthreads();
#pragma unroll
                for (int k = 0; k < 16; k++) {
                    float af[8], bf[8];
#pragma unroll
                    for (int a = 0; a < 8; a++) af[a] = As[k * 128 + ty * 8 + a];
#pragma unroll
                    for (int b = 0; b < 8; b++) bf[b] = Bs[k * 128 + tx * 8 + b];
#pragma unroll
                    for (int a = 0; a < 8; a++)
#pragma unroll
                        for (int b = 0; b < 8; b++) acc[a][b] += af[a] * bf[b];
                }
            }
            __syncthreads();
            if (half == 0) {
#pragma unroll
                for (int a = 0; a < 8; a++)
#pragma unroll
                    for (int b = 0; b < 8; b++)
                        Da[(ty * 8 + a) * 128 + tx * 8 + b] = acc[a][b];
            } else {
#pragma unroll
                for (int a = 0; a < 8; a++) {
                    int row = ty * 8 + a;
                    float ssp = 0.f;
#pragma unroll
                    for (int b = 0; b < 8; b++) {
                        int col = tx * 8 + b;
                        float av = Da[row * 128 + col];
                        float v = av * gelu_tanh(acc[a][b]);
                        ssp += v * v;
                        __nv_bfloat16 h = __float2bfloat16(v);
                        __nv_bfloat16 l = __float2bfloat16(v - __bfloat162float(h));
                        int f = tile * 128 + col;
                        int fb = f >> 5, pos = f & 31;
                        Vbf[(size_t)(pm + row) * VW + fb * 64 + pos] = h;
                        Vbf[(size_t)(pm + row) * VW + fb * 64 + 32 + pos] = l;
                    }
                    ssrd[row * 16 + tx] = ssp;
                }
            }
            __syncthreads();
        }
        if (tid < 128) {
            float sm = 0.f;
            for (int j = 0; j < 16; j++) sm += ssrd[tid * 16 + j];
            sspart[(size_t)(pm + tid) * NTILES + tile] = sm;
        }
        __syncthreads();
    }
#endif
}

// ---------------- K5: GEMM2  down = V @ (vn2*vw2), 3-buffer pipeline ----------
#define SMEM5 (1024 + 3 * 24576)
__global__ void __launch_bounds__(256, 1) k5_gemm2(const __nv_bfloat16* __restrict__ Vbf,
                                                   const __nv_bfloat16* __restrict__ WT2,
                                                   float* __restrict__ C)
{
    extern __shared__ char smem[];
    uint32_t sbase = smem_u32(smem);
    int tid = threadIdx.x;
    int wid = tid >> 5, lid = tid & 31;
    int bm = blockIdx.x * 128;

#if defined(__CUDA_ARCH_FEAT_SM103_ALL)
    const uint32_t TSLOT = sbase;
    const uint32_t MB0 = sbase + 16;
    const uint32_t MB1 = sbase + 24;
    const uint32_t MB2 = sbase + 32;
    const uint32_t SDATA = sbase + 1024;

    if (wid == 0) TC_ALLOC(TSLOT, 64);
    if (tid == 0) { MBARRIER_INIT(MB0, 1); MBARRIER_INIT(MB1, 1); MBARRIER_INIT(MB2, 1); }
    __syncthreads();
    uint32_t tmem;
    asm volatile("ld.shared.b32 %0, [%1];" : "=r"(tmem) : "r"(TSLOT));

    const uint32_t IDESC = (1u << 4) | (1u << 7) | (1u << 10) | (8u << 17) | (8u << 24);

    auto load_stage = [&](int s) {
        int buf = s % 3;
        int ks = s * 64;
        uint32_t ab = SDATA + buf * 24576;
        uint32_t wb = ab + 16384;
        const __nv_bfloat16* Asrc = Vbf + (size_t)bm * VW + ks;
        const __nv_bfloat16* Wsrc = WT2 + ks;
#pragma unroll
        for (int j = 0; j < 4; j++) {
            int idx = tid + j * 256;            // A: 1024 vecs (128 rows x 8)
            int row = idx >> 3, c = idx & 7;
            uint32_t off = (uint32_t)(row * 128 + c * 16);
            uint32_t sw = off ^ ((off >> 3) & 0x70);
            CP_ASYNC16(ab + sw, (const void*)(Asrc + (size_t)row * VW + c * 8));
        }
#pragma unroll
        for (int j = 0; j < 2; j++) {
            int idx = tid + j * 256;            // W: 512 vecs (64 rows x 8)
            int row = idx >> 3, c = idx & 7;
            uint32_t off = (uint32_t)(row * 128 + c * 16);
            uint32_t sw = off ^ ((off >> 3) & 0x70);
            CP_ASYNC16(wb + sw, (const void*)(Wsrc + (size_t)row * VW + c * 8));
        }
        CP_COMMIT();
    };

    int ph0 = 0, ph1 = 0, ph2 = 0;
    load_stage(0);
    load_stage(1);
    for (int s = 0; s < NST2; s++) {
        if (s + 2 < NST2) {
            if (s >= 1) {
                int b = (s - 1) % 3;
                if (b == 0)      { MBARRIER_WAIT_PARITY(MB0, ph0); ph0 ^= 1; }
                else if (b == 1) { MBARRIER_WAIT_PARITY(MB1, ph1); ph1 ^= 1; }
                else             { MBARRIER_WAIT_PARITY(MB2, ph2); ph2 ^= 1; }
            }
            load_stage(s + 2);
        }
        if (s + 2 < NST2)      CP_WAIT2();
        else if (s + 1 < NST2) CP_WAIT1();
        else                   CP_WAIT0();
        __syncthreads();
        FENCE_ASYNC_SH();
        if (wid == 0) {
            if (elect_one()) {
                int buf = s % 3;
                uint32_t ab = SDATA + buf * 24576;
                uint64_t ad = make_desc(ab);
                uint64_t bd = make_desc(ab + 16384);
                uint32_t en0 = (s > 0) ? 1u : 0u;
                mma_f16_ss(tmem, ad + 0, bd + 0, IDESC, en0);
                mma_f16_ss(tmem, ad + 2, bd + 2, IDESC, 1u);
                mma_f16_ss(tmem, ad + 4, bd + 0, IDESC, 1u);
                mma_f16_ss(tmem, ad + 6, bd + 2, IDESC, 1u);
                mma_f16_ss(tmem, ad + 0, bd + 4, IDESC, 1u);
                mma_f16_ss(tmem, ad + 2, bd + 6, IDESC, 1u);
                if (buf == 0) TC_COMMIT(MB0);
                else if (buf == 1) TC_COMMIT(MB1);
                else TC_COMMIT(MB2);
            }
        }
    }
    {
        int b = (NST2 - 1) % 3;   // 75 % 3 = 0
        if (b == 0)      MBARRIER_WAIT_PARITY(MB0, ph0);
        else if (b == 1) MBARRIER_WAIT_PARITY(MB1, ph1);
        else             MBARRIER_WAIT_PARITY(MB2, ph2);
    }
    TC_FENCE_AFTER();

    if (wid < 4) {
        int m = bm + wid * 32 + lid;
        uint32_t r[32];
        TC_LD_X32(r, tmem);
        TC_WAIT_LD();
        float4* dst = (float4*)(C + (size_t)m * 64);
#pragma unroll
        for (int j = 0; j < 8; j++)
            dst[j] = make_float4(__uint_as_float(r[4 * j + 0]), __uint_as_float(r[4 * j + 1]),
                                 __uint_as_float(r[4 * j + 2]), __uint_as_float(r[4 * j + 3]));
        uint32_t r2[32];
        TC_LD_X32(r2, tmem + 32);
        TC_WAIT_LD();
#pragma unroll
        for (int j = 0; j < 8; j++)
            dst[8 + j] = make_float4(__uint_as_float(r2[4 * j + 0]), __uint_as_float(r2[4 * j + 1]),
                                     __uint_as_float(r2[4 * j + 2]), __uint_as_float(r2[4 * j + 3]));
    }
    __syncthreads();
    if (wid == 0) {
        TC_RELINQ();
        TC_DEALLOC(tmem, 64);
    }
#else
    // ---- FFMA fallback (256 threads) ----
    float* Bs = (float*)smem;            // [16][64]
    for (int m0 = 0; m0 < 128; m0 += 64) {
        int m = bm + m0 + (tid >> 2);    // 64 rows per pass
        int nq = (tid & 3) * 16;
        float acc[16];
#pragma unroll
        for (int a = 0; a < 16; a++) acc[a] = 0.f;
        for (int k0 = 0; k0 < KPAD2; k0 += 16) {
            __syncthreads();
            for (int idx = tid; idx < 1024; idx += 256) {
                int kk = idx >> 6, n = idx & 63;
                int k = k0 + kk;
                const __nv_bfloat16* wr = WT2 + (size_t)n * VW + (size_t)(k >> 5) * 64 + (k & 31);
                Bs[kk * 64 + n] = __bfloat162float(wr[0]) + __bfloat162float(wr[32]);
            }
            __syncthreads();
#pragma unroll
            for (int kk = 0; kk < 16; kk++) {
                int k = k0 + kk;
                const __nv_bfloat16* ar = Vbf + (size_t)m * VW + (size_t)(k >> 5) * 64 + (k & 31);
                float av = __bfloat162float(ar[0]) + __bfloat162float(ar[32]);
#pragma unroll
                for (int a = 0; a < 16; a++) acc[a] += av * Bs[kk * 64 + nq + a];
            }
        }
        for (int a = 0; a < 16; a++) C[(size_t)m * 64 + nq + a] = acc[a];
        __syncthreads();
    }
#endif
}

// ---------------- K6: row-scale + final linear ---------------------------------
__global__ void k6_final(const float* __restrict__ t,
                         const float* __restrict__ fw, const float* __restrict__ fb,
                         float* __restrict__ out)
{
    int i = blockIdx.x * blockDim.x + threadIdx.x;
    if (i >= NPTS) return;

    const float* sp = g_sspart + (size_t)i * NTILES;
    float ss = 0.f;
#pragma unroll
    for (int r = 0; r < NTILES; r++) ss += sp[r];
    float sc = 1.0f / (sqrtf(ss / (float)TOTAL) + 1e-8f);

    const float* dr = g_down + (size_t)i * 64;
    float o0 = 0.f, o1 = 0.f, o2 = 0.f, o3 = 0.f;
#pragma unroll 8
    for (int r = 0; r < 64; r++) {
        float a = dr[r];
        o0 += a * fw[r * 4 + 0];
        o1 += a * fw[r * 4 + 1];
        o2 += a * fw[r * 4 + 2];
        o3 += a * fw[r * 4 + 3];
    }
    o0 *= sc; o1 *= sc; o2 *= sc; o3 *= sc;
    o0 += fb[0]; o1 += fb[1]; o2 += fb[2]; o3 += fb[3];
    float p0 = g_p[i * 3 + 0], p1 = g_p[i * 3 + 1], p2 = g_p[i * 3 + 2];
    float tv = t[i];
    o0 += p0 * fw[256 + 0] + p1 * fw[260 + 0] + p2 * fw[264 + 0] + tv * fw[268 + 0];
    o1 += p0 * fw[256 + 1] + p1 * fw[260 + 1] + p2 * fw[264 + 1] + tv * fw[268 + 1];
    o2 += p0 * fw[256 + 2] + p1 * fw[260 + 2] + p2 * fw[264 + 2] + tv * fw[268 + 2];
    o3 += p0 * fw[256 + 3] + p1 * fw[260 + 3] + p2 * fw[264 + 3] + tv * fw[268 + 3];
    out[i * 4 + 0] = o0;
    out[i * 4 + 1] = o1;
    out[i * 4 + 2] = o2;
    out[i * 4 + 3] = o3;
}

// ---------------- launcher ----------------------------------------------------
extern "C" void kernel_launch(void* const* d_in, const int* in_sizes, int n_in,
                              void* d_out, int out_size)
{
    const float* pos      = (const float*)d_in[0];
    const float* t        = (const float*)d_in[2];
    const float* table0   = (const float*)d_in[3];
    const float* table1   = (const float*)d_in[4];
    const float* table2   = (const float*)d_in[5];
    const float* table3   = (const float*)d_in[6];
    const float* st1      = (const float*)d_in[7];
    const float* st2      = (const float*)d_in[8];
    const float* tf       = (const float*)d_in[9];
    const float* sph_proj = (const float*)d_in[10];
    const float* tb1      = (const float*)d_in[11];
    const float* tb2      = (const float*)d_in[12];
    const float* gn1      = (const float*)d_in[13];
    const float* gw1      = (const float*)d_in[14];
    const float* gn2      = (const float*)d_in[15];
    const float* gw2      = (const float*)d_in[16];
    const float* gn3      = (const float*)d_in[17];
    const float* gw3      = (const float*)d_in[18];
    const float* vn1      = (const float*)d_in[19];
    const float* vw1      = (const float*)d_in[20];
    const float* vn2      = (const float*)d_in[21];
    const float* vw2      = (const float*)d_in[22];
    const float* fw       = (const float*)d_in[23];
    const float* fb       = (const float*)d_in[24];
    float* out = (float*)d_out;

    cudaFuncSetAttribute(k3_gemm1, cudaFuncAttributeMaxDynamicSharedMemorySize, SMEM1);
    cudaFuncSetAttribute(k5_gemm2, cudaFuncAttributeMaxDynamicSharedMemorySize, SMEM5);

    k1_preamble<<<NPTS / 256, 256>>>(pos, t, sph_proj, tb1, tb2,
                                     gn1, gw1, gn2, gw2, gn3, gw3);

    dim3 gw(WTROWS / 32, KPAD1 / 32);     // (152, 74)
    k_convW<<<gw, dim3(32, 8)>>>(vw1);
    k_convW2<<<(TOTAL * 64 + 255) / 256, 256>>>(vw2, vn2);

    k2_gather<<<NPTS, 128>>>(t, table0, table1, table2, table3, st1, st2, tf, vn1);

    __nv_bfloat16* Abf; cudaGetSymbolAddress((void**)&Abf, g_Abf);
    __nv_bfloat16* Vbf; cudaGetSymbolAddress((void**)&Vbf, g_Vbf);
    __nv_bfloat16* WT;  cudaGetSymbolAddress((void**)&WT,  g_WT);
    __nv_bfloat16* WT2; cudaGetSymbolAddress((void**)&WT2, g_WT2);
    float* Dn;          cudaGetSymbolAddress((void**)&Dn,  g_down);
    float* Sp;          cudaGetSymbolAddress((void**)&Sp,  g_sspart);

    dim3 g1(NTILES, NPTS / 256);          // (19, 128)
    k3_gemm1<<<g1, 256, SMEM1>>>(Abf, WT, Vbf, Sp);

    k5_gemm2<<<NPTS / 128, 256, SMEM5>>>(Vbf, WT2, Dn);

    k6_final<<<NPTS / 256, 256>>>(t, fw, fb, out);
}